// round 12
// baseline (speedup 1.0000x reference)
#include <cuda_runtime.h>
#include <cuda_bf16.h>
#include <math.h>
#include <float.h>
#include <stdint.h>

#define NNODE 4096
#define NIN   28
#define NE    131072
#define NEP   (NE + NNODE)
#define NH    8
#define NC    256
#define NHC   2048
#define HID   256
#define NOUT  128

// ---------------- fp32 scratch ----------------
#define OFF_G    ((size_t)0)
#define OFF_BSUM (OFF_G + (size_t)NNODE * 1024)
#define BIG_SZ   (OFF_BSUM + 1024)
__device__ float g_big[BIG_SZ];

__device__ float g_xp[2][(size_t)NNODE * NHC];
__device__ float g_as[2][NNODE * NH];
__device__ float g_ad[2][NNODE * NH];
__device__ float g_w [2][(size_t)NEP * NH];
__device__ int   g_mx[2][NNODE * NH];
__device__ int   g_cnt[2][NNODE];
__device__ int   g_cur[2][NNODE];
__device__ int   g_start[2][NNODE];
__device__ int   g_sorted[2][NE];
__device__ float g_part[2][128];
__device__ float g_mean[2];
__device__ float g_ce[2][NH];

// flash split-K partials
__device__ float g_po[(size_t)2 * NNODE * 256];
__device__ float g_pml[(size_t)2 * NNODE * 8];

// ---------------- bf16 hi/lo tensors ----------------
__device__ __nv_bfloat16 g_hth[(size_t)NNODE * NHC], g_htl[(size_t)NNODE * NHC];
__device__ __nv_bfloat16 g_hch[(size_t)NNODE * 256], g_hcl[(size_t)NNODE * 256];
__device__ __nv_bfloat16 g_qkvh[(size_t)NNODE * 768], g_qkvl[(size_t)NNODE * 768];
__device__ __nv_bfloat16 g_vth[(size_t)4 * 64 * NNODE], g_vtl[(size_t)4 * 64 * NNODE];
__device__ __nv_bfloat16 g_attnh[(size_t)NNODE * 256], g_attnl[(size_t)NNODE * 256];
__device__ __nv_bfloat16 g_hcath[(size_t)NNODE * 512], g_hcatl[(size_t)NNODE * 512];
__device__ __nv_bfloat16 g_hfush[(size_t)NNODE * 256], g_hfusl[(size_t)NNODE * 256];
// weights
__device__ __nv_bfloat16 g_wihh[1024 * 2048], g_wihl[1024 * 2048];
__device__ __nv_bfloat16 g_inwh[768 * 256],   g_inwl[768 * 256];
__device__ __nv_bfloat16 g_mowh[256 * 256],   g_mowl[256 * 256];
__device__ __nv_bfloat16 g_fuwh[256 * 512],   g_fuwl[256 * 512];
__device__ __nv_bfloat16 g_owh[128 * 256],    g_owl[128 * 256];
// padded x / W for tensor-core xp GEMM
__device__ __nv_bfloat16 g_xpadh[(size_t)NNODE * 64], g_xpadl[(size_t)NNODE * 64];
__device__ __nv_bfloat16 g_wpadh[(size_t)2 * NHC * 64], g_wpadl[(size_t)2 * NHC * 64];

// ---------------- helpers ----------------
__device__ __forceinline__ int   f2ord(float f){ int i = __float_as_int(f); return i >= 0 ? i : i ^ 0x7fffffff; }
__device__ __forceinline__ float ord2f(int k){ return __int_as_float(k >= 0 ? k : k ^ 0x7fffffff); }
__device__ __forceinline__ float sigmf(float x){ return 1.f / (1.f + expf(-x)); }
__device__ __forceinline__ void f2hl(float v, __nv_bfloat16* H, __nv_bfloat16* L, size_t i){
    __nv_bfloat16 h = __float2bfloat16(v);
    H[i] = h; L[i] = __float2bfloat16(v - __bfloat162float(h));
}
__device__ __forceinline__ uint32_t smem_u32(const void* p){
    uint32_t a;
    asm("{ .reg .u64 t; cvta.to.shared.u64 t, %1; cvt.u32.u64 %0, t; }" : "=r"(a) : "l"(p));
    return a;
}
__device__ __forceinline__ void ldm_x4(uint32_t* r, uint32_t addr){
    asm volatile("ldmatrix.sync.aligned.m8n8.x4.shared.b16 {%0,%1,%2,%3}, [%4];"
        : "=r"(r[0]), "=r"(r[1]), "=r"(r[2]), "=r"(r[3]) : "r"(addr));
}
__device__ __forceinline__ void ldm_x2(uint32_t* r, uint32_t addr){
    asm volatile("ldmatrix.sync.aligned.m8n8.x2.shared.b16 {%0,%1}, [%2];"
        : "=r"(r[0]), "=r"(r[1]) : "r"(addr));
}
__device__ __forceinline__ void mma_bf16(float* c, const uint32_t* a, const uint32_t* b){
    asm volatile("mma.sync.aligned.m16n8k16.row.col.f32.bf16.bf16.f32 "
        "{%0,%1,%2,%3}, {%4,%5,%6,%7}, {%8,%9}, {%0,%1,%2,%3};"
        : "+f"(c[0]), "+f"(c[1]), "+f"(c[2]), "+f"(c[3])
        : "r"(a[0]), "r"(a[1]), "r"(a[2]), "r"(a[3]), "r"(b[0]), "r"(b[1]));
}
__device__ __forceinline__ void cpa16(uint32_t saddr, const void* g){
    asm volatile("cp.async.ca.shared.global [%0], [%1], 16;" :: "r"(saddr), "l"(g));
}
__device__ __forceinline__ void cpa_commit(){ asm volatile("cp.async.commit_group;" ::: "memory"); }
__device__ __forceinline__ void splitpack(float a, float b, uint32_t& hi, uint32_t& lo){
    __nv_bfloat16 ha = __float2bfloat16(a), hb = __float2bfloat16(b);
    __nv_bfloat16 la = __float2bfloat16(a - __bfloat162float(ha));
    __nv_bfloat16 lb = __float2bfloat16(b - __bfloat162float(hb));
    hi = ((uint32_t)__bfloat16_as_ushort(hb) << 16) | (uint32_t)__bfloat16_as_ushort(ha);
    lo = ((uint32_t)__bfloat16_as_ushort(lb) << 16) | (uint32_t)__bfloat16_as_ushort(la);
}

// ================= setup (initmean + weight conversions, one launch) =================
#define CW0 2097152
#define CW1 (CW0 + 196608)
#define CW2 (CW1 + 65536)
#define CW3 (CW2 + 131072)
#define CW4 (CW3 + 32768)
#define CW5 (CW4 + NNODE * 64)
#define CW6 (CW5 + 2 * NHC * 64)
#define NCONVB ((CW6 + 255) / 256)

__global__ void k_initconv(const float* __restrict__ ea_t, const float* __restrict__ ea_c,
                           const float* __restrict__ w0, const float* __restrict__ w1,
                           const float* __restrict__ w2, const float* __restrict__ w3,
                           const float* __restrict__ w4, const float* __restrict__ x,
                           const float* __restrict__ W_t, const float* __restrict__ W_c){
    int bx = blockIdx.x;
    if (bx < 128){
        int idx = bx * 256 + threadIdx.x, stride = 128 * 256;
        int mi = f2ord(-FLT_MAX);
        for (int i = idx; i < NNODE * NH; i += stride){
            g_mx[0][i] = mi; g_mx[1][i] = mi;
            g_as[0][i] = 0.f; g_as[1][i] = 0.f;
            g_ad[0][i] = 0.f; g_ad[1][i] = 0.f;
        }
        for (int i = idx; i < NNODE; i += stride){
            g_cnt[0][i] = 0; g_cnt[1][i] = 0;
            g_cur[0][i] = 0; g_cur[1][i] = 0;
        }
        __shared__ float s0[256], s1[256];
        float a = 0.f, b = 0.f;
        for (int i = idx; i < NE; i += stride){ a += ea_t[i]; b += ea_c[i]; }
        s0[threadIdx.x] = a; s1[threadIdx.x] = b; __syncthreads();
        for (int s = 128; s; s >>= 1){
            if (threadIdx.x < s){ s0[threadIdx.x] += s0[threadIdx.x+s]; s1[threadIdx.x] += s1[threadIdx.x+s]; }
            __syncthreads();
        }
        if (!threadIdx.x){ g_part[0][bx] = s0[0]; g_part[1][bx] = s1[0]; }
        return;
    }
    int i = (bx - 128) * 256 + threadIdx.x;
    if (i < CW0)      f2hl(w0[i], g_wihh, g_wihl, i);
    else if (i < CW1) f2hl(w1[i - CW0], g_inwh, g_inwl, i - CW0);
    else if (i < CW2) f2hl(w2[i - CW1], g_mowh, g_mowl, i - CW1);
    else if (i < CW3) f2hl(w3[i - CW2], g_fuwh, g_fuwl, i - CW2);
    else if (i < CW4) f2hl(w4[i - CW3], g_owh, g_owl, i - CW3);
    else if (i < CW5){
        int j = i - CW4; int n = j >> 6, k = j & 63;
        float v = (k < NIN) ? x[n * NIN + k] : 0.f;
        f2hl(v, g_xpadh, g_xpadl, j);
    } else if (i < CW6){
        int j = i - CW5; int g = j >> 17; int r = j & 131071;
        int n = r >> 6, k = r & 63;
        const float* W = g ? W_c : W_t;
        float v = (k < NIN) ? W[k * NHC + n] : 0.f;
        f2hl(v, g_wpadh, g_wpadl, j);
    }
}

// ================= setup (means/ce/bsum) + edge count, one launch =================
__global__ void k_setupcount(const float* __restrict__ We_t, const float* __restrict__ ae_t,
                             const float* __restrict__ We_c, const float* __restrict__ ae_c,
                             const float* __restrict__ bih,  const float* __restrict__ bhh,
                             const int* __restrict__ dst_t, const int* __restrict__ dst_c){
    int bx = blockIdx.x;
    if (bx == 0){
        __shared__ float sh[256];
        int tid = threadIdx.x;
        for (int g = 0; g < 2; g++){
            sh[tid] = (tid < 128) ? g_part[g][tid] : 0.f;
            __syncthreads();
            for (int s = 128; s; s >>= 1){ if (tid < s) sh[tid] += sh[tid+s]; __syncthreads(); }
            if (!tid) g_mean[g] = sh[0] / (float)NE;
            __syncthreads();
        }
        int wid = tid >> 5, lane = tid & 31;
        for (int c = wid; c < 16; c += 8){
            int g = c >> 3, h = c & 7;
            const float* We = g ? We_c : We_t;
            const float* ae = g ? ae_c : ae_t;
            float s = 0.f;
            for (int i = lane; i < NC; i += 32) s = fmaf(We[h*NC + i], ae[h*NC + i], s);
            for (int o = 16; o; o >>= 1) s += __shfl_down_sync(0xffffffffu, s, o);
            if (!lane) g_ce[g][h] = s;
        }
        for (int j = tid; j < 1024; j += 256) g_big[OFF_BSUM + j] = bih[j] + bhh[j];
        return;
    }
    int idx = bx - 1;               // 0..1023
    int g = idx >> 9;               // 512 blocks per graph (512*256 = NE)
    const int* dst = g ? dst_c : dst_t;
    int e = (idx & 511) * 256 + threadIdx.x;
    atomicAdd(&g_cnt[g][dst[e]], 1);
}

// 256-thread scan over 4096 counts (runs inside the xp mma_dual launch, z==2)
__device__ void scan_body(int g){
    __shared__ int sh[256];
    int tid = threadIdx.x;
    int base = tid * 16;
    int local[16]; int s = 0;
#pragma unroll
    for (int i = 0; i < 16; i++){ local[i] = g_cnt[g][base + i]; s += local[i]; }
    sh[tid] = s; __syncthreads();
    for (int off = 1; off < 256; off <<= 1){
        int v = (tid >= off) ? sh[tid - off] : 0;
        __syncthreads();
        sh[tid] += v;
        __syncthreads();
    }
    int run = sh[tid] - s;
#pragma unroll
    for (int i = 0; i < 16; i++){ g_start[g][base + i] = run; run += local[i]; }
}

// ================= GAT edge pipeline =================
__global__ void k_scatalpha(const int* __restrict__ src_t, const int* __restrict__ dst_t, const float* __restrict__ ea_t,
                            const int* __restrict__ src_c, const int* __restrict__ dst_c, const float* __restrict__ ea_c){
    int g = blockIdx.y;
    const int* src = g ? src_c : src_t;
    const int* dst = g ? dst_c : dst_t;
    const float* ea = g ? ea_c : ea_t;
    int e = blockIdx.x * 256 + threadIdx.x;
    if (e >= NEP) return;
    int s, d; float av;
    if (e < NE){
        s = src[e]; d = dst[e]; av = ea[e];
        int pos = g_start[g][d] + atomicAdd(&g_cur[g][d], 1);
        g_sorted[g][pos] = e;
    } else { s = d = e - NE; av = g_mean[g]; }
#pragma unroll
    for (int h = 0; h < NH; h++){
        float al = g_as[g][s*NH + h] + g_ad[g][d*NH + h] + av * g_ce[g][h];
        al = al > 0.f ? al : 0.2f * al;
        g_w[g][(size_t)e * NH + h] = al;
        atomicMax(&g_mx[g][d*NH + h], f2ord(al));
    }
}

// fused: exp + denominator + weighted aggregation (body)
__device__ void agg_body(int g, int n, const int* __restrict__ src, const float* __restrict__ bias){
    int t = threadIdx.x;
    const float* xp = g_xp[g];
    const float* w  = g_w[g];

    __shared__ float smx[NH];
    __shared__ int   ssrc[32];
    __shared__ float sw[32][NH];
    if (t < NH) smx[t] = ord2f(g_mx[g][n*NH + t]);
    __syncthreads();

    float acc[NH], den[NH];
    {
        size_t e = (size_t)(NE + n) * NH;
        const float* xr = xp + (size_t)n * NHC + t;
#pragma unroll
        for (int h = 0; h < NH; h++){
            float exs = expf(w[e + h] - smx[h]);
            acc[h] = exs * xr[h * NC];
            den[h] = exs;
        }
    }
    int st = g_start[g][n], c = g_cnt[g][n];
    for (int i0 = 0; i0 < c; i0 += 32){
        int m = min(32, c - i0);
        __syncthreads();
        if (t < m) ssrc[t] = src[g_sorted[g][st + i0 + t]];
        {
            int j = t >> 3, h = t & 7;
            if (j < m) sw[j][h] = expf(w[(size_t)g_sorted[g][st + i0 + j] * NH + h] - smx[h]);
        }
        __syncthreads();
        int jj = 0;
        for (; jj + 4 <= m; jj += 4){
            const float* x0 = xp + (size_t)ssrc[jj+0] * NHC + t;
            const float* x1 = xp + (size_t)ssrc[jj+1] * NHC + t;
            const float* x2 = xp + (size_t)ssrc[jj+2] * NHC + t;
            const float* x3 = xp + (size_t)ssrc[jj+3] * NHC + t;
            float v0[NH], v1[NH], v2[NH], v3[NH];
#pragma unroll
            for (int h = 0; h < NH; h++){ v0[h] = x0[h*NC]; v1[h] = x1[h*NC]; v2[h] = x2[h*NC]; v3[h] = x3[h*NC]; }
#pragma unroll
            for (int h = 0; h < NH; h++){
                float w0 = sw[jj+0][h], w1 = sw[jj+1][h], w2 = sw[jj+2][h], w3 = sw[jj+3][h];
                acc[h] = fmaf(w0, v0[h], acc[h]);
                acc[h] = fmaf(w1, v1[h], acc[h]);
                acc[h] = fmaf(w2, v2[h], acc[h]);
                acc[h] = fmaf(w3, v3[h], acc[h]);
                den[h] += (w0 + w1) + (w2 + w3);
            }
        }
        for (; jj < m; jj++){
            const float* xr = xp + (size_t)ssrc[jj] * NHC + t;
#pragma unroll
            for (int h = 0; h < NH; h++){
                float ww = sw[jj][h];
                acc[h] = fmaf(ww, xr[h * NC], acc[h]);
                den[h] += ww;
            }
        }
    }
    if (g == 0){
#pragma unroll
        for (int h = 0; h < NH; h++){
            float v = acc[h] / (den[h] + 1e-16f) + bias[h * NC + t];
            f2hl(v, g_hth, g_htl, (size_t)n * NHC + h * NC + t);
        }
    } else {
        float s = 0.f;
#pragma unroll
        for (int h = 0; h < NH; h++) s += acc[h] / (den[h] + 1e-16f);
        f2hl(s * 0.125f + bias[t], g_hch, g_hcl, (size_t)n * NC + t);
    }
}

__global__ void __launch_bounds__(256) k_agg(const int* __restrict__ src, const float* __restrict__ bias, int g){
    agg_body(g, blockIdx.x, src, bias);
}

// ================= HMMA bf16x3 GEMM core =================
struct GA {
    const __nv_bfloat16 *Ah, *Al, *Bh, *Bl;
    float* C;
    __nv_bfloat16 *Ch, *Cl;
    const float* bias;
    const float *pas, *pad;
    float *oas, *oad;
    int lda, ldb, ldc, ldc2, c2off, K, act, gx;
    float alpha;
};

__device__ __forceinline__ void gemm_core(const GA a, int row0, int col0){
    extern __shared__ char sm[];
    int tid = threadIdx.x, lane = tid & 31, wid = tid >> 5;
    int wm = wid & 3, wn = wid >> 2;
    const __nv_bfloat16* Ah = a.Ah + (size_t)row0 * a.lda;
    const __nv_bfloat16* Al = a.Al + (size_t)row0 * a.lda;
    const __nv_bfloat16* Bh = a.Bh + (size_t)col0 * a.ldb;
    const __nv_bfloat16* Bl = a.Bl + (size_t)col0 * a.ldb;

    uint32_t sbase = smem_u32(sm);
    int nkb = a.K >> 6;

    auto issue = [&](int kb, int st){
        uint32_t su = sbase + st * 49152;
        int k0 = kb << 6;
#pragma unroll
        for (int it = 0; it < 4; it++){
            int i = tid + it * 256;
            int row = i >> 3, seg = i & 7;
            size_t goff = (size_t)row * a.lda + k0 + seg * 8;
            uint32_t so = row * 128 + ((seg ^ (row & 7)) << 4);
            cpa16(su + so,         Ah + goff);
            cpa16(su + 16384 + so, Al + goff);
        }
#pragma unroll
        for (int it = 0; it < 2; it++){
            int i = tid + it * 256;
            int row = i >> 3, seg = i & 7;
            size_t goff = (size_t)row * a.ldb + k0 + seg * 8;
            uint32_t so = row * 128 + ((seg ^ (row & 7)) << 4);
            cpa16(su + 32768 + so, Bh + goff);
            cpa16(su + 40960 + so, Bl + goff);
        }
        cpa_commit();
    };

    issue(0, 0);
    if (nkb > 1) issue(1, 1);

    float acc[2][4][4] = {};
    for (int kb = 0; kb < nkb; kb++){
        if (kb + 1 < nkb) asm volatile("cp.async.wait_group 1;" ::: "memory");
        else              asm volatile("cp.async.wait_group 0;" ::: "memory");
        __syncthreads();
        uint32_t sb2 = sbase + (kb & 1) * 49152;
#pragma unroll
        for (int ks = 0; ks < 4; ks++){
            uint32_t a_h[2][4], a_l[2][4], b_h[4][2], b_l[4][2];
#pragma unroll
            for (int mt = 0; mt < 2; mt++){
                int r = wm * 32 + mt * 16 + (lane & 15);
                int seg = ks * 2 + (lane >> 4);
                uint32_t ad = sb2 + r * 128 + ((seg ^ (r & 7)) << 4);
                ldm_x4(a_h[mt], ad);
                ldm_x4(a_l[mt], ad + 16384);
            }
#pragma unroll
            for (int nt = 0; nt < 4; nt++){
                int r = wn * 32 + nt * 8 + (lane & 7);
                int seg = ks * 2 + ((lane >> 3) & 1);
                uint32_t bd = sb2 + 32768 + r * 128 + ((seg ^ (r & 7)) << 4);
                ldm_x2(b_h[nt], bd);
                ldm_x2(b_l[nt], bd + 8192);
            }
#pragma unroll
            for (int mt = 0; mt < 2; mt++)
#pragma unroll
                for (int nt = 0; nt < 4; nt++){
                    mma_bf16(acc[mt][nt], a_h[mt], b_h[nt]);
                    mma_bf16(acc[mt][nt], a_h[mt], b_l[nt]);
                    mma_bf16(acc[mt][nt], a_l[mt], b_h[nt]);
                }
        }
        __syncthreads();
        if (kb + 2 < nkb) issue(kb + 2, kb & 1);
    }

    float s1[4] = {}, s2[4] = {};
    int h = col0 >> 8;
#pragma unroll
    for (int mt = 0; mt < 2; mt++){
#pragma unroll
        for (int nt = 0; nt < 4; nt++){
            int r0 = row0 + wm * 32 + mt * 16 + (lane >> 2);
            int c0 = col0 + wn * 32 + nt * 8 + ((lane & 3) << 1);
#pragma unroll
            for (int q = 0; q < 4; q++){
                int r = r0 + (q >> 1) * 8;
                int cc = c0 + (q & 1);
                float v = acc[mt][nt][q] * a.alpha;
                if (a.bias) v += a.bias[cc];
                if (a.act == 1) v = fmaxf(v, 0.f);
                if (a.C) a.C[(size_t)r * a.ldc + cc] = v;
                if (a.Ch) f2hl(v, a.Ch, a.Cl, (size_t)r * a.ldc2 + a.c2off + cc);
                if (a.pas){
                    int ridx = mt * 2 + (q >> 1);
                    int ci = h * 256 + (cc & 255);
                    s1[ridx] = fmaf(v, a.pas[ci], s1[ridx]);
                    s2[ridx] = fmaf(v, a.pad[ci], s2[ridx]);
                }
            }
        }
    }
    if (a.pas){
#pragma unroll
        for (int i = 0; i < 4; i++){
            s1[i] += __shfl_xor_sync(~0u, s1[i], 1); s1[i] += __shfl_xor_sync(~0u, s1[i], 2);
            s2[i] += __shfl_xor_sync(~0u, s2[i], 1); s2[i] += __shfl_xor_sync(~0u, s2[i], 2);
        }
        if ((lane & 3) == 0){
#pragma unroll
            for (int i = 0; i < 4; i++){
                int mt = i >> 1, rr = i & 1;
                int r = row0 + wm * 32 + mt * 16 + (lane >> 2) + rr * 8;
                atomicAdd(&a.oas[r * NH + h], s1[i]);
                atomicAdd(&a.oad[r * NH + h], s2[i]);
            }
        }
    }
}

__global__ void __launch_bounds__(256) mma_single(GA a){
    if ((int)blockIdx.x >= a.gx) return;
    gemm_core(a, blockIdx.y * 128, blockIdx.x * 64);
}
// z=0/1: the two xp GEMMs; z=2: the two edge-count prefix scans
__global__ void __launch_bounds__(256) mma_dual(GA a0, GA a1){
    if (blockIdx.z == 2){
        if (blockIdx.y == 0 && blockIdx.x < 2) scan_body(blockIdx.x);
        return;
    }
    GA a = blockIdx.z ? a1 : a0;
    if ((int)blockIdx.x >= a.gx) return;
    gemm_core(a, blockIdx.y * 128, blockIdx.x * 64);
}

// agg(g=0) + qkv GEMM co-launched
__global__ void __launch_bounds__(256) k_combo2(GA a, const int* __restrict__ src0, const float* __restrict__ bias0){
    int bx = blockIdx.x;
    if (bx < 384){
        gemm_core(a, (bx / 12) * 128, (bx % 12) * 64);
    } else {
        agg_body(0, bx - 384, src0, bias0);
    }
}

// ================= flash attention body (split-KV) =================
__device__ void flash_body(
    const __nv_bfloat16* __restrict__ qkvh, const __nv_bfloat16* __restrict__ qkvl,
    const __nv_bfloat16* __restrict__ vth, const __nv_bfloat16* __restrict__ vtl,
    float* __restrict__ pO, float* __restrict__ pML,
    int row0, int head, int z)
{
    extern __shared__ char sm[];
    int tid = threadIdx.x, lane = tid & 31, wid = tid >> 5;
    int kv0 = z * 2048;
    uint32_t sb = smem_u32(sm);

    const __nv_bfloat16* Qh = qkvh + (size_t)row0 * 768 + head * 64;
    const __nv_bfloat16* Ql = qkvl + (size_t)row0 * 768 + head * 64;
    const __nv_bfloat16* Kh = qkvh + 256 + head * 64;
    const __nv_bfloat16* Kl = qkvl + 256 + head * 64;
    const __nv_bfloat16* Vh = vth + (size_t)head * 64 * 4096;
    const __nv_bfloat16* Vl = vtl + (size_t)head * 64 * 4096;

#pragma unroll
    for (int it = 0; it < 4; it++){
        int i = tid + it * 256;
        int r = i >> 3, seg = i & 7;
        uint32_t so = r * 128 + ((seg ^ (r & 7)) << 4);
        cpa16(sb + so,         Qh + (size_t)r * 768 + seg * 8);
        cpa16(sb + 16384 + so, Ql + (size_t)r * 768 + seg * 8);
    }
#pragma unroll
    for (int it = 0; it < 2; it++){
        int i = tid + it * 256;
        int r = i >> 3, seg = i & 7;
        uint32_t so = r * 128 + ((seg ^ (r & 7)) << 4);
        cpa16(sb + 32768 + so,         Kh + (size_t)(kv0 + r) * 768 + seg * 8);
        cpa16(sb + 32768 + 8192 + so,  Kl + (size_t)(kv0 + r) * 768 + seg * 8);
        cpa16(sb + 32768 + 16384 + so, Vh + (size_t)r * 4096 + kv0 + seg * 8);
        cpa16(sb + 32768 + 24576 + so, Vl + (size_t)r * 4096 + kv0 + seg * 8);
    }
    cpa_commit();
    asm volatile("cp.async.wait_group 0;" ::: "memory");
    __syncthreads();

    uint32_t qf_h[4][4], qf_l[4][4];
#pragma unroll
    for (int ks = 0; ks < 4; ks++){
        int r = wid * 16 + (lane & 15);
        int seg = ks * 2 + (lane >> 4);
        uint32_t ad = sb + r * 128 + ((seg ^ (r & 7)) << 4);
        ldm_x4(qf_h[ks], ad);
        ldm_x4(qf_l[ks], ad + 16384);
    }

    float m0 = -1e30f, m1 = -1e30f, l0 = 0.f, l1 = 0.f;
    float acc_o[8][4] = {};
    int buf = 0;

    for (int kt = 0; kt < 32; kt++){
        if (kt < 31){
            uint32_t bo = sb + 32768 + (buf ^ 1) * 32768;
            int key0 = kv0 + (kt + 1) * 64;
#pragma unroll
            for (int it = 0; it < 2; it++){
                int i = tid + it * 256;
                int r = i >> 3, seg = i & 7;
                uint32_t so = r * 128 + ((seg ^ (r & 7)) << 4);
                cpa16(bo + so,         Kh + (size_t)(key0 + r) * 768 + seg * 8);
                cpa16(bo + 8192 + so,  Kl + (size_t)(key0 + r) * 768 + seg * 8);
                cpa16(bo + 16384 + so, Vh + (size_t)r * 4096 + key0 + seg * 8);
                cpa16(bo + 24576 + so, Vl + (size_t)r * 4096 + key0 + seg * 8);
            }
            cpa_commit();
            asm volatile("cp.async.wait_group 1;" ::: "memory");
        } else {
            asm volatile("cp.async.wait_group 0;" ::: "memory");
        }
        __syncthreads();

        uint32_t kb = sb + 32768 + buf * 32768;

        float acc_s[8][4] = {};
#pragma unroll
        for (int ks = 0; ks < 4; ks++){
            uint32_t bh[8][2], bl[8][2];
#pragma unroll
            for (int nt = 0; nt < 8; nt++){
                int r = nt * 8 + (lane & 7);
                int seg = ks * 2 + ((lane >> 3) & 1);
                uint32_t bd = kb + r * 128 + ((seg ^ (r & 7)) << 4);
                ldm_x2(bh[nt], bd);
                ldm_x2(bl[nt], bd + 8192);
            }
#pragma unroll
            for (int nt = 0; nt < 8; nt++){
                mma_bf16(acc_s[nt], qf_h[ks], bh[nt]);
                mma_bf16(acc_s[nt], qf_h[ks], bl[nt]);
                mma_bf16(acc_s[nt], qf_l[ks], bh[nt]);
            }
        }
#pragma unroll
        for (int nt = 0; nt < 8; nt++){
            acc_s[nt][0] *= 0.125f; acc_s[nt][1] *= 0.125f;
            acc_s[nt][2] *= 0.125f; acc_s[nt][3] *= 0.125f;
        }

        float tm0 = -1e30f, tm1 = -1e30f;
#pragma unroll
        for (int nt = 0; nt < 8; nt++){
            tm0 = fmaxf(tm0, fmaxf(acc_s[nt][0], acc_s[nt][1]));
            tm1 = fmaxf(tm1, fmaxf(acc_s[nt][2], acc_s[nt][3]));
        }
        tm0 = fmaxf(tm0, __shfl_xor_sync(~0u, tm0, 1)); tm0 = fmaxf(tm0, __shfl_xor_sync(~0u, tm0, 2));
        tm1 = fmaxf(tm1, __shfl_xor_sync(~0u, tm1, 1)); tm1 = fmaxf(tm1, __shfl_xor_sync(~0u, tm1, 2));
        float mn0 = fmaxf(m0, tm0), mn1 = fmaxf(m1, tm1);
        float sc0 = __expf(m0 - mn0), sc1 = __expf(m1 - mn1);
        m0 = mn0; m1 = mn1;
        l0 *= sc0; l1 *= sc1;
#pragma unroll
        for (int nt = 0; nt < 8; nt++){
            acc_o[nt][0] *= sc0; acc_o[nt][1] *= sc0;
            acc_o[nt][2] *= sc1; acc_o[nt][3] *= sc1;
        }
        float rs0 = 0.f, rs1 = 0.f;
        uint32_t pa_h[4][4], pa_l[4][4];
#pragma unroll
        for (int nt = 0; nt < 8; nt++){
            float p0 = __expf(acc_s[nt][0] - mn0), p1 = __expf(acc_s[nt][1] - mn0);
            float p2 = __expf(acc_s[nt][2] - mn1), p3 = __expf(acc_s[nt][3] - mn1);
            rs0 += p0 + p1; rs1 += p2 + p3;
            int k2 = nt >> 1;
            if (!(nt & 1)){
                splitpack(p0, p1, pa_h[k2][0], pa_l[k2][0]);
                splitpack(p2, p3, pa_h[k2][1], pa_l[k2][1]);
            } else {
                splitpack(p0, p1, pa_h[k2][2], pa_l[k2][2]);
                splitpack(p2, p3, pa_h[k2][3], pa_l[k2][3]);
            }
        }
        rs0 += __shfl_xor_sync(~0u, rs0, 1); rs0 += __shfl_xor_sync(~0u, rs0, 2);
        rs1 += __shfl_xor_sync(~0u, rs1, 1); rs1 += __shfl_xor_sync(~0u, rs1, 2);
        l0 += rs0; l1 += rs1;

        uint32_t vb = kb + 16384;
#pragma unroll
        for (int k2 = 0; k2 < 4; k2++){
            uint32_t vh[8][2], vl[8][2];
#pragma unroll
            for (int nt = 0; nt < 8; nt++){
                int r = nt * 8 + (lane & 7);
                int seg = k2 * 2 + ((lane >> 3) & 1);
                uint32_t vd = vb + r * 128 + ((seg ^ (r & 7)) << 4);
                ldm_x2(vh[nt], vd);
                ldm_x2(vl[nt], vd + 8192);
            }
#pragma unroll
            for (int nt = 0; nt < 8; nt++){
                mma_bf16(acc_o[nt], pa_h[k2], vh[nt]);
                mma_bf16(acc_o[nt], pa_h[k2], vl[nt]);
                mma_bf16(acc_o[nt], pa_l[k2], vh[nt]);
            }
        }
        __syncthreads();
        buf ^= 1;
    }

    int r = row0 + wid * 16 + (lane >> 2);
    size_t ro0 = ((size_t)z * NNODE + r) * 256;
    size_t ro1 = ((size_t)z * NNODE + r + 8) * 256;
#pragma unroll
    for (int nt = 0; nt < 8; nt++){
        int cc = head * 64 + nt * 8 + ((lane & 3) << 1);
        pO[ro0 + cc]     = acc_o[nt][0];
        pO[ro0 + cc + 1] = acc_o[nt][1];
        pO[ro1 + cc]     = acc_o[nt][2];
        pO[ro1 + cc + 1] = acc_o[nt][3];
    }
    if ((lane & 3) == 0){
        pML[((size_t)z * NNODE + r) * 8 + head * 2]     = m0;
        pML[((size_t)z * NNODE + r) * 8 + head * 2 + 1] = l0;
        pML[((size_t)z * NNODE + r + 8) * 8 + head * 2]     = m1;
        pML[((size_t)z * NNODE + r + 8) * 8 + head * 2 + 1] = l1;
    }
}

// combo: blocks 0..255 = flash; 256..767 = LSTM-gates GEMM
__global__ void __launch_bounds__(256) k_combo(
    GA a,
    const __nv_bfloat16* __restrict__ qkvh, const __nv_bfloat16* __restrict__ qkvl,
    const __nv_bfloat16* __restrict__ vth, const __nv_bfloat16* __restrict__ vtl,
    float* __restrict__ pO, float* __restrict__ pML)
{
    int bx = blockIdx.x;
    if (bx < 256){
        int row0 = (bx & 31) * 128;
        int head = (bx >> 5) & 3;
        int z = bx >> 7;
        flash_body(qkvh, qkvl, vth, vtl, pO, pML, row0, head, z);
    } else {
        int idx = bx - 256;
        gemm_core(a, (idx >> 4) * 128, (idx & 15) * 64);
    }
}

// ================= pointwise =================
__global__ void k_vt(const __nv_bfloat16* __restrict__ qh, const __nv_bfloat16* __restrict__ ql,
                     __nv_bfloat16* __restrict__ vh, __nv_bfloat16* __restrict__ vl){
    int idx = blockIdx.x * 256 + threadIdx.x;
    int hd = idx >> 12, n = idx & 4095;
    size_t s = (size_t)n * 768 + 512 + hd;
    vh[idx] = qh[s]; vl[idx] = ql[s];
}

__global__ void k_mergelstm(const float* __restrict__ pO, const float* __restrict__ pML,
                            __nv_bfloat16* __restrict__ Oh, __nv_bfloat16* __restrict__ Ol,
                            const float* __restrict__ G, float* __restrict__ ht_out){
    int b = blockIdx.x;
    if (b < NNODE){
        int row = b, col = threadIdx.x;
        int head = col >> 6;
        float m0 = pML[(size_t)row * 8 + head * 2],            l0 = pML[(size_t)row * 8 + head * 2 + 1];
        float m1 = pML[((size_t)NNODE + row) * 8 + head * 2],  l1 = pML[((size_t)NNODE + row) * 8 + head * 2 + 1];
        float mx = fmaxf(m0, m1);
        float w0 = __expf(m0 - mx), w1 = __expf(m1 - mx);
        float num = pO[(size_t)row * 256 + col] * w0 + pO[((size_t)NNODE + row) * 256 + col] * w1;
        float den = l0 * w0 + l1 * w1;
        f2hl(num / den, Oh, Ol, (size_t)row * 256 + col);
    } else {
        int idx = (b - NNODE) * 256 + threadIdx.x;
        int n = idx >> 8, j = idx & 255;
        const float* gr = G + (size_t)n * 1024;
        float ig = gr[j], gg = gr[512 + j], og = gr[768 + j];
        float cc = sigmf(ig) * tanhf(gg);
        float hv = sigmf(og) * tanhf(cc);
        ht_out[idx] = hv;
        f2hl(hv, g_hcath, g_hcatl, (size_t)n * 512 + j);
    }
}

// ================= launch =================
#define SYMADDR(p, s) do { void* _t; cudaGetSymbolAddress(&_t, s); p = (decltype(p))_t; } while(0)

extern "C" void kernel_launch(void* const* d_in, const int* in_sizes, int n_in,
                              void* d_out, int out_size) {
    const float* x     = (const float*)d_in[0];
    const int*   ei_t  = (const int*)d_in[1];
    const int*   ei_c  = (const int*)d_in[2];
    const float* ea_t  = (const float*)d_in[3];
    const float* ea_c  = (const float*)d_in[4];
    const float* W_t   = (const float*)d_in[5];
    const float* asrc_t= (const float*)d_in[6];
    const float* adst_t= (const float*)d_in[7];
    const float* We_t  = (const float*)d_in[8];
    const float* ae_t  = (const float*)d_in[9];
    const float* b_t   = (const float*)d_in[10];
    const float* W_c   = (const float*)d_in[11];
    const float* asrc_c= (const float*)d_in[12];
    const float* adst_c= (const float*)d_in[13];
    const float* We_c  = (const float*)d_in[14];
    const float* ae_c  = (const float*)d_in[15];
    const float* b_c   = (const float*)d_in[16];
    const float* lstm_Wih = (const float*)d_in[17];
    const float* lstm_bih = (const float*)d_in[19];
    const float* lstm_bhh = (const float*)d_in[20];
    const float* mha_in_w  = (const float*)d_in[21];
    const float* mha_in_b  = (const float*)d_in[22];
    const float* mha_out_w = (const float*)d_in[23];
    const float* mha_out_b = (const float*)d_in[24];
    const float* fus_w = (const float*)d_in[25];
    const float* fus_b = (const float*)d_in[26];
    const float* out_w = (const float*)d_in[27];
    const float* out_b = (const float*)d_in[28];

    float* big; SYMADDR(big, g_big);
    float* po;  SYMADDR(po, g_po);
    float* pml; SYMADDR(pml, g_pml);
    float* xp0; SYMADDR(xp0, g_xp);
    float* xp1 = xp0 + (size_t)NNODE * NHC;
    float* as0; SYMADDR(as0, g_as);
    float* as1 = as0 + NNODE * NH;
    float* ad0; SYMADDR(ad0, g_ad);
    float* ad1 = ad0 + NNODE * NH;
    __nv_bfloat16 *hth, *htl, *hch, *hcl, *qkvh, *qkvl, *vth, *vtl;
    __nv_bfloat16 *attnh, *attnl, *hcath, *hcatl, *hfush, *hfusl;
    __nv_bfloat16 *wihh, *wihl, *inwh, *inwl, *mowh, *mowl, *fuwh, *fuwl, *owh, *owl;
    __nv_bfloat16 *xpadh, *xpadl, *wpadh, *wpadl;
    SYMADDR(hth, g_hth); SYMADDR(htl, g_htl); SYMADDR(hch, g_hch); SYMADDR(hcl, g_hcl);
    SYMADDR(qkvh, g_qkvh); SYMADDR(qkvl, g_qkvl); SYMADDR(vth, g_vth); SYMADDR(vtl, g_vtl);
    SYMADDR(attnh, g_attnh); SYMADDR(attnl, g_attnl);
    SYMADDR(hcath, g_hcath); SYMADDR(hcatl, g_hcatl);
    SYMADDR(hfush, g_hfush); SYMADDR(hfusl, g_hfusl);
    SYMADDR(wihh, g_wihh); SYMADDR(wihl, g_wihl);
    SYMADDR(inwh, g_inwh); SYMADDR(inwl, g_inwl);
    SYMADDR(mowh, g_mowh); SYMADDR(mowl, g_mowl);
    SYMADDR(fuwh, g_fuwh); SYMADDR(fuwl, g_fuwl);
    SYMADDR(owh, g_owh); SYMADDR(owl, g_owl);
    SYMADDR(xpadh, g_xpadh); SYMADDR(xpadl, g_xpadl);
    SYMADDR(wpadh, g_wpadh); SYMADDR(wpadl, g_wpadl);

    cudaFuncSetAttribute(k_combo,  cudaFuncAttributeMaxDynamicSharedMemorySize, 98304);
    cudaFuncSetAttribute(k_combo2, cudaFuncAttributeMaxDynamicSharedMemorySize, 98304);
    cudaFuncSetAttribute(mma_single, cudaFuncAttributeMaxDynamicSharedMemorySize, 98304);
    cudaFuncSetAttribute(mma_dual, cudaFuncAttributeMaxDynamicSharedMemorySize, 98304);
    const int DYN = 98304;

    float* out_main = (float*)d_out;
    float* out_ht   = out_main + (size_t)NNODE * NOUT;
    float* out_hc   = out_ht   + (size_t)NNODE * HID;

    const int* src_t = ei_t; const int* dst_t = ei_t + NE;
    const int* src_c = ei_c; const int* dst_c = ei_c + NE;
    int nepb = (NEP + 255) / 256;

    // init + edge means + all weight/x conversions (one launch)
    k_initconv<<<128 + NCONVB, 256>>>(ea_t, ea_c, lstm_Wih, mha_in_w, mha_out_w, fus_w, out_w, x, W_t, W_c);
    // means/ce/bsum + edge count (one launch)
    k_setupcount<<<1 + 1024, 256>>>(We_t, ae_t, We_c, ae_c, lstm_bih, lstm_bhh, dst_t, dst_c);

    // ---- xp GEMMs (z=0/1) + count prefix scans (z=2) ----
    {
        GA a0 = { xpadh, xpadl, wpadh, wpadl, xp0, nullptr, nullptr, nullptr,
                  asrc_t, adst_t, as0, ad0,
                  64, 64, NHC, 0, 0, 64, 0, 32, 1.f };
        GA a1 = { xpadh, xpadl, wpadh + (size_t)NHC * 64, wpadl + (size_t)NHC * 64, xp1,
                  nullptr, nullptr, nullptr,
                  asrc_c, adst_c, as1, ad1,
                  64, 64, NHC, 0, 0, 64, 0, 32, 1.f };
        mma_dual<<<dim3(32, 32, 3), 256, DYN>>>(a0, a1);
    }

    // ---- edge scatter + logits + seg-max ----
    k_scatalpha<<<dim3(nepb, 2), 256>>>(src_t, dst_t, ea_t, src_c, dst_c, ea_c);

    // ---- agg graph 1 (-> hch) ----
    k_agg<<<NNODE, 256>>>(src_c, b_c, 1);

    // ---- qkv GEMM + agg graph 0 overlapped ----
    {
        GA a = { hch, hcl, inwh, inwl, nullptr, qkvh, qkvl, mha_in_b,
                 nullptr, nullptr, nullptr, nullptr,
                 256, 256, 0, 768, 0, 256, 0, 12, 1.f };
        k_combo2<<<384 + NNODE, 256, DYN>>>(a, src_t, b_t);
    }
    k_vt<<<(4*64*NNODE)/256, 256>>>(qkvh, qkvl, vth, vtl);

    // ---- flash attention + LSTM gates GEMM overlapped ----
    {
        GA a = { hth, htl, wihh, wihl, big + OFF_G, nullptr, nullptr, big + OFF_BSUM,
                 nullptr, nullptr, nullptr, nullptr,
                 NHC, NHC, 1024, 0, 0, NHC, 0, 16, 1.f };
        k_combo<<<768, 256, DYN>>>(a, qkvh, qkvl, vth, vtl, po, pml);
    }

    // ---- merge flash partials + lstm pointwise ----
    k_mergelstm<<<2 * NNODE, 256>>>(po, pml, attnh, attnl, big + OFF_G, out_ht);

    // ---- proj (4096x256x256) ----
    {
        GA a = { attnh, attnl, mowh, mowl, out_hc, hcath, hcatl, mha_out_b,
                 nullptr, nullptr, nullptr, nullptr,
                 256, 256, 256, 512, 256, 256, 0, 4, 1.f };
        mma_single<<<dim3(4, 32), 256, DYN>>>(a);
    }
    // ---- fusion relu (4096x256x512) ----
    {
        GA a = { hcath, hcatl, fuwh, fuwl, nullptr, hfush, hfusl, fus_b,
                 nullptr, nullptr, nullptr, nullptr,
                 512, 512, 0, 256, 0, 512, 1, 4, 1.f };
        mma_single<<<dim3(4, 32), 256, DYN>>>(a);
    }
    // ---- out (4096x128x256) ----
    {
        GA a = { hfush, hfusl, owh, owl, out_main, nullptr, nullptr, out_b,
                 nullptr, nullptr, nullptr, nullptr,
                 256, 256, NOUT, 0, 0, 256, 0, 2, 1.f };
        mma_single<<<dim3(2, 32), 256, DYN>>>(a);
    }
}

// round 13
// speedup vs baseline: 1.0646x; 1.0646x over previous
#include <cuda_runtime.h>
#include <cuda_bf16.h>
#include <math.h>
#include <float.h>
#include <stdint.h>

#define NNODE 4096
#define NIN   28
#define NE    131072
#define NEP   (NE + NNODE)
#define NH    8
#define NC    256
#define NHC   2048
#define HID   256
#define NOUT  128

// ---------------- fp32 scratch ----------------
#define OFF_G    ((size_t)0)
#define OFF_BSUM (OFF_G + (size_t)NNODE * 1024)
#define BIG_SZ   (OFF_BSUM + 1024)
__device__ float g_big[BIG_SZ];

__device__ float g_xp[2][(size_t)NNODE * NHC];
__device__ float g_as[2][NNODE * NH];
__device__ float g_ad[2][NNODE * NH];
__device__ float g_w [2][(size_t)NEP * NH];
__device__ int   g_mx[2][NNODE * NH];
__device__ int   g_cnt[2][NNODE];
__device__ int   g_cur[2][NNODE];
__device__ int   g_start[2][NNODE];
__device__ int   g_sorted[2][NE];
__device__ float g_part[2][128];
__device__ float g_mean[2];
__device__ float g_ce[2][NH];

// flash split-K partials
__device__ float g_po[(size_t)2 * NNODE * 256];
__device__ float g_pml[(size_t)2 * NNODE * 8];

// ---------------- bf16 hi/lo tensors ----------------
__device__ __nv_bfloat16 g_hth[(size_t)NNODE * NHC], g_htl[(size_t)NNODE * NHC];
__device__ __nv_bfloat16 g_hch[(size_t)NNODE * 256], g_hcl[(size_t)NNODE * 256];
__device__ __nv_bfloat16 g_qkvh[(size_t)NNODE * 768], g_qkvl[(size_t)NNODE * 768];
__device__ __nv_bfloat16 g_vth[(size_t)4 * 64 * NNODE], g_vtl[(size_t)4 * 64 * NNODE];
__device__ __nv_bfloat16 g_attnh[(size_t)NNODE * 256], g_attnl[(size_t)NNODE * 256];
__device__ __nv_bfloat16 g_hcath[(size_t)NNODE * 512], g_hcatl[(size_t)NNODE * 512];
__device__ __nv_bfloat16 g_hfush[(size_t)NNODE * 256], g_hfusl[(size_t)NNODE * 256];
// weights
__device__ __nv_bfloat16 g_wihh[1024 * 2048], g_wihl[1024 * 2048];
__device__ __nv_bfloat16 g_inwh[768 * 256],   g_inwl[768 * 256];
__device__ __nv_bfloat16 g_mowh[256 * 256],   g_mowl[256 * 256];
__device__ __nv_bfloat16 g_fuwh[256 * 512],   g_fuwl[256 * 512];
__device__ __nv_bfloat16 g_owh[128 * 256],    g_owl[128 * 256];
// padded x / W for tensor-core xp GEMM
__device__ __nv_bfloat16 g_xpadh[(size_t)NNODE * 64], g_xpadl[(size_t)NNODE * 64];
__device__ __nv_bfloat16 g_wpadh[(size_t)2 * NHC * 64], g_wpadl[(size_t)2 * NHC * 64];

// ---------------- helpers ----------------
__device__ __forceinline__ int   f2ord(float f){ int i = __float_as_int(f); return i >= 0 ? i : i ^ 0x7fffffff; }
__device__ __forceinline__ float ord2f(int k){ return __int_as_float(k >= 0 ? k : k ^ 0x7fffffff); }
__device__ __forceinline__ float sigmf(float x){ return 1.f / (1.f + expf(-x)); }
__device__ __forceinline__ void f2hl(float v, __nv_bfloat16* H, __nv_bfloat16* L, size_t i){
    __nv_bfloat16 h = __float2bfloat16(v);
    H[i] = h; L[i] = __float2bfloat16(v - __bfloat162float(h));
}
__device__ __forceinline__ uint32_t smem_u32(const void* p){
    uint32_t a;
    asm("{ .reg .u64 t; cvta.to.shared.u64 t, %1; cvt.u32.u64 %0, t; }" : "=r"(a) : "l"(p));
    return a;
}
__device__ __forceinline__ void ldm_x4(uint32_t* r, uint32_t addr){
    asm volatile("ldmatrix.sync.aligned.m8n8.x4.shared.b16 {%0,%1,%2,%3}, [%4];"
        : "=r"(r[0]), "=r"(r[1]), "=r"(r[2]), "=r"(r[3]) : "r"(addr));
}
__device__ __forceinline__ void ldm_x2(uint32_t* r, uint32_t addr){
    asm volatile("ldmatrix.sync.aligned.m8n8.x2.shared.b16 {%0,%1}, [%2];"
        : "=r"(r[0]), "=r"(r[1]) : "r"(addr));
}
__device__ __forceinline__ void mma_bf16(float* c, const uint32_t* a, const uint32_t* b){
    asm volatile("mma.sync.aligned.m16n8k16.row.col.f32.bf16.bf16.f32 "
        "{%0,%1,%2,%3}, {%4,%5,%6,%7}, {%8,%9}, {%0,%1,%2,%3};"
        : "+f"(c[0]), "+f"(c[1]), "+f"(c[2]), "+f"(c[3])
        : "r"(a[0]), "r"(a[1]), "r"(a[2]), "r"(a[3]), "r"(b[0]), "r"(b[1]));
}
__device__ __forceinline__ void cpa16(uint32_t saddr, const void* g){
    asm volatile("cp.async.ca.shared.global [%0], [%1], 16;" :: "r"(saddr), "l"(g));
}
__device__ __forceinline__ void cpa_commit(){ asm volatile("cp.async.commit_group;" ::: "memory"); }
__device__ __forceinline__ void splitpack(float a, float b, uint32_t& hi, uint32_t& lo){
    __nv_bfloat16 ha = __float2bfloat16(a), hb = __float2bfloat16(b);
    __nv_bfloat16 la = __float2bfloat16(a - __bfloat162float(ha));
    __nv_bfloat16 lb = __float2bfloat16(b - __bfloat162float(hb));
    hi = ((uint32_t)__bfloat16_as_ushort(hb) << 16) | (uint32_t)__bfloat16_as_ushort(ha);
    lo = ((uint32_t)__bfloat16_as_ushort(lb) << 16) | (uint32_t)__bfloat16_as_ushort(la);
}

// ================= setup (initmean + weight conversions, one launch) =================
#define CW0 2097152
#define CW1 (CW0 + 196608)
#define CW2 (CW1 + 65536)
#define CW3 (CW2 + 131072)
#define CW4 (CW3 + 32768)
#define CW5 (CW4 + NNODE * 64)
#define CW6 (CW5 + 2 * NHC * 64)
#define NCONVB ((CW6 + 255) / 256)

__global__ void k_initconv(const float* __restrict__ ea_t, const float* __restrict__ ea_c,
                           const float* __restrict__ w0, const float* __restrict__ w1,
                           const float* __restrict__ w2, const float* __restrict__ w3,
                           const float* __restrict__ w4, const float* __restrict__ x,
                           const float* __restrict__ W_t, const float* __restrict__ W_c){
    int bx = blockIdx.x;
    if (bx < 128){
        int idx = bx * 256 + threadIdx.x, stride = 128 * 256;
        int mi = f2ord(-FLT_MAX);
        for (int i = idx; i < NNODE * NH; i += stride){
            g_mx[0][i] = mi; g_mx[1][i] = mi;
            g_as[0][i] = 0.f; g_as[1][i] = 0.f;
            g_ad[0][i] = 0.f; g_ad[1][i] = 0.f;
        }
        for (int i = idx; i < NNODE; i += stride){
            g_cnt[0][i] = 0; g_cnt[1][i] = 0;
            g_cur[0][i] = 0; g_cur[1][i] = 0;
        }
        __shared__ float s0[256], s1[256];
        float a = 0.f, b = 0.f;
        for (int i = idx; i < NE; i += stride){ a += ea_t[i]; b += ea_c[i]; }
        s0[threadIdx.x] = a; s1[threadIdx.x] = b; __syncthreads();
        for (int s = 128; s; s >>= 1){
            if (threadIdx.x < s){ s0[threadIdx.x] += s0[threadIdx.x+s]; s1[threadIdx.x] += s1[threadIdx.x+s]; }
            __syncthreads();
        }
        if (!threadIdx.x){ g_part[0][bx] = s0[0]; g_part[1][bx] = s1[0]; }
        return;
    }
    int i = (bx - 128) * 256 + threadIdx.x;
    if (i < CW0)      f2hl(w0[i], g_wihh, g_wihl, i);
    else if (i < CW1) f2hl(w1[i - CW0], g_inwh, g_inwl, i - CW0);
    else if (i < CW2) f2hl(w2[i - CW1], g_mowh, g_mowl, i - CW1);
    else if (i < CW3) f2hl(w3[i - CW2], g_fuwh, g_fuwl, i - CW2);
    else if (i < CW4) f2hl(w4[i - CW3], g_owh, g_owl, i - CW3);
    else if (i < CW5){
        int j = i - CW4; int n = j >> 6, k = j & 63;
        float v = (k < NIN) ? x[n * NIN + k] : 0.f;
        f2hl(v, g_xpadh, g_xpadl, j);
    } else if (i < CW6){
        int j = i - CW5; int g = j >> 17; int r = j & 131071;
        int n = r >> 6, k = r & 63;
        const float* W = g ? W_c : W_t;
        float v = (k < NIN) ? W[k * NHC + n] : 0.f;
        f2hl(v, g_wpadh, g_wpadl, j);
    }
}

// ================= setup (means/ce/bsum) + edge count, one launch =================
__global__ void k_setupcount(const float* __restrict__ We_t, const float* __restrict__ ae_t,
                             const float* __restrict__ We_c, const float* __restrict__ ae_c,
                             const float* __restrict__ bih,  const float* __restrict__ bhh,
                             const int* __restrict__ dst_t, const int* __restrict__ dst_c){
    int bx = blockIdx.x;
    if (bx == 0){
        __shared__ float sh[256];
        int tid = threadIdx.x;
        for (int g = 0; g < 2; g++){
            sh[tid] = (tid < 128) ? g_part[g][tid] : 0.f;
            __syncthreads();
            for (int s = 128; s; s >>= 1){ if (tid < s) sh[tid] += sh[tid+s]; __syncthreads(); }
            if (!tid) g_mean[g] = sh[0] / (float)NE;
            __syncthreads();
        }
        int wid = tid >> 5, lane = tid & 31;
        for (int c = wid; c < 16; c += 8){
            int g = c >> 3, h = c & 7;
            const float* We = g ? We_c : We_t;
            const float* ae = g ? ae_c : ae_t;
            float s = 0.f;
            for (int i = lane; i < NC; i += 32) s = fmaf(We[h*NC + i], ae[h*NC + i], s);
            for (int o = 16; o; o >>= 1) s += __shfl_down_sync(0xffffffffu, s, o);
            if (!lane) g_ce[g][h] = s;
        }
        for (int j = tid; j < 1024; j += 256) g_big[OFF_BSUM + j] = bih[j] + bhh[j];
        return;
    }
    int idx = bx - 1;
    int g = idx >> 9;
    const int* dst = g ? dst_c : dst_t;
    int e = (idx & 511) * 256 + threadIdx.x;
    atomicAdd(&g_cnt[g][dst[e]], 1);
}

// 256-thread scan over 4096 counts (runs inside the xp mma_dual launch, z==2)
__device__ void scan_body(int g){
    __shared__ int sh[256];
    int tid = threadIdx.x;
    int base = tid * 16;
    int local[16]; int s = 0;
#pragma unroll
    for (int i = 0; i < 16; i++){ local[i] = g_cnt[g][base + i]; s += local[i]; }
    sh[tid] = s; __syncthreads();
    for (int off = 1; off < 256; off <<= 1){
        int v = (tid >= off) ? sh[tid - off] : 0;
        __syncthreads();
        sh[tid] += v;
        __syncthreads();
    }
    int run = sh[tid] - s;
#pragma unroll
    for (int i = 0; i < 16; i++){ g_start[g][base + i] = run; run += local[i]; }
}

// ================= GAT edge pipeline =================
__global__ void k_scatalpha(const int* __restrict__ src_t, const int* __restrict__ dst_t, const float* __restrict__ ea_t,
                            const int* __restrict__ src_c, const int* __restrict__ dst_c, const float* __restrict__ ea_c){
    int g = blockIdx.y;
    const int* src = g ? src_c : src_t;
    const int* dst = g ? dst_c : dst_t;
    const float* ea = g ? ea_c : ea_t;
    int e = blockIdx.x * 256 + threadIdx.x;
    if (e >= NEP) return;
    int s, d; float av;
    if (e < NE){
        s = src[e]; d = dst[e]; av = ea[e];
        int pos = g_start[g][d] + atomicAdd(&g_cur[g][d], 1);
        g_sorted[g][pos] = e;
    } else { s = d = e - NE; av = g_mean[g]; }
#pragma unroll
    for (int h = 0; h < NH; h++){
        float al = g_as[g][s*NH + h] + g_ad[g][d*NH + h] + av * g_ce[g][h];
        al = al > 0.f ? al : 0.2f * al;
        g_w[g][(size_t)e * NH + h] = al;
        atomicMax(&g_mx[g][d*NH + h], f2ord(al));
    }
}

// fused: exp + denominator + weighted aggregation
__global__ void __launch_bounds__(256) k_agg(const int* __restrict__ src_t, const int* __restrict__ src_c,
                                             const float* __restrict__ b_t, const float* __restrict__ b_c){
    int g = blockIdx.y;
    const int* src = g ? src_c : src_t;
    const float* bias = g ? b_c : b_t;
    int n = blockIdx.x, t = threadIdx.x;
    const float* xp = g_xp[g];
    const float* w  = g_w[g];

    __shared__ float smx[NH];
    __shared__ int   ssrc[32];
    __shared__ float sw[32][NH];
    if (t < NH) smx[t] = ord2f(g_mx[g][n*NH + t]);
    __syncthreads();

    float acc[NH], den[NH];
    {
        size_t e = (size_t)(NE + n) * NH;
        const float* xr = xp + (size_t)n * NHC + t;
#pragma unroll
        for (int h = 0; h < NH; h++){
            float exs = expf(w[e + h] - smx[h]);
            acc[h] = exs * xr[h * NC];
            den[h] = exs;
        }
    }
    int st = g_start[g][n], c = g_cnt[g][n];
    for (int i0 = 0; i0 < c; i0 += 32){
        int m = min(32, c - i0);
        __syncthreads();
        if (t < m) ssrc[t] = src[g_sorted[g][st + i0 + t]];
        {
            int j = t >> 3, h = t & 7;
            if (j < m) sw[j][h] = expf(w[(size_t)g_sorted[g][st + i0 + j] * NH + h] - smx[h]);
        }
        __syncthreads();
        int jj = 0;
        for (; jj + 4 <= m; jj += 4){
            const float* x0 = xp + (size_t)ssrc[jj+0] * NHC + t;
            const float* x1 = xp + (size_t)ssrc[jj+1] * NHC + t;
            const float* x2 = xp + (size_t)ssrc[jj+2] * NHC + t;
            const float* x3 = xp + (size_t)ssrc[jj+3] * NHC + t;
            float v0[NH], v1[NH], v2[NH], v3[NH];
#pragma unroll
            for (int h = 0; h < NH; h++){ v0[h] = x0[h*NC]; v1[h] = x1[h*NC]; v2[h] = x2[h*NC]; v3[h] = x3[h*NC]; }
#pragma unroll
            for (int h = 0; h < NH; h++){
                float w0 = sw[jj+0][h], w1 = sw[jj+1][h], w2 = sw[jj+2][h], w3 = sw[jj+3][h];
                acc[h] = fmaf(w0, v0[h], acc[h]);
                acc[h] = fmaf(w1, v1[h], acc[h]);
                acc[h] = fmaf(w2, v2[h], acc[h]);
                acc[h] = fmaf(w3, v3[h], acc[h]);
                den[h] += (w0 + w1) + (w2 + w3);
            }
        }
        for (; jj < m; jj++){
            const float* xr = xp + (size_t)ssrc[jj] * NHC + t;
#pragma unroll
            for (int h = 0; h < NH; h++){
                float ww = sw[jj][h];
                acc[h] = fmaf(ww, xr[h * NC], acc[h]);
                den[h] += ww;
            }
        }
    }
    if (g == 0){
#pragma unroll
        for (int h = 0; h < NH; h++){
            float v = acc[h] / (den[h] + 1e-16f) + bias[h * NC + t];
            f2hl(v, g_hth, g_htl, (size_t)n * NHC + h * NC + t);
        }
    } else {
        float s = 0.f;
#pragma unroll
        for (int h = 0; h < NH; h++) s += acc[h] / (den[h] + 1e-16f);
        f2hl(s * 0.125f + bias[t], g_hch, g_hcl, (size_t)n * NC + t);
    }
}

// ================= HMMA bf16x3 GEMM core =================
struct GA {
    const __nv_bfloat16 *Ah, *Al, *Bh, *Bl;
    float* C;
    __nv_bfloat16 *Ch, *Cl;
    const float* bias;
    const float *pas, *pad;
    float *oas, *oad;
    int lda, ldb, ldc, ldc2, c2off, K, act, gx;
    float alpha;
};

__device__ __forceinline__ void gemm_core(const GA a, int row0, int col0){
    extern __shared__ char sm[];
    int tid = threadIdx.x, lane = tid & 31, wid = tid >> 5;
    int wm = wid & 3, wn = wid >> 2;
    const __nv_bfloat16* Ah = a.Ah + (size_t)row0 * a.lda;
    const __nv_bfloat16* Al = a.Al + (size_t)row0 * a.lda;
    const __nv_bfloat16* Bh = a.Bh + (size_t)col0 * a.ldb;
    const __nv_bfloat16* Bl = a.Bl + (size_t)col0 * a.ldb;

    uint32_t sbase = smem_u32(sm);
    int nkb = a.K >> 6;

    auto issue = [&](int kb, int st){
        uint32_t su = sbase + st * 49152;
        int k0 = kb << 6;
#pragma unroll
        for (int it = 0; it < 4; it++){
            int i = tid + it * 256;
            int row = i >> 3, seg = i & 7;
            size_t goff = (size_t)row * a.lda + k0 + seg * 8;
            uint32_t so = row * 128 + ((seg ^ (row & 7)) << 4);
            cpa16(su + so,         Ah + goff);
            cpa16(su + 16384 + so, Al + goff);
        }
#pragma unroll
        for (int it = 0; it < 2; it++){
            int i = tid + it * 256;
            int row = i >> 3, seg = i & 7;
            size_t goff = (size_t)row * a.ldb + k0 + seg * 8;
            uint32_t so = row * 128 + ((seg ^ (row & 7)) << 4);
            cpa16(su + 32768 + so, Bh + goff);
            cpa16(su + 40960 + so, Bl + goff);
        }
        cpa_commit();
    };

    issue(0, 0);
    if (nkb > 1) issue(1, 1);

    float acc[2][4][4] = {};
    for (int kb = 0; kb < nkb; kb++){
        if (kb + 1 < nkb) asm volatile("cp.async.wait_group 1;" ::: "memory");
        else              asm volatile("cp.async.wait_group 0;" ::: "memory");
        __syncthreads();
        uint32_t sb2 = sbase + (kb & 1) * 49152;
#pragma unroll
        for (int ks = 0; ks < 4; ks++){
            uint32_t a_h[2][4], a_l[2][4], b_h[4][2], b_l[4][2];
#pragma unroll
            for (int mt = 0; mt < 2; mt++){
                int r = wm * 32 + mt * 16 + (lane & 15);
                int seg = ks * 2 + (lane >> 4);
                uint32_t ad = sb2 + r * 128 + ((seg ^ (r & 7)) << 4);
                ldm_x4(a_h[mt], ad);
                ldm_x4(a_l[mt], ad + 16384);
            }
#pragma unroll
            for (int nt = 0; nt < 4; nt++){
                int r = wn * 32 + nt * 8 + (lane & 7);
                int seg = ks * 2 + ((lane >> 3) & 1);
                uint32_t bd = sb2 + 32768 + r * 128 + ((seg ^ (r & 7)) << 4);
                ldm_x2(b_h[nt], bd);
                ldm_x2(b_l[nt], bd + 8192);
            }
#pragma unroll
            for (int mt = 0; mt < 2; mt++)
#pragma unroll
                for (int nt = 0; nt < 4; nt++){
                    mma_bf16(acc[mt][nt], a_h[mt], b_h[nt]);
                    mma_bf16(acc[mt][nt], a_h[mt], b_l[nt]);
                    mma_bf16(acc[mt][nt], a_l[mt], b_h[nt]);
                }
        }
        __syncthreads();
        if (kb + 2 < nkb) issue(kb + 2, kb & 1);
    }

    float s1[4] = {}, s2[4] = {};
    int h = col0 >> 8;
#pragma unroll
    for (int mt = 0; mt < 2; mt++){
#pragma unroll
        for (int nt = 0; nt < 4; nt++){
            int r0 = row0 + wm * 32 + mt * 16 + (lane >> 2);
            int c0 = col0 + wn * 32 + nt * 8 + ((lane & 3) << 1);
#pragma unroll
            for (int q = 0; q < 4; q++){
                int r = r0 + (q >> 1) * 8;
                int cc = c0 + (q & 1);
                float v = acc[mt][nt][q] * a.alpha;
                if (a.bias) v += a.bias[cc];
                if (a.act == 1) v = fmaxf(v, 0.f);
                if (a.C) a.C[(size_t)r * a.ldc + cc] = v;
                if (a.Ch) f2hl(v, a.Ch, a.Cl, (size_t)r * a.ldc2 + a.c2off + cc);
                if (a.pas){
                    int ridx = mt * 2 + (q >> 1);
                    int ci = h * 256 + (cc & 255);
                    s1[ridx] = fmaf(v, a.pas[ci], s1[ridx]);
                    s2[ridx] = fmaf(v, a.pad[ci], s2[ridx]);
                }
            }
        }
    }
    if (a.pas){
#pragma unroll
        for (int i = 0; i < 4; i++){
            s1[i] += __shfl_xor_sync(~0u, s1[i], 1); s1[i] += __shfl_xor_sync(~0u, s1[i], 2);
            s2[i] += __shfl_xor_sync(~0u, s2[i], 1); s2[i] += __shfl_xor_sync(~0u, s2[i], 2);
        }
        if ((lane & 3) == 0){
#pragma unroll
            for (int i = 0; i < 4; i++){
                int mt = i >> 1, rr = i & 1;
                int r = row0 + wm * 32 + mt * 16 + (lane >> 2) + rr * 8;
                atomicAdd(&a.oas[r * NH + h], s1[i]);
                atomicAdd(&a.oad[r * NH + h], s2[i]);
            }
        }
    }
}

__global__ void __launch_bounds__(256) mma_single(GA a){
    if ((int)blockIdx.x >= a.gx) return;
    gemm_core(a, blockIdx.y * 128, blockIdx.x * 64);
}
// z=0/1: the two xp GEMMs; z=2: the two edge-count prefix scans
__global__ void __launch_bounds__(256) mma_dual(GA a0, GA a1){
    if (blockIdx.z == 2){
        if (blockIdx.y == 0 && blockIdx.x < 2) scan_body(blockIdx.x);
        return;
    }
    GA a = blockIdx.z ? a1 : a0;
    if ((int)blockIdx.x >= a.gx) return;
    gemm_core(a, blockIdx.y * 128, blockIdx.x * 64);
}

// ================= flash attention body (split-KV) =================
__device__ void flash_body(
    const __nv_bfloat16* __restrict__ qkvh, const __nv_bfloat16* __restrict__ qkvl,
    const __nv_bfloat16* __restrict__ vth, const __nv_bfloat16* __restrict__ vtl,
    float* __restrict__ pO, float* __restrict__ pML,
    int row0, int head, int z)
{
    extern __shared__ char sm[];
    int tid = threadIdx.x, lane = tid & 31, wid = tid >> 5;
    int kv0 = z * 2048;
    uint32_t sb = smem_u32(sm);

    const __nv_bfloat16* Qh = qkvh + (size_t)row0 * 768 + head * 64;
    const __nv_bfloat16* Ql = qkvl + (size_t)row0 * 768 + head * 64;
    const __nv_bfloat16* Kh = qkvh + 256 + head * 64;
    const __nv_bfloat16* Kl = qkvl + 256 + head * 64;
    const __nv_bfloat16* Vh = vth + (size_t)head * 64 * 4096;
    const __nv_bfloat16* Vl = vtl + (size_t)head * 64 * 4096;

#pragma unroll
    for (int it = 0; it < 4; it++){
        int i = tid + it * 256;
        int r = i >> 3, seg = i & 7;
        uint32_t so = r * 128 + ((seg ^ (r & 7)) << 4);
        cpa16(sb + so,         Qh + (size_t)r * 768 + seg * 8);
        cpa16(sb + 16384 + so, Ql + (size_t)r * 768 + seg * 8);
    }
#pragma unroll
    for (int it = 0; it < 2; it++){
        int i = tid + it * 256;
        int r = i >> 3, seg = i & 7;
        uint32_t so = r * 128 + ((seg ^ (r & 7)) << 4);
        cpa16(sb + 32768 + so,         Kh + (size_t)(kv0 + r) * 768 + seg * 8);
        cpa16(sb + 32768 + 8192 + so,  Kl + (size_t)(kv0 + r) * 768 + seg * 8);
        cpa16(sb + 32768 + 16384 + so, Vh + (size_t)r * 4096 + kv0 + seg * 8);
        cpa16(sb + 32768 + 24576 + so, Vl + (size_t)r * 4096 + kv0 + seg * 8);
    }
    cpa_commit();
    asm volatile("cp.async.wait_group 0;" ::: "memory");
    __syncthreads();

    uint32_t qf_h[4][4], qf_l[4][4];
#pragma unroll
    for (int ks = 0; ks < 4; ks++){
        int r = wid * 16 + (lane & 15);
        int seg = ks * 2 + (lane >> 4);
        uint32_t ad = sb + r * 128 + ((seg ^ (r & 7)) << 4);
        ldm_x4(qf_h[ks], ad);
        ldm_x4(qf_l[ks], ad + 16384);
    }

    float m0 = -1e30f, m1 = -1e30f, l0 = 0.f, l1 = 0.f;
    float acc_o[8][4] = {};
    int buf = 0;

    for (int kt = 0; kt < 32; kt++){
        if (kt < 31){
            uint32_t bo = sb + 32768 + (buf ^ 1) * 32768;
            int key0 = kv0 + (kt + 1) * 64;
#pragma unroll
            for (int it = 0; it < 2; it++){
                int i = tid + it * 256;
                int r = i >> 3, seg = i & 7;
                uint32_t so = r * 128 + ((seg ^ (r & 7)) << 4);
                cpa16(bo + so,         Kh + (size_t)(key0 + r) * 768 + seg * 8);
                cpa16(bo + 8192 + so,  Kl + (size_t)(key0 + r) * 768 + seg * 8);
                cpa16(bo + 16384 + so, Vh + (size_t)r * 4096 + key0 + seg * 8);
                cpa16(bo + 24576 + so, Vl + (size_t)r * 4096 + key0 + seg * 8);
            }
            cpa_commit();
            asm volatile("cp.async.wait_group 1;" ::: "memory");
        } else {
            asm volatile("cp.async.wait_group 0;" ::: "memory");
        }
        __syncthreads();

        uint32_t kb = sb + 32768 + buf * 32768;

        float acc_s[8][4] = {};
#pragma unroll
        for (int ks = 0; ks < 4; ks++){
            uint32_t bh[8][2], bl[8][2];
#pragma unroll
            for (int nt = 0; nt < 8; nt++){
                int r = nt * 8 + (lane & 7);
                int seg = ks * 2 + ((lane >> 3) & 1);
                uint32_t bd = kb + r * 128 + ((seg ^ (r & 7)) << 4);
                ldm_x2(bh[nt], bd);
                ldm_x2(bl[nt], bd + 8192);
            }
#pragma unroll
            for (int nt = 0; nt < 8; nt++){
                mma_bf16(acc_s[nt], qf_h[ks], bh[nt]);
                mma_bf16(acc_s[nt], qf_h[ks], bl[nt]);
                mma_bf16(acc_s[nt], qf_l[ks], bh[nt]);
            }
        }
#pragma unroll
        for (int nt = 0; nt < 8; nt++){
            acc_s[nt][0] *= 0.125f; acc_s[nt][1] *= 0.125f;
            acc_s[nt][2] *= 0.125f; acc_s[nt][3] *= 0.125f;
        }

        float tm0 = -1e30f, tm1 = -1e30f;
#pragma unroll
        for (int nt = 0; nt < 8; nt++){
            tm0 = fmaxf(tm0, fmaxf(acc_s[nt][0], acc_s[nt][1]));
            tm1 = fmaxf(tm1, fmaxf(acc_s[nt][2], acc_s[nt][3]));
        }
        tm0 = fmaxf(tm0, __shfl_xor_sync(~0u, tm0, 1)); tm0 = fmaxf(tm0, __shfl_xor_sync(~0u, tm0, 2));
        tm1 = fmaxf(tm1, __shfl_xor_sync(~0u, tm1, 1)); tm1 = fmaxf(tm1, __shfl_xor_sync(~0u, tm1, 2));
        float mn0 = fmaxf(m0, tm0), mn1 = fmaxf(m1, tm1);
        float sc0 = __expf(m0 - mn0), sc1 = __expf(m1 - mn1);
        m0 = mn0; m1 = mn1;
        l0 *= sc0; l1 *= sc1;
#pragma unroll
        for (int nt = 0; nt < 8; nt++){
            acc_o[nt][0] *= sc0; acc_o[nt][1] *= sc0;
            acc_o[nt][2] *= sc1; acc_o[nt][3] *= sc1;
        }
        float rs0 = 0.f, rs1 = 0.f;
        uint32_t pa_h[4][4], pa_l[4][4];
#pragma unroll
        for (int nt = 0; nt < 8; nt++){
            float p0 = __expf(acc_s[nt][0] - mn0), p1 = __expf(acc_s[nt][1] - mn0);
            float p2 = __expf(acc_s[nt][2] - mn1), p3 = __expf(acc_s[nt][3] - mn1);
            rs0 += p0 + p1; rs1 += p2 + p3;
            int k2 = nt >> 1;
            if (!(nt & 1)){
                splitpack(p0, p1, pa_h[k2][0], pa_l[k2][0]);
                splitpack(p2, p3, pa_h[k2][1], pa_l[k2][1]);
            } else {
                splitpack(p0, p1, pa_h[k2][2], pa_l[k2][2]);
                splitpack(p2, p3, pa_h[k2][3], pa_l[k2][3]);
            }
        }
        rs0 += __shfl_xor_sync(~0u, rs0, 1); rs0 += __shfl_xor_sync(~0u, rs0, 2);
        rs1 += __shfl_xor_sync(~0u, rs1, 1); rs1 += __shfl_xor_sync(~0u, rs1, 2);
        l0 += rs0; l1 += rs1;

        uint32_t vb = kb + 16384;
#pragma unroll
        for (int k2 = 0; k2 < 4; k2++){
            uint32_t vh[8][2], vl[8][2];
#pragma unroll
            for (int nt = 0; nt < 8; nt++){
                int r = nt * 8 + (lane & 7);
                int seg = k2 * 2 + ((lane >> 3) & 1);
                uint32_t vd = vb + r * 128 + ((seg ^ (r & 7)) << 4);
                ldm_x2(vh[nt], vd);
                ldm_x2(vl[nt], vd + 8192);
            }
#pragma unroll
            for (int nt = 0; nt < 8; nt++){
                mma_bf16(acc_o[nt], pa_h[k2], vh[nt]);
                mma_bf16(acc_o[nt], pa_h[k2], vl[nt]);
                mma_bf16(acc_o[nt], pa_l[k2], vh[nt]);
            }
        }
        __syncthreads();
        buf ^= 1;
    }

    int r = row0 + wid * 16 + (lane >> 2);
    size_t ro0 = ((size_t)z * NNODE + r) * 256;
    size_t ro1 = ((size_t)z * NNODE + r + 8) * 256;
#pragma unroll
    for (int nt = 0; nt < 8; nt++){
        int cc = head * 64 + nt * 8 + ((lane & 3) << 1);
        pO[ro0 + cc]     = acc_o[nt][0];
        pO[ro0 + cc + 1] = acc_o[nt][1];
        pO[ro1 + cc]     = acc_o[nt][2];
        pO[ro1 + cc + 1] = acc_o[nt][3];
    }
    if ((lane & 3) == 0){
        pML[((size_t)z * NNODE + r) * 8 + head * 2]     = m0;
        pML[((size_t)z * NNODE + r) * 8 + head * 2 + 1] = l0;
        pML[((size_t)z * NNODE + r + 8) * 8 + head * 2]     = m1;
        pML[((size_t)z * NNODE + r + 8) * 8 + head * 2 + 1] = l1;
    }
}

// combo: blocks 0..255 = flash; 256..767 = LSTM-gates GEMM
__global__ void __launch_bounds__(256) k_combo(
    GA a,
    const __nv_bfloat16* __restrict__ qkvh, const __nv_bfloat16* __restrict__ qkvl,
    const __nv_bfloat16* __restrict__ vth, const __nv_bfloat16* __restrict__ vtl,
    float* __restrict__ pO, float* __restrict__ pML)
{
    int bx = blockIdx.x;
    if (bx < 256){
        int row0 = (bx & 31) * 128;
        int head = (bx >> 5) & 3;
        int z = bx >> 7;
        flash_body(qkvh, qkvl, vth, vtl, pO, pML, row0, head, z);
    } else {
        int idx = bx - 256;
        gemm_core(a, (idx >> 4) * 128, (idx & 15) * 64);
    }
}

// ================= pointwise =================
__global__ void k_vt(const __nv_bfloat16* __restrict__ qh, const __nv_bfloat16* __restrict__ ql,
                     __nv_bfloat16* __restrict__ vh, __nv_bfloat16* __restrict__ vl){
    int idx = blockIdx.x * 256 + threadIdx.x;
    int hd = idx >> 12, n = idx & 4095;
    size_t s = (size_t)n * 768 + 512 + hd;
    vh[idx] = qh[s]; vl[idx] = ql[s];
}

__global__ void k_mergelstm(const float* __restrict__ pO, const float* __restrict__ pML,
                            __nv_bfloat16* __restrict__ Oh, __nv_bfloat16* __restrict__ Ol,
                            const float* __restrict__ G, float* __restrict__ ht_out){
    int b = blockIdx.x;
    if (b < NNODE){
        int row = b, col = threadIdx.x;
        int head = col >> 6;
        float m0 = pML[(size_t)row * 8 + head * 2],            l0 = pML[(size_t)row * 8 + head * 2 + 1];
        float m1 = pML[((size_t)NNODE + row) * 8 + head * 2],  l1 = pML[((size_t)NNODE + row) * 8 + head * 2 + 1];
        float mx = fmaxf(m0, m1);
        float w0 = __expf(m0 - mx), w1 = __expf(m1 - mx);
        float num = pO[(size_t)row * 256 + col] * w0 + pO[((size_t)NNODE + row) * 256 + col] * w1;
        float den = l0 * w0 + l1 * w1;
        f2hl(num / den, Oh, Ol, (size_t)row * 256 + col);
    } else {
        int idx = (b - NNODE) * 256 + threadIdx.x;
        int n = idx >> 8, j = idx & 255;
        const float* gr = G + (size_t)n * 1024;
        float ig = gr[j], gg = gr[512 + j], og = gr[768 + j];
        float cc = sigmf(ig) * tanhf(gg);
        float hv = sigmf(og) * tanhf(cc);
        ht_out[idx] = hv;
        f2hl(hv, g_hcath, g_hcatl, (size_t)n * 512 + j);
    }
}

// ================= launch =================
#define SYMADDR(p, s) do { void* _t; cudaGetSymbolAddress(&_t, s); p = (decltype(p))_t; } while(0)

extern "C" void kernel_launch(void* const* d_in, const int* in_sizes, int n_in,
                              void* d_out, int out_size) {
    const float* x     = (const float*)d_in[0];
    const int*   ei_t  = (const int*)d_in[1];
    const int*   ei_c  = (const int*)d_in[2];
    const float* ea_t  = (const float*)d_in[3];
    const float* ea_c  = (const float*)d_in[4];
    const float* W_t   = (const float*)d_in[5];
    const float* asrc_t= (const float*)d_in[6];
    const float* adst_t= (const float*)d_in[7];
    const float* We_t  = (const float*)d_in[8];
    const float* ae_t  = (const float*)d_in[9];
    const float* b_t   = (const float*)d_in[10];
    const float* W_c   = (const float*)d_in[11];
    const float* asrc_c= (const float*)d_in[12];
    const float* adst_c= (const float*)d_in[13];
    const float* We_c  = (const float*)d_in[14];
    const float* ae_c  = (const float*)d_in[15];
    const float* b_c   = (const float*)d_in[16];
    const float* lstm_Wih = (const float*)d_in[17];
    const float* lstm_bih = (const float*)d_in[19];
    const float* lstm_bhh = (const float*)d_in[20];
    const float* mha_in_w  = (const float*)d_in[21];
    const float* mha_in_b  = (const float*)d_in[22];
    const float* mha_out_w = (const float*)d_in[23];
    const float* mha_out_b = (const float*)d_in[24];
    const float* fus_w = (const float*)d_in[25];
    const float* fus_b = (const float*)d_in[26];
    const float* out_w = (const float*)d_in[27];
    const float* out_b = (const float*)d_in[28];

    float* big; SYMADDR(big, g_big);
    float* po;  SYMADDR(po, g_po);
    float* pml; SYMADDR(pml, g_pml);
    float* xp0; SYMADDR(xp0, g_xp);
    float* xp1 = xp0 + (size_t)NNODE * NHC;
    float* as0; SYMADDR(as0, g_as);
    float* as1 = as0 + NNODE * NH;
    float* ad0; SYMADDR(ad0, g_ad);
    float* ad1 = ad0 + NNODE * NH;
    __nv_bfloat16 *hth, *htl, *hch, *hcl, *qkvh, *qkvl, *vth, *vtl;
    __nv_bfloat16 *attnh, *attnl, *hcath, *hcatl, *hfush, *hfusl;
    __nv_bfloat16 *wihh, *wihl, *inwh, *inwl, *mowh, *mowl, *fuwh, *fuwl, *owh, *owl;
    __nv_bfloat16 *xpadh, *xpadl, *wpadh, *wpadl;
    SYMADDR(hth, g_hth); SYMADDR(htl, g_htl); SYMADDR(hch, g_hch); SYMADDR(hcl, g_hcl);
    SYMADDR(qkvh, g_qkvh); SYMADDR(qkvl, g_qkvl); SYMADDR(vth, g_vth); SYMADDR(vtl, g_vtl);
    SYMADDR(attnh, g_attnh); SYMADDR(attnl, g_attnl);
    SYMADDR(hcath, g_hcath); SYMADDR(hcatl, g_hcatl);
    SYMADDR(hfush, g_hfush); SYMADDR(hfusl, g_hfusl);
    SYMADDR(wihh, g_wihh); SYMADDR(wihl, g_wihl);
    SYMADDR(inwh, g_inwh); SYMADDR(inwl, g_inwl);
    SYMADDR(mowh, g_mowh); SYMADDR(mowl, g_mowl);
    SYMADDR(fuwh, g_fuwh); SYMADDR(fuwl, g_fuwl);
    SYMADDR(owh, g_owh); SYMADDR(owl, g_owl);
    SYMADDR(xpadh, g_xpadh); SYMADDR(xpadl, g_xpadl);
    SYMADDR(wpadh, g_wpadh); SYMADDR(wpadl, g_wpadl);

    cudaFuncSetAttribute(k_combo,  cudaFuncAttributeMaxDynamicSharedMemorySize, 98304);
    cudaFuncSetAttribute(mma_single, cudaFuncAttributeMaxDynamicSharedMemorySize, 98304);
    cudaFuncSetAttribute(mma_dual, cudaFuncAttributeMaxDynamicSharedMemorySize, 98304);
    const int DYN = 98304;

    float* out_main = (float*)d_out;
    float* out_ht   = out_main + (size_t)NNODE * NOUT;
    float* out_hc   = out_ht   + (size_t)NNODE * HID;

    const int* src_t = ei_t; const int* dst_t = ei_t + NE;
    const int* src_c = ei_c; const int* dst_c = ei_c + NE;
    int nepb = (NEP + 255) / 256;

    // init + edge means + all weight/x conversions (one launch)
    k_initconv<<<128 + NCONVB, 256>>>(ea_t, ea_c, lstm_Wih, mha_in_w, mha_out_w, fus_w, out_w, x, W_t, W_c);
    // means/ce/bsum + edge count (one launch)
    k_setupcount<<<1 + 1024, 256>>>(We_t, ae_t, We_c, ae_c, lstm_bih, lstm_bhh, dst_t, dst_c);

    // ---- xp GEMMs (z=0/1) + count prefix scans (z=2) ----
    {
        GA a0 = { xpadh, xpadl, wpadh, wpadl, xp0, nullptr, nullptr, nullptr,
                  asrc_t, adst_t, as0, ad0,
                  64, 64, NHC, 0, 0, 64, 0, 32, 1.f };
        GA a1 = { xpadh, xpadl, wpadh + (size_t)NHC * 64, wpadl + (size_t)NHC * 64, xp1,
                  nullptr, nullptr, nullptr,
                  asrc_c, adst_c, as1, ad1,
                  64, 64, NHC, 0, 0, 64, 0, 32, 1.f };
        mma_dual<<<dim3(32, 32, 3), 256, DYN>>>(a0, a1);
    }

    // ---- edge scatter + logits + seg-max ----
    k_scatalpha<<<dim3(nepb, 2), 256>>>(src_t, dst_t, ea_t, src_c, dst_c, ea_c);

    // ---- aggregation, both graphs concurrently (R11-winning shape) ----
    k_agg<<<dim3(NNODE, 2), 256>>>(src_t, src_c, b_t, b_c);

    // ---- qkv GEMM (4096x768x256) ----
    {
        GA a = { hch, hcl, inwh, inwl, nullptr, qkvh, qkvl, mha_in_b,
                 nullptr, nullptr, nullptr, nullptr,
                 256, 256, 0, 768, 0, 256, 0, 12, 1.f };
        mma_single<<<dim3(12, 32), 256, DYN>>>(a);
    }
    k_vt<<<(4*64*NNODE)/256, 256>>>(qkvh, qkvl, vth, vtl);

    // ---- flash attention + LSTM gates GEMM overlapped ----
    {
        GA a = { hth, htl, wihh, wihl, big + OFF_G, nullptr, nullptr, big + OFF_BSUM,
                 nullptr, nullptr, nullptr, nullptr,
                 NHC, NHC, 1024, 0, 0, NHC, 0, 16, 1.f };
        k_combo<<<768, 256, DYN>>>(a, qkvh, qkvl, vth, vtl, po, pml);
    }

    // ---- merge flash partials + lstm pointwise ----
    k_mergelstm<<<2 * NNODE, 256>>>(po, pml, attnh, attnl, big + OFF_G, out_ht);

    // ---- proj (4096x256x256) ----
    {
        GA a = { attnh, attnl, mowh, mowl, out_hc, hcath, hcatl, mha_out_b,
                 nullptr, nullptr, nullptr, nullptr,
                 256, 256, 256, 512, 256, 256, 0, 4, 1.f };
        mma_single<<<dim3(4, 32), 256, DYN>>>(a);
    }
    // ---- fusion relu (4096x256x512) ----
    {
        GA a = { hcath, hcatl, fuwh, fuwl, nullptr, hfush, hfusl, fus_b,
                 nullptr, nullptr, nullptr, nullptr,
                 512, 512, 0, 256, 0, 512, 1, 4, 1.f };
        mma_single<<<dim3(4, 32), 256, DYN>>>(a);
    }
    // ---- out (4096x128x256) ----
    {
        GA a = { hfush, hfusl, owh, owl, out_main, nullptr, nullptr, out_b,
                 nullptr, nullptr, nullptr, nullptr,
                 256, 256, NOUT, 0, 0, 256, 0, 2, 1.f };
        mma_single<<<dim3(2, 32), 256, DYN>>>(a);
    }
}

// round 14
// speedup vs baseline: 1.0847x; 1.0190x over previous
#include <cuda_runtime.h>
#include <cuda_bf16.h>
#include <math.h>
#include <float.h>
#include <stdint.h>

#define NNODE 4096
#define NIN   28
#define NE    131072
#define NEP   (NE + NNODE)
#define NH    8
#define NC    256
#define NHC   2048
#define HID   256
#define NOUT  128

// ---------------- fp32 scratch ----------------
#define OFF_G    ((size_t)0)
#define OFF_BSUM (OFF_G + (size_t)NNODE * 1024)
#define BIG_SZ   (OFF_BSUM + 1024)
__device__ float g_big[BIG_SZ];

__device__ float g_xp[2][(size_t)NNODE * NHC];
__device__ float g_as[2][NNODE * NH];
__device__ float g_ad[2][NNODE * NH];
__device__ float g_w [2][(size_t)NEP * NH];
__device__ int   g_cnt[2][NNODE];
__device__ int   g_cur[2][NNODE];
__device__ int   g_start[2][NNODE];
__device__ int   g_sorted[2][NE];
__device__ float g_part[2][128];
__device__ float g_mean[2];
__device__ float g_ce[2][NH];

// flash split-K partials
__device__ float g_po[(size_t)2 * NNODE * 256];
__device__ float g_pml[(size_t)2 * NNODE * 8];

// ---------------- bf16 hi/lo tensors ----------------
__device__ __nv_bfloat16 g_hth[(size_t)NNODE * NHC], g_htl[(size_t)NNODE * NHC];
__device__ __nv_bfloat16 g_hch[(size_t)NNODE * 256], g_hcl[(size_t)NNODE * 256];
__device__ __nv_bfloat16 g_qkvh[(size_t)NNODE * 768], g_qkvl[(size_t)NNODE * 768];
__device__ __nv_bfloat16 g_vth[(size_t)4 * 64 * NNODE], g_vtl[(size_t)4 * 64 * NNODE];
__device__ __nv_bfloat16 g_attnh[(size_t)NNODE * 256], g_attnl[(size_t)NNODE * 256];
__device__ __nv_bfloat16 g_hcath[(size_t)NNODE * 512], g_hcatl[(size_t)NNODE * 512];
__device__ __nv_bfloat16 g_hfush[(size_t)NNODE * 256], g_hfusl[(size_t)NNODE * 256];
// weights
__device__ __nv_bfloat16 g_wihh[1024 * 2048], g_wihl[1024 * 2048];
__device__ __nv_bfloat16 g_inwh[768 * 256],   g_inwl[768 * 256];
__device__ __nv_bfloat16 g_mowh[256 * 256],   g_mowl[256 * 256];
__device__ __nv_bfloat16 g_fuwh[256 * 512],   g_fuwl[256 * 512];
__device__ __nv_bfloat16 g_owh[128 * 256],    g_owl[128 * 256];
// padded x / W for tensor-core xp GEMM
__device__ __nv_bfloat16 g_xpadh[(size_t)NNODE * 64], g_xpadl[(size_t)NNODE * 64];
__device__ __nv_bfloat16 g_wpadh[(size_t)2 * NHC * 64], g_wpadl[(size_t)2 * NHC * 64];

// ---------------- helpers ----------------
__device__ __forceinline__ int   f2ord(float f){ int i = __float_as_int(f); return i >= 0 ? i : i ^ 0x7fffffff; }
__device__ __forceinline__ float ord2f(int k){ return __int_as_float(k >= 0 ? k : k ^ 0x7fffffff); }
__device__ __forceinline__ float sigmf(float x){ return 1.f / (1.f + expf(-x)); }
__device__ __forceinline__ void f2hl(float v, __nv_bfloat16* H, __nv_bfloat16* L, size_t i){
    __nv_bfloat16 h = __float2bfloat16(v);
    H[i] = h; L[i] = __float2bfloat16(v - __bfloat162float(h));
}
__device__ __forceinline__ uint32_t smem_u32(const void* p){
    uint32_t a;
    asm("{ .reg .u64 t; cvta.to.shared.u64 t, %1; cvt.u32.u64 %0, t; }" : "=r"(a) : "l"(p));
    return a;
}
__device__ __forceinline__ void ldm_x4(uint32_t* r, uint32_t addr){
    asm volatile("ldmatrix.sync.aligned.m8n8.x4.shared.b16 {%0,%1,%2,%3}, [%4];"
        : "=r"(r[0]), "=r"(r[1]), "=r"(r[2]), "=r"(r[3]) : "r"(addr));
}
__device__ __forceinline__ void ldm_x2(uint32_t* r, uint32_t addr){
    asm volatile("ldmatrix.sync.aligned.m8n8.x2.shared.b16 {%0,%1}, [%2];"
        : "=r"(r[0]), "=r"(r[1]) : "r"(addr));
}
__device__ __forceinline__ void mma_bf16(float* c, const uint32_t* a, const uint32_t* b){
    asm volatile("mma.sync.aligned.m16n8k16.row.col.f32.bf16.bf16.f32 "
        "{%0,%1,%2,%3}, {%4,%5,%6,%7}, {%8,%9}, {%0,%1,%2,%3};"
        : "+f"(c[0]), "+f"(c[1]), "+f"(c[2]), "+f"(c[3])
        : "r"(a[0]), "r"(a[1]), "r"(a[2]), "r"(a[3]), "r"(b[0]), "r"(b[1]));
}
__device__ __forceinline__ void cpa16(uint32_t saddr, const void* g){
    asm volatile("cp.async.ca.shared.global [%0], [%1], 16;" :: "r"(saddr), "l"(g));
}
__device__ __forceinline__ void cpa_commit(){ asm volatile("cp.async.commit_group;" ::: "memory"); }
__device__ __forceinline__ void splitpack(float a, float b, uint32_t& hi, uint32_t& lo){
    __nv_bfloat16 ha = __float2bfloat16(a), hb = __float2bfloat16(b);
    __nv_bfloat16 la = __float2bfloat16(a - __bfloat162float(ha));
    __nv_bfloat16 lb = __float2bfloat16(b - __bfloat162float(hb));
    hi = ((uint32_t)__bfloat16_as_ushort(hb) << 16) | (uint32_t)__bfloat16_as_ushort(ha);
    lo = ((uint32_t)__bfloat16_as_ushort(lb) << 16) | (uint32_t)__bfloat16_as_ushort(la);
}

// ================= setup (initmean + weight conversions, one launch) =================
#define CW0 2097152
#define CW1 (CW0 + 196608)
#define CW2 (CW1 + 65536)
#define CW3 (CW2 + 131072)
#define CW4 (CW3 + 32768)
#define CW5 (CW4 + NNODE * 64)
#define CW6 (CW5 + 2 * NHC * 64)
#define NCONVB ((CW6 + 255) / 256)

__global__ void k_initconv(const float* __restrict__ ea_t, const float* __restrict__ ea_c,
                           const float* __restrict__ w0, const float* __restrict__ w1,
                           const float* __restrict__ w2, const float* __restrict__ w3,
                           const float* __restrict__ w4, const float* __restrict__ x,
                           const float* __restrict__ W_t, const float* __restrict__ W_c){
    int bx = blockIdx.x;
    if (bx < 128){
        int idx = bx * 256 + threadIdx.x, stride = 128 * 256;
        for (int i = idx; i < NNODE * NH; i += stride){
            g_as[0][i] = 0.f; g_as[1][i] = 0.f;
            g_ad[0][i] = 0.f; g_ad[1][i] = 0.f;
        }
        for (int i = idx; i < NNODE; i += stride){
            g_cnt[0][i] = 0; g_cnt[1][i] = 0;
            g_cur[0][i] = 0; g_cur[1][i] = 0;
        }
        __shared__ float s0[256], s1[256];
        float a = 0.f, b = 0.f;
        for (int i = idx; i < NE; i += stride){ a += ea_t[i]; b += ea_c[i]; }
        s0[threadIdx.x] = a; s1[threadIdx.x] = b; __syncthreads();
        for (int s = 128; s; s >>= 1){
            if (threadIdx.x < s){ s0[threadIdx.x] += s0[threadIdx.x+s]; s1[threadIdx.x] += s1[threadIdx.x+s]; }
            __syncthreads();
        }
        if (!threadIdx.x){ g_part[0][bx] = s0[0]; g_part[1][bx] = s1[0]; }
        return;
    }
    int i = (bx - 128) * 256 + threadIdx.x;
    if (i < CW0)      f2hl(w0[i], g_wihh, g_wihl, i);
    else if (i < CW1) f2hl(w1[i - CW0], g_inwh, g_inwl, i - CW0);
    else if (i < CW2) f2hl(w2[i - CW1], g_mowh, g_mowl, i - CW1);
    else if (i < CW3) f2hl(w3[i - CW2], g_fuwh, g_fuwl, i - CW2);
    else if (i < CW4) f2hl(w4[i - CW3], g_owh, g_owl, i - CW3);
    else if (i < CW5){
        int j = i - CW4; int n = j >> 6, k = j & 63;
        float v = (k < NIN) ? x[n * NIN + k] : 0.f;
        f2hl(v, g_xpadh, g_xpadl, j);
    } else if (i < CW6){
        int j = i - CW5; int g = j >> 17; int r = j & 131071;
        int n = r >> 6, k = r & 63;
        const float* W = g ? W_c : W_t;
        float v = (k < NIN) ? W[k * NHC + n] : 0.f;
        f2hl(v, g_wpadh, g_wpadl, j);
    }
}

// ================= setup (means/ce/bsum) + edge count, one launch =================
__global__ void k_setupcount(const float* __restrict__ We_t, const float* __restrict__ ae_t,
                             const float* __restrict__ We_c, const float* __restrict__ ae_c,
                             const float* __restrict__ bih,  const float* __restrict__ bhh,
                             const int* __restrict__ dst_t, const int* __restrict__ dst_c){
    int bx = blockIdx.x;
    if (bx == 0){
        __shared__ float sh[256];
        int tid = threadIdx.x;
        for (int g = 0; g < 2; g++){
            sh[tid] = (tid < 128) ? g_part[g][tid] : 0.f;
            __syncthreads();
            for (int s = 128; s; s >>= 1){ if (tid < s) sh[tid] += sh[tid+s]; __syncthreads(); }
            if (!tid) g_mean[g] = sh[0] / (float)NE;
            __syncthreads();
        }
        int wid = tid >> 5, lane = tid & 31;
        for (int c = wid; c < 16; c += 8){
            int g = c >> 3, h = c & 7;
            const float* We = g ? We_c : We_t;
            const float* ae = g ? ae_c : ae_t;
            float s = 0.f;
            for (int i = lane; i < NC; i += 32) s = fmaf(We[h*NC + i], ae[h*NC + i], s);
            for (int o = 16; o; o >>= 1) s += __shfl_down_sync(0xffffffffu, s, o);
            if (!lane) g_ce[g][h] = s;
        }
        for (int j = tid; j < 1024; j += 256) g_big[OFF_BSUM + j] = bih[j] + bhh[j];
        return;
    }
    int idx = bx - 1;
    int g = idx >> 9;
    const int* dst = g ? dst_c : dst_t;
    int e = (idx & 511) * 256 + threadIdx.x;
    atomicAdd(&g_cnt[g][dst[e]], 1);
}

// 256-thread scan over 4096 counts (runs inside the xp mma_dual launch, z==2)
__device__ void scan_body(int g){
    __shared__ int sh[256];
    int tid = threadIdx.x;
    int base = tid * 16;
    int local[16]; int s = 0;
#pragma unroll
    for (int i = 0; i < 16; i++){ local[i] = g_cnt[g][base + i]; s += local[i]; }
    sh[tid] = s; __syncthreads();
    for (int off = 1; off < 256; off <<= 1){
        int v = (tid >= off) ? sh[tid - off] : 0;
        __syncthreads();
        sh[tid] += v;
        __syncthreads();
    }
    int run = sh[tid] - s;
#pragma unroll
    for (int i = 0; i < 16; i++){ g_start[g][base + i] = run; run += local[i]; }
}

// ================= GAT edge pipeline =================
// scatter + logits (vectorized); seg-max moved into k_agg prepass
__global__ void k_scatalpha(const int* __restrict__ src_t, const int* __restrict__ dst_t, const float* __restrict__ ea_t,
                            const int* __restrict__ src_c, const int* __restrict__ dst_c, const float* __restrict__ ea_c){
    int g = blockIdx.y;
    const int* src = g ? src_c : src_t;
    const int* dst = g ? dst_c : dst_t;
    const float* ea = g ? ea_c : ea_t;
    int e = blockIdx.x * 256 + threadIdx.x;
    if (e >= NEP) return;
    int s, d; float av;
    if (e < NE){
        s = src[e]; d = dst[e]; av = ea[e];
        int pos = g_start[g][d] + atomicAdd(&g_cur[g][d], 1);
        g_sorted[g][pos] = e;
    } else { s = d = e - NE; av = g_mean[g]; }
    float4 s0 = *(const float4*)&g_as[g][s*NH];
    float4 s1 = *(const float4*)&g_as[g][s*NH + 4];
    float4 d0 = *(const float4*)&g_ad[g][d*NH];
    float4 d1 = *(const float4*)&g_ad[g][d*NH + 4];
    float4 c0 = *(const float4*)&g_ce[g][0];
    float4 c1 = *(const float4*)&g_ce[g][4];
    float4 o0, o1;
    o0.x = s0.x + d0.x + av * c0.x;  o0.y = s0.y + d0.y + av * c0.y;
    o0.z = s0.z + d0.z + av * c0.z;  o0.w = s0.w + d0.w + av * c0.w;
    o1.x = s1.x + d1.x + av * c1.x;  o1.y = s1.y + d1.y + av * c1.y;
    o1.z = s1.z + d1.z + av * c1.z;  o1.w = s1.w + d1.w + av * c1.w;
    o0.x = o0.x > 0.f ? o0.x : 0.2f * o0.x;  o0.y = o0.y > 0.f ? o0.y : 0.2f * o0.y;
    o0.z = o0.z > 0.f ? o0.z : 0.2f * o0.z;  o0.w = o0.w > 0.f ? o0.w : 0.2f * o0.w;
    o1.x = o1.x > 0.f ? o1.x : 0.2f * o1.x;  o1.y = o1.y > 0.f ? o1.y : 0.2f * o1.y;
    o1.z = o1.z > 0.f ? o1.z : 0.2f * o1.z;  o1.w = o1.w > 0.f ? o1.w : 0.2f * o1.w;
    *(float4*)&g_w[g][(size_t)e * NH]     = o0;
    *(float4*)&g_w[g][(size_t)e * NH + 4] = o1;
}

// fused: per-node max prepass + exp + denominator + weighted aggregation
__global__ void __launch_bounds__(256) k_agg(const int* __restrict__ src_t, const int* __restrict__ src_c,
                                             const float* __restrict__ b_t, const float* __restrict__ b_c){
    int g = blockIdx.y;
    const int* src = g ? src_c : src_t;
    const float* bias = g ? b_c : b_t;
    int n = blockIdx.x, t = threadIdx.x;
    const float* xp = g_xp[g];
    const float* w  = g_w[g];

    __shared__ int   smxi[NH];
    __shared__ float smx[NH];
    __shared__ int   ssrc[32];
    __shared__ float sw[32][NH];
    if (t < NH) smxi[t] = f2ord(-FLT_MAX);
    __syncthreads();

    int st = g_start[g][n], c = g_cnt[g][n];

    // ---- max prepass over self-loop + incoming edges (exact, order-indep) ----
    {
        float lm[NH];
        if (t == 0){
            const float* ws = w + (size_t)(NE + n) * NH;
            float4 a = *(const float4*)ws, b = *(const float4*)(ws + 4);
            lm[0]=a.x; lm[1]=a.y; lm[2]=a.z; lm[3]=a.w; lm[4]=b.x; lm[5]=b.y; lm[6]=b.z; lm[7]=b.w;
        } else {
#pragma unroll
            for (int h = 0; h < NH; h++) lm[h] = -FLT_MAX;
        }
        for (int i = t; i < c; i += 256){
            const float* we = w + (size_t)g_sorted[g][st + i] * NH;
            float4 a = *(const float4*)we, b = *(const float4*)(we + 4);
            lm[0]=fmaxf(lm[0],a.x); lm[1]=fmaxf(lm[1],a.y); lm[2]=fmaxf(lm[2],a.z); lm[3]=fmaxf(lm[3],a.w);
            lm[4]=fmaxf(lm[4],b.x); lm[5]=fmaxf(lm[5],b.y); lm[6]=fmaxf(lm[6],b.z); lm[7]=fmaxf(lm[7],b.w);
        }
#pragma unroll
        for (int h = 0; h < NH; h++){
            for (int o = 16; o; o >>= 1) lm[h] = fmaxf(lm[h], __shfl_xor_sync(~0u, lm[h], o));
        }
        if ((t & 31) == 0){
#pragma unroll
            for (int h = 0; h < NH; h++) atomicMax(&smxi[h], f2ord(lm[h]));
        }
    }
    __syncthreads();
    if (t < NH) smx[t] = ord2f(smxi[t]);
    __syncthreads();

    float acc[NH], den[NH];
    {
        size_t e = (size_t)(NE + n) * NH;
        const float* xr = xp + (size_t)n * NHC + t;
#pragma unroll
        for (int h = 0; h < NH; h++){
            float exs = expf(w[e + h] - smx[h]);
            acc[h] = exs * xr[h * NC];
            den[h] = exs;
        }
    }
    for (int i0 = 0; i0 < c; i0 += 32){
        int m = min(32, c - i0);
        __syncthreads();
        if (t < m) ssrc[t] = src[g_sorted[g][st + i0 + t]];
        {
            int j = t >> 3, h = t & 7;
            if (j < m) sw[j][h] = expf(w[(size_t)g_sorted[g][st + i0 + j] * NH + h] - smx[h]);
        }
        __syncthreads();
        int jj = 0;
        for (; jj + 4 <= m; jj += 4){
            const float* x0 = xp + (size_t)ssrc[jj+0] * NHC + t;
            const float* x1 = xp + (size_t)ssrc[jj+1] * NHC + t;
            const float* x2 = xp + (size_t)ssrc[jj+2] * NHC + t;
            const float* x3 = xp + (size_t)ssrc[jj+3] * NHC + t;
            float v0[NH], v1[NH], v2[NH], v3[NH];
#pragma unroll
            for (int h = 0; h < NH; h++){ v0[h] = x0[h*NC]; v1[h] = x1[h*NC]; v2[h] = x2[h*NC]; v3[h] = x3[h*NC]; }
#pragma unroll
            for (int h = 0; h < NH; h++){
                float w0 = sw[jj+0][h], w1 = sw[jj+1][h], w2 = sw[jj+2][h], w3 = sw[jj+3][h];
                acc[h] = fmaf(w0, v0[h], acc[h]);
                acc[h] = fmaf(w1, v1[h], acc[h]);
                acc[h] = fmaf(w2, v2[h], acc[h]);
                acc[h] = fmaf(w3, v3[h], acc[h]);
                den[h] += (w0 + w1) + (w2 + w3);
            }
        }
        for (; jj < m; jj++){
            const float* xr = xp + (size_t)ssrc[jj] * NHC + t;
#pragma unroll
            for (int h = 0; h < NH; h++){
                float ww = sw[jj][h];
                acc[h] = fmaf(ww, xr[h * NC], acc[h]);
                den[h] += ww;
            }
        }
    }
    if (g == 0){
#pragma unroll
        for (int h = 0; h < NH; h++){
            float v = acc[h] / (den[h] + 1e-16f) + bias[h * NC + t];
            f2hl(v, g_hth, g_htl, (size_t)n * NHC + h * NC + t);
        }
    } else {
        float s = 0.f;
#pragma unroll
        for (int h = 0; h < NH; h++) s += acc[h] / (den[h] + 1e-16f);
        f2hl(s * 0.125f + bias[t], g_hch, g_hcl, (size_t)n * NC + t);
    }
}

// ================= HMMA bf16x3 GEMM core =================
struct GA {
    const __nv_bfloat16 *Ah, *Al, *Bh, *Bl;
    float* C;
    __nv_bfloat16 *Ch, *Cl;
    const float* bias;
    const float *pas, *pad;
    float *oas, *oad;
    int lda, ldb, ldc, ldc2, c2off, K, act, gx;
    float alpha;
};

__device__ __forceinline__ void gemm_core(const GA a, int row0, int col0){
    extern __shared__ char sm[];
    int tid = threadIdx.x, lane = tid & 31, wid = tid >> 5;
    int wm = wid & 3, wn = wid >> 2;
    const __nv_bfloat16* Ah = a.Ah + (size_t)row0 * a.lda;
    const __nv_bfloat16* Al = a.Al + (size_t)row0 * a.lda;
    const __nv_bfloat16* Bh = a.Bh + (size_t)col0 * a.ldb;
    const __nv_bfloat16* Bl = a.Bl + (size_t)col0 * a.ldb;

    uint32_t sbase = smem_u32(sm);
    int nkb = a.K >> 6;

    auto issue = [&](int kb, int st){
        uint32_t su = sbase + st * 49152;
        int k0 = kb << 6;
#pragma unroll
        for (int it = 0; it < 4; it++){
            int i = tid + it * 256;
            int row = i >> 3, seg = i & 7;
            size_t goff = (size_t)row * a.lda + k0 + seg * 8;
            uint32_t so = row * 128 + ((seg ^ (row & 7)) << 4);
            cpa16(su + so,         Ah + goff);
            cpa16(su + 16384 + so, Al + goff);
        }
#pragma unroll
        for (int it = 0; it < 2; it++){
            int i = tid + it * 256;
            int row = i >> 3, seg = i & 7;
            size_t goff = (size_t)row * a.ldb + k0 + seg * 8;
            uint32_t so = row * 128 + ((seg ^ (row & 7)) << 4);
            cpa16(su + 32768 + so, Bh + goff);
            cpa16(su + 40960 + so, Bl + goff);
        }
        cpa_commit();
    };

    issue(0, 0);
    if (nkb > 1) issue(1, 1);

    float acc[2][4][4] = {};
    for (int kb = 0; kb < nkb; kb++){
        if (kb + 1 < nkb) asm volatile("cp.async.wait_group 1;" ::: "memory");
        else              asm volatile("cp.async.wait_group 0;" ::: "memory");
        __syncthreads();
        uint32_t sb2 = sbase + (kb & 1) * 49152;
#pragma unroll
        for (int ks = 0; ks < 4; ks++){
            uint32_t a_h[2][4], a_l[2][4], b_h[4][2], b_l[4][2];
#pragma unroll
            for (int mt = 0; mt < 2; mt++){
                int r = wm * 32 + mt * 16 + (lane & 15);
                int seg = ks * 2 + (lane >> 4);
                uint32_t ad = sb2 + r * 128 + ((seg ^ (r & 7)) << 4);
                ldm_x4(a_h[mt], ad);
                ldm_x4(a_l[mt], ad + 16384);
            }
#pragma unroll
            for (int nt = 0; nt < 4; nt++){
                int r = wn * 32 + nt * 8 + (lane & 7);
                int seg = ks * 2 + ((lane >> 3) & 1);
                uint32_t bd = sb2 + 32768 + r * 128 + ((seg ^ (r & 7)) << 4);
                ldm_x2(b_h[nt], bd);
                ldm_x2(b_l[nt], bd + 8192);
            }
#pragma unroll
            for (int mt = 0; mt < 2; mt++)
#pragma unroll
                for (int nt = 0; nt < 4; nt++){
                    mma_bf16(acc[mt][nt], a_h[mt], b_h[nt]);
                    mma_bf16(acc[mt][nt], a_h[mt], b_l[nt]);
                    mma_bf16(acc[mt][nt], a_l[mt], b_h[nt]);
                }
        }
        __syncthreads();
        if (kb + 2 < nkb) issue(kb + 2, kb & 1);
    }

    float s1[4] = {}, s2[4] = {};
    int h = col0 >> 8;
#pragma unroll
    for (int mt = 0; mt < 2; mt++){
#pragma unroll
        for (int nt = 0; nt < 4; nt++){
            int r0 = row0 + wm * 32 + mt * 16 + (lane >> 2);
            int c0 = col0 + wn * 32 + nt * 8 + ((lane & 3) << 1);
#pragma unroll
            for (int q = 0; q < 4; q++){
                int r = r0 + (q >> 1) * 8;
                int cc = c0 + (q & 1);
                float v = acc[mt][nt][q] * a.alpha;
                if (a.bias) v += a.bias[cc];
                if (a.act == 1) v = fmaxf(v, 0.f);
                if (a.C) a.C[(size_t)r * a.ldc + cc] = v;
                if (a.Ch) f2hl(v, a.Ch, a.Cl, (size_t)r * a.ldc2 + a.c2off + cc);
                if (a.pas){
                    int ridx = mt * 2 + (q >> 1);
                    int ci = h * 256 + (cc & 255);
                    s1[ridx] = fmaf(v, a.pas[ci], s1[ridx]);
                    s2[ridx] = fmaf(v, a.pad[ci], s2[ridx]);
                }
            }
        }
    }
    if (a.pas){
#pragma unroll
        for (int i = 0; i < 4; i++){
            s1[i] += __shfl_xor_sync(~0u, s1[i], 1); s1[i] += __shfl_xor_sync(~0u, s1[i], 2);
            s2[i] += __shfl_xor_sync(~0u, s2[i], 1); s2[i] += __shfl_xor_sync(~0u, s2[i], 2);
        }
        if ((lane & 3) == 0){
#pragma unroll
            for (int i = 0; i < 4; i++){
                int mt = i >> 1, rr = i & 1;
                int r = row0 + wm * 32 + mt * 16 + (lane >> 2) + rr * 8;
                atomicAdd(&a.oas[r * NH + h], s1[i]);
                atomicAdd(&a.oad[r * NH + h], s2[i]);
            }
        }
    }
}

__global__ void __launch_bounds__(256) mma_single(GA a){
    if ((int)blockIdx.x >= a.gx) return;
    gemm_core(a, blockIdx.y * 128, blockIdx.x * 64);
}
// z=0/1: the two xp GEMMs; z=2: the two edge-count prefix scans
__global__ void __launch_bounds__(256) mma_dual(GA a0, GA a1){
    if (blockIdx.z == 2){
        if (blockIdx.y == 0 && blockIdx.x < 2) scan_body(blockIdx.x);
        return;
    }
    GA a = blockIdx.z ? a1 : a0;
    if ((int)blockIdx.x >= a.gx) return;
    gemm_core(a, blockIdx.y * 128, blockIdx.x * 64);
}

// ================= flash attention body (split-KV) =================
__device__ void flash_body(
    const __nv_bfloat16* __restrict__ qkvh, const __nv_bfloat16* __restrict__ qkvl,
    const __nv_bfloat16* __restrict__ vth, const __nv_bfloat16* __restrict__ vtl,
    float* __restrict__ pO, float* __restrict__ pML,
    int row0, int head, int z)
{
    extern __shared__ char sm[];
    int tid = threadIdx.x, lane = tid & 31, wid = tid >> 5;
    int kv0 = z * 2048;
    uint32_t sb = smem_u32(sm);

    const __nv_bfloat16* Qh = qkvh + (size_t)row0 * 768 + head * 64;
    const __nv_bfloat16* Ql = qkvl + (size_t)row0 * 768 + head * 64;
    const __nv_bfloat16* Kh = qkvh + 256 + head * 64;
    const __nv_bfloat16* Kl = qkvl + 256 + head * 64;
    const __nv_bfloat16* Vh = vth + (size_t)head * 64 * 4096;
    const __nv_bfloat16* Vl = vtl + (size_t)head * 64 * 4096;

#pragma unroll
    for (int it = 0; it < 4; it++){
        int i = tid + it * 256;
        int r = i >> 3, seg = i & 7;
        uint32_t so = r * 128 + ((seg ^ (r & 7)) << 4);
        cpa16(sb + so,         Qh + (size_t)r * 768 + seg * 8);
        cpa16(sb + 16384 + so, Ql + (size_t)r * 768 + seg * 8);
    }
#pragma unroll
    for (int it = 0; it < 2; it++){
        int i = tid + it * 256;
        int r = i >> 3, seg = i & 7;
        uint32_t so = r * 128 + ((seg ^ (r & 7)) << 4);
        cpa16(sb + 32768 + so,         Kh + (size_t)(kv0 + r) * 768 + seg * 8);
        cpa16(sb + 32768 + 8192 + so,  Kl + (size_t)(kv0 + r) * 768 + seg * 8);
        cpa16(sb + 32768 + 16384 + so, Vh + (size_t)r * 4096 + kv0 + seg * 8);
        cpa16(sb + 32768 + 24576 + so, Vl + (size_t)r * 4096 + kv0 + seg * 8);
    }
    cpa_commit();
    asm volatile("cp.async.wait_group 0;" ::: "memory");
    __syncthreads();

    uint32_t qf_h[4][4], qf_l[4][4];
#pragma unroll
    for (int ks = 0; ks < 4; ks++){
        int r = wid * 16 + (lane & 15);
        int seg = ks * 2 + (lane >> 4);
        uint32_t ad = sb + r * 128 + ((seg ^ (r & 7)) << 4);
        ldm_x4(qf_h[ks], ad);
        ldm_x4(qf_l[ks], ad + 16384);
    }

    float m0 = -1e30f, m1 = -1e30f, l0 = 0.f, l1 = 0.f;
    float acc_o[8][4] = {};
    int buf = 0;

    for (int kt = 0; kt < 32; kt++){
        if (kt < 31){
            uint32_t bo = sb + 32768 + (buf ^ 1) * 32768;
            int key0 = kv0 + (kt + 1) * 64;
#pragma unroll
            for (int it = 0; it < 2; it++){
                int i = tid + it * 256;
                int r = i >> 3, seg = i & 7;
                uint32_t so = r * 128 + ((seg ^ (r & 7)) << 4);
                cpa16(bo + so,         Kh + (size_t)(key0 + r) * 768 + seg * 8);
                cpa16(bo + 8192 + so,  Kl + (size_t)(key0 + r) * 768 + seg * 8);
                cpa16(bo + 16384 + so, Vh + (size_t)r * 4096 + key0 + seg * 8);
                cpa16(bo + 24576 + so, Vl + (size_t)r * 4096 + key0 + seg * 8);
            }
            cpa_commit();
            asm volatile("cp.async.wait_group 1;" ::: "memory");
        } else {
            asm volatile("cp.async.wait_group 0;" ::: "memory");
        }
        __syncthreads();

        uint32_t kb = sb + 32768 + buf * 32768;

        float acc_s[8][4] = {};
#pragma unroll
        for (int ks = 0; ks < 4; ks++){
            uint32_t bh[8][2], bl[8][2];
#pragma unroll
            for (int nt = 0; nt < 8; nt++){
                int r = nt * 8 + (lane & 7);
                int seg = ks * 2 + ((lane >> 3) & 1);
                uint32_t bd = kb + r * 128 + ((seg ^ (r & 7)) << 4);
                ldm_x2(bh[nt], bd);
                ldm_x2(bl[nt], bd + 8192);
            }
#pragma unroll
            for (int nt = 0; nt < 8; nt++){
                mma_bf16(acc_s[nt], qf_h[ks], bh[nt]);
                mma_bf16(acc_s[nt], qf_h[ks], bl[nt]);
                mma_bf16(acc_s[nt], qf_l[ks], bh[nt]);
            }
        }
#pragma unroll
        for (int nt = 0; nt < 8; nt++){
            acc_s[nt][0] *= 0.125f; acc_s[nt][1] *= 0.125f;
            acc_s[nt][2] *= 0.125f; acc_s[nt][3] *= 0.125f;
        }

        float tm0 = -1e30f, tm1 = -1e30f;
#pragma unroll
        for (int nt = 0; nt < 8; nt++){
            tm0 = fmaxf(tm0, fmaxf(acc_s[nt][0], acc_s[nt][1]));
            tm1 = fmaxf(tm1, fmaxf(acc_s[nt][2], acc_s[nt][3]));
        }
        tm0 = fmaxf(tm0, __shfl_xor_sync(~0u, tm0, 1)); tm0 = fmaxf(tm0, __shfl_xor_sync(~0u, tm0, 2));
        tm1 = fmaxf(tm1, __shfl_xor_sync(~0u, tm1, 1)); tm1 = fmaxf(tm1, __shfl_xor_sync(~0u, tm1, 2));
        float mn0 = fmaxf(m0, tm0), mn1 = fmaxf(m1, tm1);
        float sc0 = __expf(m0 - mn0), sc1 = __expf(m1 - mn1);
        m0 = mn0; m1 = mn1;
        l0 *= sc0; l1 *= sc1;
#pragma unroll
        for (int nt = 0; nt < 8; nt++){
            acc_o[nt][0] *= sc0; acc_o[nt][1] *= sc0;
            acc_o[nt][2] *= sc1; acc_o[nt][3] *= sc1;
        }
        float rs0 = 0.f, rs1 = 0.f;
        uint32_t pa_h[4][4], pa_l[4][4];
#pragma unroll
        for (int nt = 0; nt < 8; nt++){
            float p0 = __expf(acc_s[nt][0] - mn0), p1 = __expf(acc_s[nt][1] - mn0);
            float p2 = __expf(acc_s[nt][2] - mn1), p3 = __expf(acc_s[nt][3] - mn1);
            rs0 += p0 + p1; rs1 += p2 + p3;
            int k2 = nt >> 1;
            if (!(nt & 1)){
                splitpack(p0, p1, pa_h[k2][0], pa_l[k2][0]);
                splitpack(p2, p3, pa_h[k2][1], pa_l[k2][1]);
            } else {
                splitpack(p0, p1, pa_h[k2][2], pa_l[k2][2]);
                splitpack(p2, p3, pa_h[k2][3], pa_l[k2][3]);
            }
        }
        rs0 += __shfl_xor_sync(~0u, rs0, 1); rs0 += __shfl_xor_sync(~0u, rs0, 2);
        rs1 += __shfl_xor_sync(~0u, rs1, 1); rs1 += __shfl_xor_sync(~0u, rs1, 2);
        l0 += rs0; l1 += rs1;

        uint32_t vb = kb + 16384;
#pragma unroll
        for (int k2 = 0; k2 < 4; k2++){
            uint32_t vh[8][2], vl[8][2];
#pragma unroll
            for (int nt = 0; nt < 8; nt++){
                int r = nt * 8 + (lane & 7);
                int seg = k2 * 2 + ((lane >> 3) & 1);
                uint32_t vd = vb + r * 128 + ((seg ^ (r & 7)) << 4);
                ldm_x2(vh[nt], vd);
                ldm_x2(vl[nt], vd + 8192);
            }
#pragma unroll
            for (int nt = 0; nt < 8; nt++){
                mma_bf16(acc_o[nt], pa_h[k2], vh[nt]);
                mma_bf16(acc_o[nt], pa_h[k2], vl[nt]);
                mma_bf16(acc_o[nt], pa_l[k2], vh[nt]);
            }
        }
        __syncthreads();
        buf ^= 1;
    }

    int r = row0 + wid * 16 + (lane >> 2);
    size_t ro0 = ((size_t)z * NNODE + r) * 256;
    size_t ro1 = ((size_t)z * NNODE + r + 8) * 256;
#pragma unroll
    for (int nt = 0; nt < 8; nt++){
        int cc = head * 64 + nt * 8 + ((lane & 3) << 1);
        pO[ro0 + cc]     = acc_o[nt][0];
        pO[ro0 + cc + 1] = acc_o[nt][1];
        pO[ro1 + cc]     = acc_o[nt][2];
        pO[ro1 + cc + 1] = acc_o[nt][3];
    }
    if ((lane & 3) == 0){
        pML[((size_t)z * NNODE + r) * 8 + head * 2]     = m0;
        pML[((size_t)z * NNODE + r) * 8 + head * 2 + 1] = l0;
        pML[((size_t)z * NNODE + r + 8) * 8 + head * 2]     = m1;
        pML[((size_t)z * NNODE + r + 8) * 8 + head * 2 + 1] = l1;
    }
}

// combo: blocks 0..255 = flash; 256..767 = LSTM-gates GEMM
__global__ void __launch_bounds__(256) k_combo(
    GA a,
    const __nv_bfloat16* __restrict__ qkvh, const __nv_bfloat16* __restrict__ qkvl,
    const __nv_bfloat16* __restrict__ vth, const __nv_bfloat16* __restrict__ vtl,
    float* __restrict__ pO, float* __restrict__ pML)
{
    int bx = blockIdx.x;
    if (bx < 256){
        int row0 = (bx & 31) * 128;
        int head = (bx >> 5) & 3;
        int z = bx >> 7;
        flash_body(qkvh, qkvl, vth, vtl, pO, pML, row0, head, z);
    } else {
        int idx = bx - 256;
        gemm_core(a, (idx >> 4) * 128, (idx & 15) * 64);
    }
}

// ================= pointwise =================
__global__ void k_vt(const __nv_bfloat16* __restrict__ qh, const __nv_bfloat16* __restrict__ ql,
                     __nv_bfloat16* __restrict__ vh, __nv_bfloat16* __restrict__ vl){
    int idx = blockIdx.x * 256 + threadIdx.x;
    int hd = idx >> 12, n = idx & 4095;
    size_t s = (size_t)n * 768 + 512 + hd;
    vh[idx] = qh[s]; vl[idx] = ql[s];
}

__global__ void k_mergelstm(const float* __restrict__ pO, const float* __restrict__ pML,
                            __nv_bfloat16* __restrict__ Oh, __nv_bfloat16* __restrict__ Ol,
                            const float* __restrict__ G, float* __restrict__ ht_out){
    int b = blockIdx.x;
    if (b < NNODE){
        int row = b, col = threadIdx.x;
        int head = col >> 6;
        float m0 = pML[(size_t)row * 8 + head * 2],            l0 = pML[(size_t)row * 8 + head * 2 + 1];
        float m1 = pML[((size_t)NNODE + row) * 8 + head * 2],  l1 = pML[((size_t)NNODE + row) * 8 + head * 2 + 1];
        float mx = fmaxf(m0, m1);
        float w0 = __expf(m0 - mx), w1 = __expf(m1 - mx);
        float num = pO[(size_t)row * 256 + col] * w0 + pO[((size_t)NNODE + row) * 256 + col] * w1;
        float den = l0 * w0 + l1 * w1;
        f2hl(num / den, Oh, Ol, (size_t)row * 256 + col);
    } else {
        int idx = (b - NNODE) * 256 + threadIdx.x;
        int n = idx >> 8, j = idx & 255;
        const float* gr = G + (size_t)n * 1024;
        float ig = gr[j], gg = gr[512 + j], og = gr[768 + j];
        float cc = sigmf(ig) * tanhf(gg);
        float hv = sigmf(og) * tanhf(cc);
        ht_out[idx] = hv;
        f2hl(hv, g_hcath, g_hcatl, (size_t)n * 512 + j);
    }
}

// ================= launch =================
#define SYMADDR(p, s) do { void* _t; cudaGetSymbolAddress(&_t, s); p = (decltype(p))_t; } while(0)

extern "C" void kernel_launch(void* const* d_in, const int* in_sizes, int n_in,
                              void* d_out, int out_size) {
    const float* x     = (const float*)d_in[0];
    const int*   ei_t  = (const int*)d_in[1];
    const int*   ei_c  = (const int*)d_in[2];
    const float* ea_t  = (const float*)d_in[3];
    const float* ea_c  = (const float*)d_in[4];
    const float* W_t   = (const float*)d_in[5];
    const float* asrc_t= (const float*)d_in[6];
    const float* adst_t= (const float*)d_in[7];
    const float* We_t  = (const float*)d_in[8];
    const float* ae_t  = (const float*)d_in[9];
    const float* b_t   = (const float*)d_in[10];
    const float* W_c   = (const float*)d_in[11];
    const float* asrc_c= (const float*)d_in[12];
    const float* adst_c= (const float*)d_in[13];
    const float* We_c  = (const float*)d_in[14];
    const float* ae_c  = (const float*)d_in[15];
    const float* b_c   = (const float*)d_in[16];
    const float* lstm_Wih = (const float*)d_in[17];
    const float* lstm_bih = (const float*)d_in[19];
    const float* lstm_bhh = (const float*)d_in[20];
    const float* mha_in_w  = (const float*)d_in[21];
    const float* mha_in_b  = (const float*)d_in[22];
    const float* mha_out_w = (const float*)d_in[23];
    const float* mha_out_b = (const float*)d_in[24];
    const float* fus_w = (const float*)d_in[25];
    const float* fus_b = (const float*)d_in[26];
    const float* out_w = (const float*)d_in[27];
    const float* out_b = (const float*)d_in[28];

    float* big; SYMADDR(big, g_big);
    float* po;  SYMADDR(po, g_po);
    float* pml; SYMADDR(pml, g_pml);
    float* xp0; SYMADDR(xp0, g_xp);
    float* xp1 = xp0 + (size_t)NNODE * NHC;
    float* as0; SYMADDR(as0, g_as);
    float* as1 = as0 + NNODE * NH;
    float* ad0; SYMADDR(ad0, g_ad);
    float* ad1 = ad0 + NNODE * NH;
    __nv_bfloat16 *hth, *htl, *hch, *hcl, *qkvh, *qkvl, *vth, *vtl;
    __nv_bfloat16 *attnh, *attnl, *hcath, *hcatl, *hfush, *hfusl;
    __nv_bfloat16 *wihh, *wihl, *inwh, *inwl, *mowh, *mowl, *fuwh, *fuwl, *owh, *owl;
    __nv_bfloat16 *xpadh, *xpadl, *wpadh, *wpadl;
    SYMADDR(hth, g_hth); SYMADDR(htl, g_htl); SYMADDR(hch, g_hch); SYMADDR(hcl, g_hcl);
    SYMADDR(qkvh, g_qkvh); SYMADDR(qkvl, g_qkvl); SYMADDR(vth, g_vth); SYMADDR(vtl, g_vtl);
    SYMADDR(attnh, g_attnh); SYMADDR(attnl, g_attnl);
    SYMADDR(hcath, g_hcath); SYMADDR(hcatl, g_hcatl);
    SYMADDR(hfush, g_hfush); SYMADDR(hfusl, g_hfusl);
    SYMADDR(wihh, g_wihh); SYMADDR(wihl, g_wihl);
    SYMADDR(inwh, g_inwh); SYMADDR(inwl, g_inwl);
    SYMADDR(mowh, g_mowh); SYMADDR(mowl, g_mowl);
    SYMADDR(fuwh, g_fuwh); SYMADDR(fuwl, g_fuwl);
    SYMADDR(owh, g_owh); SYMADDR(owl, g_owl);
    SYMADDR(xpadh, g_xpadh); SYMADDR(xpadl, g_xpadl);
    SYMADDR(wpadh, g_wpadh); SYMADDR(wpadl, g_wpadl);

    cudaFuncSetAttribute(k_combo,  cudaFuncAttributeMaxDynamicSharedMemorySize, 98304);
    cudaFuncSetAttribute(mma_single, cudaFuncAttributeMaxDynamicSharedMemorySize, 98304);
    cudaFuncSetAttribute(mma_dual, cudaFuncAttributeMaxDynamicSharedMemorySize, 98304);
    const int DYN = 98304;

    float* out_main = (float*)d_out;
    float* out_ht   = out_main + (size_t)NNODE * NOUT;
    float* out_hc   = out_ht   + (size_t)NNODE * HID;

    const int* src_t = ei_t; const int* dst_t = ei_t + NE;
    const int* src_c = ei_c; const int* dst_c = ei_c + NE;
    int nepb = (NEP + 255) / 256;

    k_initconv<<<128 + NCONVB, 256>>>(ea_t, ea_c, lstm_Wih, mha_in_w, mha_out_w, fus_w, out_w, x, W_t, W_c);
    k_setupcount<<<1 + 1024, 256>>>(We_t, ae_t, We_c, ae_c, lstm_bih, lstm_bhh, dst_t, dst_c);

    // ---- xp GEMMs (z=0/1) + count prefix scans (z=2) ----
    {
        GA a0 = { xpadh, xpadl, wpadh, wpadl, xp0, nullptr, nullptr, nullptr,
                  asrc_t, adst_t, as0, ad0,
                  64, 64, NHC, 0, 0, 64, 0, 32, 1.f };
        GA a1 = { xpadh, xpadl, wpadh + (size_t)NHC * 64, wpadl + (size_t)NHC * 64, xp1,
                  nullptr, nullptr, nullptr,
                  asrc_c, adst_c, as1, ad1,
                  64, 64, NHC, 0, 0, 64, 0, 32, 1.f };
        mma_dual<<<dim3(32, 32, 3), 256, DYN>>>(a0, a1);
    }

    // ---- edge scatter + logits (seg-max moved into agg) ----
    k_scatalpha<<<dim3(nepb, 2), 256>>>(src_t, dst_t, ea_t, src_c, dst_c, ea_c);

    // ---- aggregation, both graphs concurrently ----
    k_agg<<<dim3(NNODE, 2), 256>>>(src_t, src_c, b_t, b_c);

    // ---- qkv GEMM (4096x768x256) ----
    {
        GA a = { hch, hcl, inwh, inwl, nullptr, qkvh, qkvl, mha_in_b,
                 nullptr, nullptr, nullptr, nullptr,
                 256, 256, 0, 768, 0, 256, 0, 12, 1.f };
        mma_single<<<dim3(12, 32), 256, DYN>>>(a);
    }
    k_vt<<<(4*64*NNODE)/256, 256>>>(qkvh, qkvl, vth, vtl);

    // ---- flash attention + LSTM gates GEMM overlapped ----
    {
        GA a = { hth, htl, wihh, wihl, big + OFF_G, nullptr, nullptr, big + OFF_BSUM,
                 nullptr, nullptr, nullptr, nullptr,
                 NHC, NHC, 1024, 0, 0, NHC, 0, 16, 1.f };
        k_combo<<<768, 256, DYN>>>(a, qkvh, qkvl, vth, vtl, po, pml);
    }

    // ---- merge flash partials + lstm pointwise ----
    k_mergelstm<<<2 * NNODE, 256>>>(po, pml, attnh, attnl, big + OFF_G, out_ht);

    // ---- proj (4096x256x256) ----
    {
        GA a = { attnh, attnl, mowh, mowl, out_hc, hcath, hcatl, mha_out_b,
                 nullptr, nullptr, nullptr, nullptr,
                 256, 256, 256, 512, 256, 256, 0, 4, 1.f };
        mma_single<<<dim3(4, 32), 256, DYN>>>(a);
    }
    // ---- fusion relu (4096x256x512) ----
    {
        GA a = { hcath, hcatl, fuwh, fuwl, nullptr, hfush, hfusl, fus_b,
                 nullptr, nullptr, nullptr, nullptr,
                 512, 512, 0, 256, 0, 512, 1, 4, 1.f };
        mma_single<<<dim3(4, 32), 256, DYN>>>(a);
    }
    // ---- out (4096x128x256) ----
    {
        GA a = { hfush, hfusl, owh, owl, out_main, nullptr, nullptr, out_b,
                 nullptr, nullptr, nullptr, nullptr,
                 256, 256, NOUT, 0, 0, 256, 0, 2, 1.f };
        mma_single<<<dim3(2, 32), 256, DYN>>>(a);
    }
}

// round 15
// speedup vs baseline: 1.0851x; 1.0003x over previous
#include <cuda_runtime.h>
#include <cuda_bf16.h>
#include <math.h>
#include <float.h>
#include <stdint.h>

#define NNODE 4096
#define NIN   28
#define NE    131072
#define NEP   (NE + NNODE)
#define NH    8
#define NC    256
#define NHC   2048
#define HID   256
#define NOUT  128

// ---------------- fp32 scratch ----------------
#define OFF_G    ((size_t)0)
#define OFF_BSUM (OFF_G + (size_t)NNODE * 1024)
#define BIG_SZ   (OFF_BSUM + 1024)
__device__ float g_big[BIG_SZ];

__device__ float g_xp[2][(size_t)NNODE * NHC];
__device__ float g_as[2][NNODE * NH];
__device__ float g_ad[2][NNODE * NH];
__device__ float g_w [2][(size_t)NEP * NH];
__device__ int   g_cnt[2][NNODE];
__device__ int   g_cur[2][NNODE];
__device__ int   g_start[2][NNODE];
__device__ int   g_sorted[2][NE];
__device__ float g_part[2][128];
__device__ float g_mean[2];
__device__ float g_ce[2][NH];

// flash split-K partials
__device__ float g_po[(size_t)2 * NNODE * 256];
__device__ float g_pml[(size_t)2 * NNODE * 8];

// ---------------- bf16 hi/lo tensors ----------------
__device__ __nv_bfloat16 g_hth[(size_t)NNODE * NHC], g_htl[(size_t)NNODE * NHC];
__device__ __nv_bfloat16 g_hch[(size_t)NNODE * 256], g_hcl[(size_t)NNODE * 256];
__device__ __nv_bfloat16 g_qkvh[(size_t)NNODE * 768], g_qkvl[(size_t)NNODE * 768];
__device__ __nv_bfloat16 g_vth[(size_t)4 * 64 * NNODE], g_vtl[(size_t)4 * 64 * NNODE];
__device__ __nv_bfloat16 g_attnh[(size_t)NNODE * 256], g_attnl[(size_t)NNODE * 256];
__device__ __nv_bfloat16 g_hcath[(size_t)NNODE * 512], g_hcatl[(size_t)NNODE * 512];
__device__ __nv_bfloat16 g_hfush[(size_t)NNODE * 256], g_hfusl[(size_t)NNODE * 256];
// weights
__device__ __nv_bfloat16 g_wihh[1024 * 2048], g_wihl[1024 * 2048];
__device__ __nv_bfloat16 g_inwh[768 * 256],   g_inwl[768 * 256];
__device__ __nv_bfloat16 g_mowh[256 * 256],   g_mowl[256 * 256];
__device__ __nv_bfloat16 g_fuwh[256 * 512],   g_fuwl[256 * 512];
__device__ __nv_bfloat16 g_owh[128 * 256],    g_owl[128 * 256];
// padded x / W for tensor-core xp GEMM
__device__ __nv_bfloat16 g_xpadh[(size_t)NNODE * 64], g_xpadl[(size_t)NNODE * 64];
__device__ __nv_bfloat16 g_wpadh[(size_t)2 * NHC * 64], g_wpadl[(size_t)2 * NHC * 64];

// ---------------- helpers ----------------
__device__ __forceinline__ int   f2ord(float f){ int i = __float_as_int(f); return i >= 0 ? i : i ^ 0x7fffffff; }
__device__ __forceinline__ float ord2f(int k){ return __int_as_float(k >= 0 ? k : k ^ 0x7fffffff); }
__device__ __forceinline__ float sigmf(float x){ return 1.f / (1.f + expf(-x)); }
__device__ __forceinline__ void f2hl(float v, __nv_bfloat16* H, __nv_bfloat16* L, size_t i){
    __nv_bfloat16 h = __float2bfloat16(v);
    H[i] = h; L[i] = __float2bfloat16(v - __bfloat162float(h));
}
__device__ __forceinline__ uint32_t smem_u32(const void* p){
    uint32_t a;
    asm("{ .reg .u64 t; cvta.to.shared.u64 t, %1; cvt.u32.u64 %0, t; }" : "=r"(a) : "l"(p));
    return a;
}
__device__ __forceinline__ void ldm_x4(uint32_t* r, uint32_t addr){
    asm volatile("ldmatrix.sync.aligned.m8n8.x4.shared.b16 {%0,%1,%2,%3}, [%4];"
        : "=r"(r[0]), "=r"(r[1]), "=r"(r[2]), "=r"(r[3]) : "r"(addr));
}
__device__ __forceinline__ void ldm_x2(uint32_t* r, uint32_t addr){
    asm volatile("ldmatrix.sync.aligned.m8n8.x2.shared.b16 {%0,%1}, [%2];"
        : "=r"(r[0]), "=r"(r[1]) : "r"(addr));
}
__device__ __forceinline__ void mma_bf16(float* c, const uint32_t* a, const uint32_t* b){
    asm volatile("mma.sync.aligned.m16n8k16.row.col.f32.bf16.bf16.f32 "
        "{%0,%1,%2,%3}, {%4,%5,%6,%7}, {%8,%9}, {%0,%1,%2,%3};"
        : "+f"(c[0]), "+f"(c[1]), "+f"(c[2]), "+f"(c[3])
        : "r"(a[0]), "r"(a[1]), "r"(a[2]), "r"(a[3]), "r"(b[0]), "r"(b[1]));
}
__device__ __forceinline__ void cpa16(uint32_t saddr, const void* g){
    asm volatile("cp.async.ca.shared.global [%0], [%1], 16;" :: "r"(saddr), "l"(g));
}
__device__ __forceinline__ void cpa_commit(){ asm volatile("cp.async.commit_group;" ::: "memory"); }
__device__ __forceinline__ void splitpack(float a, float b, uint32_t& hi, uint32_t& lo){
    __nv_bfloat16 ha = __float2bfloat16(a), hb = __float2bfloat16(b);
    __nv_bfloat16 la = __float2bfloat16(a - __bfloat162float(ha));
    __nv_bfloat16 lb = __float2bfloat16(b - __bfloat162float(hb));
    hi = ((uint32_t)__bfloat16_as_ushort(hb) << 16) | (uint32_t)__bfloat16_as_ushort(ha);
    lo = ((uint32_t)__bfloat16_as_ushort(lb) << 16) | (uint32_t)__bfloat16_as_ushort(la);
}

// ================= setup (initmean + weight conversions, one launch) =================
#define CW0 2097152
#define CW1 (CW0 + 196608)
#define CW2 (CW1 + 65536)
#define CW3 (CW2 + 131072)
#define CW4 (CW3 + 32768)
#define CW5 (CW4 + NNODE * 64)
#define CW6 (CW5 + 2 * NHC * 64)
#define NCONVB ((CW6 + 255) / 256)

__global__ void k_initconv(const float* __restrict__ ea_t, const float* __restrict__ ea_c,
                           const float* __restrict__ w0, const float* __restrict__ w1,
                           const float* __restrict__ w2, const float* __restrict__ w3,
                           const float* __restrict__ w4, const float* __restrict__ x,
                           const float* __restrict__ W_t, const float* __restrict__ W_c){
    int bx = blockIdx.x;
    if (bx < 128){
        int idx = bx * 256 + threadIdx.x, stride = 128 * 256;
        for (int i = idx; i < NNODE * NH; i += stride){
            g_as[0][i] = 0.f; g_as[1][i] = 0.f;
            g_ad[0][i] = 0.f; g_ad[1][i] = 0.f;
        }
        for (int i = idx; i < NNODE; i += stride){
            g_cnt[0][i] = 0; g_cnt[1][i] = 0;
            g_cur[0][i] = 0; g_cur[1][i] = 0;
        }
        __shared__ float s0[256], s1[256];
        float a = 0.f, b = 0.f;
        for (int i = idx; i < NE; i += stride){ a += ea_t[i]; b += ea_c[i]; }
        s0[threadIdx.x] = a; s1[threadIdx.x] = b; __syncthreads();
        for (int s = 128; s; s >>= 1){
            if (threadIdx.x < s){ s0[threadIdx.x] += s0[threadIdx.x+s]; s1[threadIdx.x] += s1[threadIdx.x+s]; }
            __syncthreads();
        }
        if (!threadIdx.x){ g_part[0][bx] = s0[0]; g_part[1][bx] = s1[0]; }
        return;
    }
    int i = (bx - 128) * 256 + threadIdx.x;
    if (i < CW0)      f2hl(w0[i], g_wihh, g_wihl, i);
    else if (i < CW1) f2hl(w1[i - CW0], g_inwh, g_inwl, i - CW0);
    else if (i < CW2) f2hl(w2[i - CW1], g_mowh, g_mowl, i - CW1);
    else if (i < CW3) f2hl(w3[i - CW2], g_fuwh, g_fuwl, i - CW2);
    else if (i < CW4) f2hl(w4[i - CW3], g_owh, g_owl, i - CW3);
    else if (i < CW5){
        int j = i - CW4; int n = j >> 6, k = j & 63;
        float v = (k < NIN) ? x[n * NIN + k] : 0.f;
        f2hl(v, g_xpadh, g_xpadl, j);
    } else if (i < CW6){
        int j = i - CW5; int g = j >> 17; int r = j & 131071;
        int n = r >> 6, k = r & 63;
        const float* W = g ? W_c : W_t;
        float v = (k < NIN) ? W[k * NHC + n] : 0.f;
        f2hl(v, g_wpadh, g_wpadl, j);
    }
}

// ================= setup (means/ce/bsum) + edge count, one launch =================
__global__ void k_setupcount(const float* __restrict__ We_t, const float* __restrict__ ae_t,
                             const float* __restrict__ We_c, const float* __restrict__ ae_c,
                             const float* __restrict__ bih,  const float* __restrict__ bhh,
                             const int* __restrict__ dst_t, const int* __restrict__ dst_c){
    int bx = blockIdx.x;
    if (bx == 0){
        __shared__ float sh[256];
        int tid = threadIdx.x;
        for (int g = 0; g < 2; g++){
            sh[tid] = (tid < 128) ? g_part[g][tid] : 0.f;
            __syncthreads();
            for (int s = 128; s; s >>= 1){ if (tid < s) sh[tid] += sh[tid+s]; __syncthreads(); }
            if (!tid) g_mean[g] = sh[0] / (float)NE;
            __syncthreads();
        }
        int wid = tid >> 5, lane = tid & 31;
        for (int c = wid; c < 16; c += 8){
            int g = c >> 3, h = c & 7;
            const float* We = g ? We_c : We_t;
            const float* ae = g ? ae_c : ae_t;
            float s = 0.f;
            for (int i = lane; i < NC; i += 32) s = fmaf(We[h*NC + i], ae[h*NC + i], s);
            for (int o = 16; o; o >>= 1) s += __shfl_down_sync(0xffffffffu, s, o);
            if (!lane) g_ce[g][h] = s;
        }
        for (int j = tid; j < 1024; j += 256) g_big[OFF_BSUM + j] = bih[j] + bhh[j];
        return;
    }
    int idx = bx - 1;
    int g = idx >> 9;
    const int* dst = g ? dst_c : dst_t;
    int e = (idx & 511) * 256 + threadIdx.x;
    atomicAdd(&g_cnt[g][dst[e]], 1);
}

// 256-thread scan over 4096 counts (runs inside the xp mma_dual launch, z==2)
__device__ void scan_body(int g){
    __shared__ int sh[256];
    int tid = threadIdx.x;
    int base = tid * 16;
    int local[16]; int s = 0;
#pragma unroll
    for (int i = 0; i < 16; i++){ local[i] = g_cnt[g][base + i]; s += local[i]; }
    sh[tid] = s; __syncthreads();
    for (int off = 1; off < 256; off <<= 1){
        int v = (tid >= off) ? sh[tid - off] : 0;
        __syncthreads();
        sh[tid] += v;
        __syncthreads();
    }
    int run = sh[tid] - s;
#pragma unroll
    for (int i = 0; i < 16; i++){ g_start[g][base + i] = run; run += local[i]; }
}

// ================= GAT edge pipeline =================
__device__ __forceinline__ void edge_one(int g, int e,
        const int* __restrict__ src, const int* __restrict__ dst, const float* __restrict__ ea){
    int s, d; float av;
    if (e < NE){
        s = src[e]; d = dst[e]; av = ea[e];
        int pos = g_start[g][d] + atomicAdd(&g_cur[g][d], 1);
        g_sorted[g][pos] = e;
    } else { s = d = e - NE; av = g_mean[g]; }
    float4 s0 = *(const float4*)&g_as[g][s*NH];
    float4 s1 = *(const float4*)&g_as[g][s*NH + 4];
    float4 d0 = *(const float4*)&g_ad[g][d*NH];
    float4 d1 = *(const float4*)&g_ad[g][d*NH + 4];
    float4 c0 = *(const float4*)&g_ce[g][0];
    float4 c1 = *(const float4*)&g_ce[g][4];
    float4 o0, o1;
    o0.x = s0.x + d0.x + av * c0.x;  o0.y = s0.y + d0.y + av * c0.y;
    o0.z = s0.z + d0.z + av * c0.z;  o0.w = s0.w + d0.w + av * c0.w;
    o1.x = s1.x + d1.x + av * c1.x;  o1.y = s1.y + d1.y + av * c1.y;
    o1.z = s1.z + d1.z + av * c1.z;  o1.w = s1.w + d1.w + av * c1.w;
    o0.x = o0.x > 0.f ? o0.x : 0.2f * o0.x;  o0.y = o0.y > 0.f ? o0.y : 0.2f * o0.y;
    o0.z = o0.z > 0.f ? o0.z : 0.2f * o0.z;  o0.w = o0.w > 0.f ? o0.w : 0.2f * o0.w;
    o1.x = o1.x > 0.f ? o1.x : 0.2f * o1.x;  o1.y = o1.y > 0.f ? o1.y : 0.2f * o1.y;
    o1.z = o1.z > 0.f ? o1.z : 0.2f * o1.z;  o1.w = o1.w > 0.f ? o1.w : 0.2f * o1.w;
    *(float4*)&g_w[g][(size_t)e * NH]     = o0;
    *(float4*)&g_w[g][(size_t)e * NH + 4] = o1;
}

// scatter + logits, 2 edges per thread for MLP
__global__ void k_scatalpha(const int* __restrict__ src_t, const int* __restrict__ dst_t, const float* __restrict__ ea_t,
                            const int* __restrict__ src_c, const int* __restrict__ dst_c, const float* __restrict__ ea_c){
    int g = blockIdx.y;
    const int* src = g ? src_c : src_t;
    const int* dst = g ? dst_c : dst_t;
    const float* ea = g ? ea_c : ea_t;
    int e0 = blockIdx.x * 512 + threadIdx.x;
    int e1 = e0 + 256;
    if (e0 < NEP) edge_one(g, e0, src, dst, ea);
    if (e1 < NEP) edge_one(g, e1, src, dst, ea);
}

// fused: per-node max prepass + exp + denominator + weighted aggregation
__global__ void __launch_bounds__(256) k_agg(const int* __restrict__ src_t, const int* __restrict__ src_c,
                                             const float* __restrict__ b_t, const float* __restrict__ b_c){
    int g = blockIdx.y;
    const int* src = g ? src_c : src_t;
    const float* bias = g ? b_c : b_t;
    int n = blockIdx.x, t = threadIdx.x;
    const float* xp = g_xp[g];
    const float* w  = g_w[g];

    __shared__ int   smxi[NH];
    __shared__ float smx[NH];
    __shared__ int   ssrc[32];
    __shared__ float sw[32][NH];
    if (t < NH) smxi[t] = f2ord(-FLT_MAX);
    __syncthreads();

    int st = g_start[g][n], c = g_cnt[g][n];

    // ---- max prepass over self-loop + incoming edges ----
    {
        float lm[NH];
        if (t == 0){
            const float* ws = w + (size_t)(NE + n) * NH;
            float4 a = *(const float4*)ws, b = *(const float4*)(ws + 4);
            lm[0]=a.x; lm[1]=a.y; lm[2]=a.z; lm[3]=a.w; lm[4]=b.x; lm[5]=b.y; lm[6]=b.z; lm[7]=b.w;
        } else {
#pragma unroll
            for (int h = 0; h < NH; h++) lm[h] = -FLT_MAX;
        }
        for (int i = t; i < c; i += 256){
            const float* we = w + (size_t)g_sorted[g][st + i] * NH;
            float4 a = *(const float4*)we, b = *(const float4*)(we + 4);
            lm[0]=fmaxf(lm[0],a.x); lm[1]=fmaxf(lm[1],a.y); lm[2]=fmaxf(lm[2],a.z); lm[3]=fmaxf(lm[3],a.w);
            lm[4]=fmaxf(lm[4],b.x); lm[5]=fmaxf(lm[5],b.y); lm[6]=fmaxf(lm[6],b.z); lm[7]=fmaxf(lm[7],b.w);
        }
#pragma unroll
        for (int h = 0; h < NH; h++){
            for (int o = 16; o; o >>= 1) lm[h] = fmaxf(lm[h], __shfl_xor_sync(~0u, lm[h], o));
        }
        if ((t & 31) == 0){
#pragma unroll
            for (int h = 0; h < NH; h++) atomicMax(&smxi[h], f2ord(lm[h]));
        }
    }
    __syncthreads();
    if (t < NH) smx[t] = ord2f(smxi[t]);
    __syncthreads();

    float acc[NH], den[NH];
    {
        size_t e = (size_t)(NE + n) * NH;
        const float* xr = xp + (size_t)n * NHC + t;
#pragma unroll
        for (int h = 0; h < NH; h++){
            float exs = expf(w[e + h] - smx[h]);
            acc[h] = exs * xr[h * NC];
            den[h] = exs;
        }
    }
    for (int i0 = 0; i0 < c; i0 += 32){
        int m = min(32, c - i0);
        __syncthreads();
        if (t < m) ssrc[t] = src[g_sorted[g][st + i0 + t]];
        {
            int j = t >> 3, h = t & 7;
            if (j < m) sw[j][h] = expf(w[(size_t)g_sorted[g][st + i0 + j] * NH + h] - smx[h]);
        }
        __syncthreads();
        int jj = 0;
        for (; jj + 4 <= m; jj += 4){
            const float* x0 = xp + (size_t)ssrc[jj+0] * NHC + t;
            const float* x1 = xp + (size_t)ssrc[jj+1] * NHC + t;
            const float* x2 = xp + (size_t)ssrc[jj+2] * NHC + t;
            const float* x3 = xp + (size_t)ssrc[jj+3] * NHC + t;
            float v0[NH], v1[NH], v2[NH], v3[NH];
#pragma unroll
            for (int h = 0; h < NH; h++){ v0[h] = x0[h*NC]; v1[h] = x1[h*NC]; v2[h] = x2[h*NC]; v3[h] = x3[h*NC]; }
#pragma unroll
            for (int h = 0; h < NH; h++){
                float w0 = sw[jj+0][h], w1 = sw[jj+1][h], w2 = sw[jj+2][h], w3 = sw[jj+3][h];
                acc[h] = fmaf(w0, v0[h], acc[h]);
                acc[h] = fmaf(w1, v1[h], acc[h]);
                acc[h] = fmaf(w2, v2[h], acc[h]);
                acc[h] = fmaf(w3, v3[h], acc[h]);
                den[h] += (w0 + w1) + (w2 + w3);
            }
        }
        for (; jj < m; jj++){
            const float* xr = xp + (size_t)ssrc[jj] * NHC + t;
#pragma unroll
            for (int h = 0; h < NH; h++){
                float ww = sw[jj][h];
                acc[h] = fmaf(ww, xr[h * NC], acc[h]);
                den[h] += ww;
            }
        }
    }
    if (g == 0){
#pragma unroll
        for (int h = 0; h < NH; h++){
            float v = acc[h] / (den[h] + 1e-16f) + bias[h * NC + t];
            f2hl(v, g_hth, g_htl, (size_t)n * NHC + h * NC + t);
        }
    } else {
        float s = 0.f;
#pragma unroll
        for (int h = 0; h < NH; h++) s += acc[h] / (den[h] + 1e-16f);
        f2hl(s * 0.125f + bias[t], g_hch, g_hcl, (size_t)n * NC + t);
    }
}

// ================= HMMA bf16x3 GEMM core =================
struct GA {
    const __nv_bfloat16 *Ah, *Al, *Bh, *Bl;
    float* C;
    __nv_bfloat16 *Ch, *Cl;
    const float* bias;
    const float *pas, *pad;
    float *oas, *oad;
    __nv_bfloat16 *vh2, *vl2;   // optional: transposed V write (qkv GEMM), cols >= 512
    int lda, ldb, ldc, ldc2, c2off, K, act, gx;
    float alpha;
};

__device__ __forceinline__ void gemm_core(const GA a, int row0, int col0){
    extern __shared__ char sm[];
    int tid = threadIdx.x, lane = tid & 31, wid = tid >> 5;
    int wm = wid & 3, wn = wid >> 2;
    const __nv_bfloat16* Ah = a.Ah + (size_t)row0 * a.lda;
    const __nv_bfloat16* Al = a.Al + (size_t)row0 * a.lda;
    const __nv_bfloat16* Bh = a.Bh + (size_t)col0 * a.ldb;
    const __nv_bfloat16* Bl = a.Bl + (size_t)col0 * a.ldb;

    uint32_t sbase = smem_u32(sm);
    int nkb = a.K >> 6;

    auto issue = [&](int kb, int st){
        uint32_t su = sbase + st * 49152;
        int k0 = kb << 6;
#pragma unroll
        for (int it = 0; it < 4; it++){
            int i = tid + it * 256;
            int row = i >> 3, seg = i & 7;
            size_t goff = (size_t)row * a.lda + k0 + seg * 8;
            uint32_t so = row * 128 + ((seg ^ (row & 7)) << 4);
            cpa16(su + so,         Ah + goff);
            cpa16(su + 16384 + so, Al + goff);
        }
#pragma unroll
        for (int it = 0; it < 2; it++){
            int i = tid + it * 256;
            int row = i >> 3, seg = i & 7;
            size_t goff = (size_t)row * a.ldb + k0 + seg * 8;
            uint32_t so = row * 128 + ((seg ^ (row & 7)) << 4);
            cpa16(su + 32768 + so, Bh + goff);
            cpa16(su + 40960 + so, Bl + goff);
        }
        cpa_commit();
    };

    issue(0, 0);
    if (nkb > 1) issue(1, 1);

    float acc[2][4][4] = {};
    for (int kb = 0; kb < nkb; kb++){
        if (kb + 1 < nkb) asm volatile("cp.async.wait_group 1;" ::: "memory");
        else              asm volatile("cp.async.wait_group 0;" ::: "memory");
        __syncthreads();
        uint32_t sb2 = sbase + (kb & 1) * 49152;
#pragma unroll
        for (int ks = 0; ks < 4; ks++){
            uint32_t a_h[2][4], a_l[2][4], b_h[4][2], b_l[4][2];
#pragma unroll
            for (int mt = 0; mt < 2; mt++){
                int r = wm * 32 + mt * 16 + (lane & 15);
                int seg = ks * 2 + (lane >> 4);
                uint32_t ad = sb2 + r * 128 + ((seg ^ (r & 7)) << 4);
                ldm_x4(a_h[mt], ad);
                ldm_x4(a_l[mt], ad + 16384);
            }
#pragma unroll
            for (int nt = 0; nt < 4; nt++){
                int r = wn * 32 + nt * 8 + (lane & 7);
                int seg = ks * 2 + ((lane >> 3) & 1);
                uint32_t bd = sb2 + 32768 + r * 128 + ((seg ^ (r & 7)) << 4);
                ldm_x2(b_h[nt], bd);
                ldm_x2(b_l[nt], bd + 8192);
            }
#pragma unroll
            for (int mt = 0; mt < 2; mt++)
#pragma unroll
                for (int nt = 0; nt < 4; nt++){
                    mma_bf16(acc[mt][nt], a_h[mt], b_h[nt]);
                    mma_bf16(acc[mt][nt], a_h[mt], b_l[nt]);
                    mma_bf16(acc[mt][nt], a_l[mt], b_h[nt]);
                }
        }
        __syncthreads();
        if (kb + 2 < nkb) issue(kb + 2, kb & 1);
    }

    float s1[4] = {}, s2[4] = {};
    int h = col0 >> 8;
#pragma unroll
    for (int mt = 0; mt < 2; mt++){
#pragma unroll
        for (int nt = 0; nt < 4; nt++){
            int r0 = row0 + wm * 32 + mt * 16 + (lane >> 2);
            int c0 = col0 + wn * 32 + nt * 8 + ((lane & 3) << 1);
#pragma unroll
            for (int q = 0; q < 4; q++){
                int r = r0 + (q >> 1) * 8;
                int cc = c0 + (q & 1);
                float v = acc[mt][nt][q] * a.alpha;
                if (a.bias) v += a.bias[cc];
                if (a.act == 1) v = fmaxf(v, 0.f);
                if (a.C) a.C[(size_t)r * a.ldc + cc] = v;
                if (a.Ch) f2hl(v, a.Ch, a.Cl, (size_t)r * a.ldc2 + a.c2off + cc);
                if (a.vh2 && cc >= 512) f2hl(v, a.vh2, a.vl2, (size_t)(cc - 512) * 4096 + r);
                if (a.pas){
                    int ridx = mt * 2 + (q >> 1);
                    int ci = h * 256 + (cc & 255);
                    s1[ridx] = fmaf(v, a.pas[ci], s1[ridx]);
                    s2[ridx] = fmaf(v, a.pad[ci], s2[ridx]);
                }
            }
        }
    }
    if (a.pas){
#pragma unroll
        for (int i = 0; i < 4; i++){
            s1[i] += __shfl_xor_sync(~0u, s1[i], 1); s1[i] += __shfl_xor_sync(~0u, s1[i], 2);
            s2[i] += __shfl_xor_sync(~0u, s2[i], 1); s2[i] += __shfl_xor_sync(~0u, s2[i], 2);
        }
        if ((lane & 3) == 0){
#pragma unroll
            for (int i = 0; i < 4; i++){
                int mt = i >> 1, rr = i & 1;
                int r = row0 + wm * 32 + mt * 16 + (lane >> 2) + rr * 8;
                atomicAdd(&a.oas[r * NH + h], s1[i]);
                atomicAdd(&a.oad[r * NH + h], s2[i]);
            }
        }
    }
}

__global__ void __launch_bounds__(256) mma_single(GA a){
    if ((int)blockIdx.x >= a.gx) return;
    gemm_core(a, blockIdx.y * 128, blockIdx.x * 64);
}
// z=0/1: the two xp GEMMs; z=2: the two edge-count prefix scans
__global__ void __launch_bounds__(256) mma_dual(GA a0, GA a1){
    if (blockIdx.z == 2){
        if (blockIdx.y == 0 && blockIdx.x < 2) scan_body(blockIdx.x);
        return;
    }
    GA a = blockIdx.z ? a1 : a0;
    if ((int)blockIdx.x >= a.gx) return;
    gemm_core(a, blockIdx.y * 128, blockIdx.x * 64);
}

// ================= flash attention body (split-KV) =================
__device__ void flash_body(
    const __nv_bfloat16* __restrict__ qkvh, const __nv_bfloat16* __restrict__ qkvl,
    const __nv_bfloat16* __restrict__ vth, const __nv_bfloat16* __restrict__ vtl,
    float* __restrict__ pO, float* __restrict__ pML,
    int row0, int head, int z)
{
    extern __shared__ char sm[];
    int tid = threadIdx.x, lane = tid & 31, wid = tid >> 5;
    int kv0 = z * 2048;
    uint32_t sb = smem_u32(sm);

    const __nv_bfloat16* Qh = qkvh + (size_t)row0 * 768 + head * 64;
    const __nv_bfloat16* Ql = qkvl + (size_t)row0 * 768 + head * 64;
    const __nv_bfloat16* Kh = qkvh + 256 + head * 64;
    const __nv_bfloat16* Kl = qkvl + 256 + head * 64;
    const __nv_bfloat16* Vh = vth + (size_t)head * 64 * 4096;
    const __nv_bfloat16* Vl = vtl + (size_t)head * 64 * 4096;

#pragma unroll
    for (int it = 0; it < 4; it++){
        int i = tid + it * 256;
        int r = i >> 3, seg = i & 7;
        uint32_t so = r * 128 + ((seg ^ (r & 7)) << 4);
        cpa16(sb + so,         Qh + (size_t)r * 768 + seg * 8);
        cpa16(sb + 16384 + so, Ql + (size_t)r * 768 + seg * 8);
    }
#pragma unroll
    for (int it = 0; it < 2; it++){
        int i = tid + it * 256;
        int r = i >> 3, seg = i & 7;
        uint32_t so = r * 128 + ((seg ^ (r & 7)) << 4);
        cpa16(sb + 32768 + so,         Kh + (size_t)(kv0 + r) * 768 + seg * 8);
        cpa16(sb + 32768 + 8192 + so,  Kl + (size_t)(kv0 + r) * 768 + seg * 8);
        cpa16(sb + 32768 + 16384 + so, Vh + (size_t)r * 4096 + kv0 + seg * 8);
        cpa16(sb + 32768 + 24576 + so, Vl + (size_t)r * 4096 + kv0 + seg * 8);
    }
    cpa_commit();
    asm volatile("cp.async.wait_group 0;" ::: "memory");
    __syncthreads();

    uint32_t qf_h[4][4], qf_l[4][4];
#pragma unroll
    for (int ks = 0; ks < 4; ks++){
        int r = wid * 16 + (lane & 15);
        int seg = ks * 2 + (lane >> 4);
        uint32_t ad = sb + r * 128 + ((seg ^ (r & 7)) << 4);
        ldm_x4(qf_h[ks], ad);
        ldm_x4(qf_l[ks], ad + 16384);
    }

    float m0 = -1e30f, m1 = -1e30f, l0 = 0.f, l1 = 0.f;
    float acc_o[8][4] = {};
    int buf = 0;

    for (int kt = 0; kt < 32; kt++){
        if (kt < 31){
            uint32_t bo = sb + 32768 + (buf ^ 1) * 32768;
            int key0 = kv0 + (kt + 1) * 64;
#pragma unroll
            for (int it = 0; it < 2; it++){
                int i = tid + it * 256;
                int r = i >> 3, seg = i & 7;
                uint32_t so = r * 128 + ((seg ^ (r & 7)) << 4);
                cpa16(bo + so,         Kh + (size_t)(key0 + r) * 768 + seg * 8);
                cpa16(bo + 8192 + so,  Kl + (size_t)(key0 + r) * 768 + seg * 8);
                cpa16(bo + 16384 + so, Vh + (size_t)r * 4096 + key0 + seg * 8);
                cpa16(bo + 24576 + so, Vl + (size_t)r * 4096 + key0 + seg * 8);
            }
            cpa_commit();
            asm volatile("cp.async.wait_group 1;" ::: "memory");
        } else {
            asm volatile("cp.async.wait_group 0;" ::: "memory");
        }
        __syncthreads();

        uint32_t kb = sb + 32768 + buf * 32768;

        float acc_s[8][4] = {};
#pragma unroll
        for (int ks = 0; ks < 4; ks++){
            uint32_t bh[8][2], bl[8][2];
#pragma unroll
            for (int nt = 0; nt < 8; nt++){
                int r = nt * 8 + (lane & 7);
                int seg = ks * 2 + ((lane >> 3) & 1);
                uint32_t bd = kb + r * 128 + ((seg ^ (r & 7)) << 4);
                ldm_x2(bh[nt], bd);
                ldm_x2(bl[nt], bd + 8192);
            }
#pragma unroll
            for (int nt = 0; nt < 8; nt++){
                mma_bf16(acc_s[nt], qf_h[ks], bh[nt]);
                mma_bf16(acc_s[nt], qf_h[ks], bl[nt]);
                mma_bf16(acc_s[nt], qf_l[ks], bh[nt]);
            }
        }
#pragma unroll
        for (int nt = 0; nt < 8; nt++){
            acc_s[nt][0] *= 0.125f; acc_s[nt][1] *= 0.125f;
            acc_s[nt][2] *= 0.125f; acc_s[nt][3] *= 0.125f;
        }

        float tm0 = -1e30f, tm1 = -1e30f;
#pragma unroll
        for (int nt = 0; nt < 8; nt++){
            tm0 = fmaxf(tm0, fmaxf(acc_s[nt][0], acc_s[nt][1]));
            tm1 = fmaxf(tm1, fmaxf(acc_s[nt][2], acc_s[nt][3]));
        }
        tm0 = fmaxf(tm0, __shfl_xor_sync(~0u, tm0, 1)); tm0 = fmaxf(tm0, __shfl_xor_sync(~0u, tm0, 2));
        tm1 = fmaxf(tm1, __shfl_xor_sync(~0u, tm1, 1)); tm1 = fmaxf(tm1, __shfl_xor_sync(~0u, tm1, 2));
        float mn0 = fmaxf(m0, tm0), mn1 = fmaxf(m1, tm1);
        float sc0 = __expf(m0 - mn0), sc1 = __expf(m1 - mn1);
        m0 = mn0; m1 = mn1;
        l0 *= sc0; l1 *= sc1;
#pragma unroll
        for (int nt = 0; nt < 8; nt++){
            acc_o[nt][0] *= sc0; acc_o[nt][1] *= sc0;
            acc_o[nt][2] *= sc1; acc_o[nt][3] *= sc1;
        }
        float rs0 = 0.f, rs1 = 0.f;
        uint32_t pa_h[4][4], pa_l[4][4];
#pragma unroll
        for (int nt = 0; nt < 8; nt++){
            float p0 = __expf(acc_s[nt][0] - mn0), p1 = __expf(acc_s[nt][1] - mn0);
            float p2 = __expf(acc_s[nt][2] - mn1), p3 = __expf(acc_s[nt][3] - mn1);
            rs0 += p0 + p1; rs1 += p2 + p3;
            int k2 = nt >> 1;
            if (!(nt & 1)){
                splitpack(p0, p1, pa_h[k2][0], pa_l[k2][0]);
                splitpack(p2, p3, pa_h[k2][1], pa_l[k2][1]);
            } else {
                splitpack(p0, p1, pa_h[k2][2], pa_l[k2][2]);
                splitpack(p2, p3, pa_h[k2][3], pa_l[k2][3]);
            }
        }
        rs0 += __shfl_xor_sync(~0u, rs0, 1); rs0 += __shfl_xor_sync(~0u, rs0, 2);
        rs1 += __shfl_xor_sync(~0u, rs1, 1); rs1 += __shfl_xor_sync(~0u, rs1, 2);
        l0 += rs0; l1 += rs1;

        uint32_t vb = kb + 16384;
#pragma unroll
        for (int k2 = 0; k2 < 4; k2++){
            uint32_t vh[8][2], vl[8][2];
#pragma unroll
            for (int nt = 0; nt < 8; nt++){
                int r = nt * 8 + (lane & 7);
                int seg = k2 * 2 + ((lane >> 3) & 1);
                uint32_t vd = vb + r * 128 + ((seg ^ (r & 7)) << 4);
                ldm_x2(vh[nt], vd);
                ldm_x2(vl[nt], vd + 8192);
            }
#pragma unroll
            for (int nt = 0; nt < 8; nt++){
                mma_bf16(acc_o[nt], pa_h[k2], vh[nt]);
                mma_bf16(acc_o[nt], pa_h[k2], vl[nt]);
                mma_bf16(acc_o[nt], pa_l[k2], vh[nt]);
            }
        }
        __syncthreads();
        buf ^= 1;
    }

    int r = row0 + wid * 16 + (lane >> 2);
    size_t ro0 = ((size_t)z * NNODE + r) * 256;
    size_t ro1 = ((size_t)z * NNODE + r + 8) * 256;
#pragma unroll
    for (int nt = 0; nt < 8; nt++){
        int cc = head * 64 + nt * 8 + ((lane & 3) << 1);
        pO[ro0 + cc]     = acc_o[nt][0];
        pO[ro0 + cc + 1] = acc_o[nt][1];
        pO[ro1 + cc]     = acc_o[nt][2];
        pO[ro1 + cc + 1] = acc_o[nt][3];
    }
    if ((lane & 3) == 0){
        pML[((size_t)z * NNODE + r) * 8 + head * 2]     = m0;
        pML[((size_t)z * NNODE + r) * 8 + head * 2 + 1] = l0;
        pML[((size_t)z * NNODE + r + 8) * 8 + head * 2]     = m1;
        pML[((size_t)z * NNODE + r + 8) * 8 + head * 2 + 1] = l1;
    }
}

// combo: blocks 0..255 = flash; 256..767 = LSTM-gates GEMM
__global__ void __launch_bounds__(256) k_combo(
    GA a,
    const __nv_bfloat16* __restrict__ qkvh, const __nv_bfloat16* __restrict__ qkvl,
    const __nv_bfloat16* __restrict__ vth, const __nv_bfloat16* __restrict__ vtl,
    float* __restrict__ pO, float* __restrict__ pML)
{
    int bx = blockIdx.x;
    if (bx < 256){
        int row0 = (bx & 31) * 128;
        int head = (bx >> 5) & 3;
        int z = bx >> 7;
        flash_body(qkvh, qkvl, vth, vtl, pO, pML, row0, head, z);
    } else {
        int idx = bx - 256;
        gemm_core(a, (idx >> 4) * 128, (idx & 15) * 64);
    }
}

// ================= pointwise =================
__global__ void k_mergelstm(const float* __restrict__ pO, const float* __restrict__ pML,
                            __nv_bfloat16* __restrict__ Oh, __nv_bfloat16* __restrict__ Ol,
                            const float* __restrict__ G, float* __restrict__ ht_out){
    int b = blockIdx.x;
    if (b < NNODE){
        int row = b, col = threadIdx.x;
        int head = col >> 6;
        float m0 = pML[(size_t)row * 8 + head * 2],            l0 = pML[(size_t)row * 8 + head * 2 + 1];
        float m1 = pML[((size_t)NNODE + row) * 8 + head * 2],  l1 = pML[((size_t)NNODE + row) * 8 + head * 2 + 1];
        float mx = fmaxf(m0, m1);
        float w0 = __expf(m0 - mx), w1 = __expf(m1 - mx);
        float num = pO[(size_t)row * 256 + col] * w0 + pO[((size_t)NNODE + row) * 256 + col] * w1;
        float den = l0 * w0 + l1 * w1;
        f2hl(num / den, Oh, Ol, (size_t)row * 256 + col);
    } else {
        int idx = (b - NNODE) * 256 + threadIdx.x;
        int n = idx >> 8, j = idx & 255;
        const float* gr = G + (size_t)n * 1024;
        float ig = gr[j], gg = gr[512 + j], og = gr[768 + j];
        float cc = sigmf(ig) * tanhf(gg);
        float hv = sigmf(og) * tanhf(cc);
        ht_out[idx] = hv;
        f2hl(hv, g_hcath, g_hcatl, (size_t)n * 512 + j);
    }
}

// ================= launch =================
#define SYMADDR(p, s) do { void* _t; cudaGetSymbolAddress(&_t, s); p = (decltype(p))_t; } while(0)

extern "C" void kernel_launch(void* const* d_in, const int* in_sizes, int n_in,
                              void* d_out, int out_size) {
    const float* x     = (const float*)d_in[0];
    const int*   ei_t  = (const int*)d_in[1];
    const int*   ei_c  = (const int*)d_in[2];
    const float* ea_t  = (const float*)d_in[3];
    const float* ea_c  = (const float*)d_in[4];
    const float* W_t   = (const float*)d_in[5];
    const float* asrc_t= (const float*)d_in[6];
    const float* adst_t= (const float*)d_in[7];
    const float* We_t  = (const float*)d_in[8];
    const float* ae_t  = (const float*)d_in[9];
    const float* b_t   = (const float*)d_in[10];
    const float* W_c   = (const float*)d_in[11];
    const float* asrc_c= (const float*)d_in[12];
    const float* adst_c= (const float*)d_in[13];
    const float* We_c  = (const float*)d_in[14];
    const float* ae_c  = (const float*)d_in[15];
    const float* b_c   = (const float*)d_in[16];
    const float* lstm_Wih = (const float*)d_in[17];
    const float* lstm_bih = (const float*)d_in[19];
    const float* lstm_bhh = (const float*)d_in[20];
    const float* mha_in_w  = (const float*)d_in[21];
    const float* mha_in_b  = (const float*)d_in[22];
    const float* mha_out_w = (const float*)d_in[23];
    const float* mha_out_b = (const float*)d_in[24];
    const float* fus_w = (const float*)d_in[25];
    const float* fus_b = (const float*)d_in[26];
    const float* out_w = (const float*)d_in[27];
    const float* out_b = (const float*)d_in[28];

    float* big; SYMADDR(big, g_big);
    float* po;  SYMADDR(po, g_po);
    float* pml; SYMADDR(pml, g_pml);
    float* xp0; SYMADDR(xp0, g_xp);
    float* xp1 = xp0 + (size_t)NNODE * NHC;
    float* as0; SYMADDR(as0, g_as);
    float* as1 = as0 + NNODE * NH;
    float* ad0; SYMADDR(ad0, g_ad);
    float* ad1 = ad0 + NNODE * NH;
    __nv_bfloat16 *hth, *htl, *hch, *hcl, *qkvh, *qkvl, *vth, *vtl;
    __nv_bfloat16 *attnh, *attnl, *hcath, *hcatl, *hfush, *hfusl;
    __nv_bfloat16 *wihh, *wihl, *inwh, *inwl, *mowh, *mowl, *fuwh, *fuwl, *owh, *owl;
    __nv_bfloat16 *xpadh, *xpadl, *wpadh, *wpadl;
    SYMADDR(hth, g_hth); SYMADDR(htl, g_htl); SYMADDR(hch, g_hch); SYMADDR(hcl, g_hcl);
    SYMADDR(qkvh, g_qkvh); SYMADDR(qkvl, g_qkvl); SYMADDR(vth, g_vth); SYMADDR(vtl, g_vtl);
    SYMADDR(attnh, g_attnh); SYMADDR(attnl, g_attnl);
    SYMADDR(hcath, g_hcath); SYMADDR(hcatl, g_hcatl);
    SYMADDR(hfush, g_hfush); SYMADDR(hfusl, g_hfusl);
    SYMADDR(wihh, g_wihh); SYMADDR(wihl, g_wihl);
    SYMADDR(inwh, g_inwh); SYMADDR(inwl, g_inwl);
    SYMADDR(mowh, g_mowh); SYMADDR(mowl, g_mowl);
    SYMADDR(fuwh, g_fuwh); SYMADDR(fuwl, g_fuwl);
    SYMADDR(owh, g_owh); SYMADDR(owl, g_owl);
    SYMADDR(xpadh, g_xpadh); SYMADDR(xpadl, g_xpadl);
    SYMADDR(wpadh, g_wpadh); SYMADDR(wpadl, g_wpadl);

    cudaFuncSetAttribute(k_combo,  cudaFuncAttributeMaxDynamicSharedMemorySize, 98304);
    cudaFuncSetAttribute(mma_single, cudaFuncAttributeMaxDynamicSharedMemorySize, 98304);
    cudaFuncSetAttribute(mma_dual, cudaFuncAttributeMaxDynamicSharedMemorySize, 98304);
    const int DYN = 98304;

    float* out_main = (float*)d_out;
    float* out_ht   = out_main + (size_t)NNODE * NOUT;
    float* out_hc   = out_ht   + (size_t)NNODE * HID;

    const int* src_t = ei_t; const int* dst_t = ei_t + NE;
    const int* src_c = ei_c; const int* dst_c = ei_c + NE;
    int nepb2 = (NEP + 511) / 512;

    k_initconv<<<128 + NCONVB, 256>>>(ea_t, ea_c, lstm_Wih, mha_in_w, mha_out_w, fus_w, out_w, x, W_t, W_c);
    k_setupcount<<<1 + 1024, 256>>>(We_t, ae_t, We_c, ae_c, lstm_bih, lstm_bhh, dst_t, dst_c);

    // ---- xp GEMMs (z=0/1) + count prefix scans (z=2) ----
    {
        GA a0 = { xpadh, xpadl, wpadh, wpadl, xp0, nullptr, nullptr, nullptr,
                  asrc_t, adst_t, as0, ad0, nullptr, nullptr,
                  64, 64, NHC, 0, 0, 64, 0, 32, 1.f };
        GA a1 = { xpadh, xpadl, wpadh + (size_t)NHC * 64, wpadl + (size_t)NHC * 64, xp1,
                  nullptr, nullptr, nullptr,
                  asrc_c, adst_c, as1, ad1, nullptr, nullptr,
                  64, 64, NHC, 0, 0, 64, 0, 32, 1.f };
        mma_dual<<<dim3(32, 32, 3), 256, DYN>>>(a0, a1);
    }

    // ---- edge scatter + logits (2 edges/thread) ----
    k_scatalpha<<<dim3(nepb2, 2), 256>>>(src_t, dst_t, ea_t, src_c, dst_c, ea_c);

    // ---- aggregation, both graphs concurrently ----
    k_agg<<<dim3(NNODE, 2), 256>>>(src_t, src_c, b_t, b_c);

    // ---- qkv GEMM (4096x768x256), V-transpose fused in epilogue ----
    {
        GA a = { hch, hcl, inwh, inwl, nullptr, qkvh, qkvl, mha_in_b,
                 nullptr, nullptr, nullptr, nullptr, vth, vtl,
                 256, 256, 0, 768, 0, 256, 0, 12, 1.f };
        mma_single<<<dim3(12, 32), 256, DYN>>>(a);
    }

    // ---- flash attention + LSTM gates GEMM overlapped ----
    {
        GA a = { hth, htl, wihh, wihl, big + OFF_G, nullptr, nullptr, big + OFF_BSUM,
                 nullptr, nullptr, nullptr, nullptr, nullptr, nullptr,
                 NHC, NHC, 1024, 0, 0, NHC, 0, 16, 1.f };
        k_combo<<<768, 256, DYN>>>(a, qkvh, qkvl, vth, vtl, po, pml);
    }

    // ---- merge flash partials + lstm pointwise ----
    k_mergelstm<<<2 * NNODE, 256>>>(po, pml, attnh, attnl, big + OFF_G, out_ht);

    // ---- proj (4096x256x256) ----
    {
        GA a = { attnh, attnl, mowh, mowl, out_hc, hcath, hcatl, mha_out_b,
                 nullptr, nullptr, nullptr, nullptr, nullptr, nullptr,
                 256, 256, 256, 512, 256, 256, 0, 4, 1.f };
        mma_single<<<dim3(4, 32), 256, DYN>>>(a);
    }
    // ---- fusion relu (4096x256x512) ----
    {
        GA a = { hcath, hcatl, fuwh, fuwl, nullptr, hfush, hfusl, fus_b,
                 nullptr, nullptr, nullptr, nullptr, nullptr, nullptr,
                 512, 512, 0, 256, 0, 512, 1, 4, 1.f };
        mma_single<<<dim3(4, 32), 256, DYN>>>(a);
    }
    // ---- out (4096x128x256) ----
    {
        GA a = { hfush, hfusl, owh, owl, out_main, nullptr, nullptr, out_b,
                 nullptr, nullptr, nullptr, nullptr, nullptr, nullptr,
                 256, 256, NOUT, 0, 0, 256, 0, 2, 1.f };
        mma_single<<<dim3(2, 32), 256, DYN>>>(a);
    }
}

// round 16
// speedup vs baseline: 1.1037x; 1.0172x over previous
#include <cuda_runtime.h>
#include <cuda_bf16.h>
#include <math.h>
#include <float.h>
#include <stdint.h>

#define NNODE 4096
#define NIN   28
#define NE    131072
#define NEP   (NE + NNODE)
#define NH    8
#define NC    256
#define NHC   2048
#define HID   256
#define NOUT  128
#define ECAP  256

// ---------------- fp32 scratch ----------------
#define OFF_G    ((size_t)0)
#define OFF_BSUM (OFF_G + (size_t)NNODE * 1024)
#define BIG_SZ   (OFF_BSUM + 1024)
__device__ float g_big[BIG_SZ];

__device__ float g_xp[2][(size_t)NNODE * NHC];
__device__ float g_as[2][NNODE * NH];
__device__ float g_ad[2][NNODE * NH];
__device__ int   g_cnt[2][NNODE];
__device__ int   g_cur[2][NNODE];
__device__ int   g_start[2][NNODE];
__device__ int   g_sorted[2][NE];
__device__ float g_part[2][128];
__device__ float g_mean[2];
__device__ float g_ce[2][NH];

// flash split-K partials
__device__ float g_po[(size_t)2 * NNODE * 256];
__device__ float g_pml[(size_t)2 * NNODE * 8];

// ---------------- bf16 hi/lo tensors ----------------
__device__ __nv_bfloat16 g_hth[(size_t)NNODE * NHC], g_htl[(size_t)NNODE * NHC];
__device__ __nv_bfloat16 g_hch[(size_t)NNODE * 256], g_hcl[(size_t)NNODE * 256];
__device__ __nv_bfloat16 g_qkvh[(size_t)NNODE * 768], g_qkvl[(size_t)NNODE * 768];
__device__ __nv_bfloat16 g_vth[(size_t)4 * 64 * NNODE], g_vtl[(size_t)4 * 64 * NNODE];
__device__ __nv_bfloat16 g_attnh[(size_t)NNODE * 256], g_attnl[(size_t)NNODE * 256];
__device__ __nv_bfloat16 g_hcath[(size_t)NNODE * 512], g_hcatl[(size_t)NNODE * 512];
__device__ __nv_bfloat16 g_hfush[(size_t)NNODE * 256], g_hfusl[(size_t)NNODE * 256];
// weights
__device__ __nv_bfloat16 g_wihh[1024 * 2048], g_wihl[1024 * 2048];
__device__ __nv_bfloat16 g_inwh[768 * 256],   g_inwl[768 * 256];
__device__ __nv_bfloat16 g_mowh[256 * 256],   g_mowl[256 * 256];
__device__ __nv_bfloat16 g_fuwh[256 * 512],   g_fuwl[256 * 512];
__device__ __nv_bfloat16 g_owh[128 * 256],    g_owl[128 * 256];
// padded x / W for tensor-core xp GEMM
__device__ __nv_bfloat16 g_xpadh[(size_t)NNODE * 64], g_xpadl[(size_t)NNODE * 64];
__device__ __nv_bfloat16 g_wpadh[(size_t)2 * NHC * 64], g_wpadl[(size_t)2 * NHC * 64];

// ---------------- helpers ----------------
__device__ __forceinline__ int   f2ord(float f){ int i = __float_as_int(f); return i >= 0 ? i : i ^ 0x7fffffff; }
__device__ __forceinline__ float ord2f(int k){ return __int_as_float(k >= 0 ? k : k ^ 0x7fffffff); }
__device__ __forceinline__ float sigmf(float x){ return 1.f / (1.f + expf(-x)); }
__device__ __forceinline__ void f2hl(float v, __nv_bfloat16* H, __nv_bfloat16* L, size_t i){
    __nv_bfloat16 h = __float2bfloat16(v);
    H[i] = h; L[i] = __float2bfloat16(v - __bfloat162float(h));
}
__device__ __forceinline__ uint32_t smem_u32(const void* p){
    uint32_t a;
    asm("{ .reg .u64 t; cvta.to.shared.u64 t, %1; cvt.u32.u64 %0, t; }" : "=r"(a) : "l"(p));
    return a;
}
__device__ __forceinline__ void ldm_x4(uint32_t* r, uint32_t addr){
    asm volatile("ldmatrix.sync.aligned.m8n8.x4.shared.b16 {%0,%1,%2,%3}, [%4];"
        : "=r"(r[0]), "=r"(r[1]), "=r"(r[2]), "=r"(r[3]) : "r"(addr));
}
__device__ __forceinline__ void ldm_x2(uint32_t* r, uint32_t addr){
    asm volatile("ldmatrix.sync.aligned.m8n8.x2.shared.b16 {%0,%1}, [%2];"
        : "=r"(r[0]), "=r"(r[1]) : "r"(addr));
}
__device__ __forceinline__ void mma_bf16(float* c, const uint32_t* a, const uint32_t* b){
    asm volatile("mma.sync.aligned.m16n8k16.row.col.f32.bf16.bf16.f32 "
        "{%0,%1,%2,%3}, {%4,%5,%6,%7}, {%8,%9}, {%0,%1,%2,%3};"
        : "+f"(c[0]), "+f"(c[1]), "+f"(c[2]), "+f"(c[3])
        : "r"(a[0]), "r"(a[1]), "r"(a[2]), "r"(a[3]), "r"(b[0]), "r"(b[1]));
}
__device__ __forceinline__ void cpa16(uint32_t saddr, const void* g){
    asm volatile("cp.async.ca.shared.global [%0], [%1], 16;" :: "r"(saddr), "l"(g));
}
__device__ __forceinline__ void cpa_commit(){ asm volatile("cp.async.commit_group;" ::: "memory"); }
__device__ __forceinline__ void splitpack(float a, float b, uint32_t& hi, uint32_t& lo){
    __nv_bfloat16 ha = __float2bfloat16(a), hb = __float2bfloat16(b);
    __nv_bfloat16 la = __float2bfloat16(a - __bfloat162float(ha));
    __nv_bfloat16 lb = __float2bfloat16(b - __bfloat162float(hb));
    hi = ((uint32_t)__bfloat16_as_ushort(hb) << 16) | (uint32_t)__bfloat16_as_ushort(ha);
    lo = ((uint32_t)__bfloat16_as_ushort(lb) << 16) | (uint32_t)__bfloat16_as_ushort(la);
}

// ================= setup (initmean + weight conversions, one launch) =================
#define CW0 2097152
#define CW1 (CW0 + 196608)
#define CW2 (CW1 + 65536)
#define CW3 (CW2 + 131072)
#define CW4 (CW3 + 32768)
#define CW5 (CW4 + NNODE * 64)
#define CW6 (CW5 + 2 * NHC * 64)
#define NCONVB ((CW6 + 255) / 256)

__global__ void k_initconv(const float* __restrict__ ea_t, const float* __restrict__ ea_c,
                           const float* __restrict__ w0, const float* __restrict__ w1,
                           const float* __restrict__ w2, const float* __restrict__ w3,
                           const float* __restrict__ w4, const float* __restrict__ x,
                           const float* __restrict__ W_t, const float* __restrict__ W_c){
    int bx = blockIdx.x;
    if (bx < 128){
        int idx = bx * 256 + threadIdx.x, stride = 128 * 256;
        for (int i = idx; i < NNODE * NH; i += stride){
            g_as[0][i] = 0.f; g_as[1][i] = 0.f;
            g_ad[0][i] = 0.f; g_ad[1][i] = 0.f;
        }
        for (int i = idx; i < NNODE; i += stride){
            g_cnt[0][i] = 0; g_cnt[1][i] = 0;
            g_cur[0][i] = 0; g_cur[1][i] = 0;
        }
        __shared__ float s0[256], s1[256];
        float a = 0.f, b = 0.f;
        for (int i = idx; i < NE; i += stride){ a += ea_t[i]; b += ea_c[i]; }
        s0[threadIdx.x] = a; s1[threadIdx.x] = b; __syncthreads();
        for (int s = 128; s; s >>= 1){
            if (threadIdx.x < s){ s0[threadIdx.x] += s0[threadIdx.x+s]; s1[threadIdx.x] += s1[threadIdx.x+s]; }
            __syncthreads();
        }
        if (!threadIdx.x){ g_part[0][bx] = s0[0]; g_part[1][bx] = s1[0]; }
        return;
    }
    int i = (bx - 128) * 256 + threadIdx.x;
    if (i < CW0)      f2hl(w0[i], g_wihh, g_wihl, i);
    else if (i < CW1) f2hl(w1[i - CW0], g_inwh, g_inwl, i - CW0);
    else if (i < CW2) f2hl(w2[i - CW1], g_mowh, g_mowl, i - CW1);
    else if (i < CW3) f2hl(w3[i - CW2], g_fuwh, g_fuwl, i - CW2);
    else if (i < CW4) f2hl(w4[i - CW3], g_owh, g_owl, i - CW3);
    else if (i < CW5){
        int j = i - CW4; int n = j >> 6, k = j & 63;
        float v = (k < NIN) ? x[n * NIN + k] : 0.f;
        f2hl(v, g_xpadh, g_xpadl, j);
    } else if (i < CW6){
        int j = i - CW5; int g = j >> 17; int r = j & 131071;
        int n = r >> 6, k = r & 63;
        const float* W = g ? W_c : W_t;
        float v = (k < NIN) ? W[k * NHC + n] : 0.f;
        f2hl(v, g_wpadh, g_wpadl, j);
    }
}

// ================= setup (means/ce/bsum) + edge count, one launch =================
__global__ void k_setupcount(const float* __restrict__ We_t, const float* __restrict__ ae_t,
                             const float* __restrict__ We_c, const float* __restrict__ ae_c,
                             const float* __restrict__ bih,  const float* __restrict__ bhh,
                             const int* __restrict__ dst_t, const int* __restrict__ dst_c){
    int bx = blockIdx.x;
    if (bx == 0){
        __shared__ float sh[256];
        int tid = threadIdx.x;
        for (int g = 0; g < 2; g++){
            sh[tid] = (tid < 128) ? g_part[g][tid] : 0.f;
            __syncthreads();
            for (int s = 128; s; s >>= 1){ if (tid < s) sh[tid] += sh[tid+s]; __syncthreads(); }
            if (!tid) g_mean[g] = sh[0] / (float)NE;
            __syncthreads();
        }
        int wid = tid >> 5, lane = tid & 31;
        for (int c = wid; c < 16; c += 8){
            int g = c >> 3, h = c & 7;
            const float* We = g ? We_c : We_t;
            const float* ae = g ? ae_c : ae_t;
            float s = 0.f;
            for (int i = lane; i < NC; i += 32) s = fmaf(We[h*NC + i], ae[h*NC + i], s);
            for (int o = 16; o; o >>= 1) s += __shfl_down_sync(0xffffffffu, s, o);
            if (!lane) g_ce[g][h] = s;
        }
        for (int j = tid; j < 1024; j += 256) g_big[OFF_BSUM + j] = bih[j] + bhh[j];
        return;
    }
    int idx = bx - 1;
    int g = idx >> 9;
    const int* dst = g ? dst_c : dst_t;
    int e = (idx & 511) * 256 + threadIdx.x;
    atomicAdd(&g_cnt[g][dst[e]], 1);
}

// 256-thread scan over 4096 counts (runs inside the xp mma_dual launch, z==2)
__device__ void scan_body(int g){
    __shared__ int sh[256];
    int tid = threadIdx.x;
    int base = tid * 16;
    int local[16]; int s = 0;
#pragma unroll
    for (int i = 0; i < 16; i++){ local[i] = g_cnt[g][base + i]; s += local[i]; }
    sh[tid] = s; __syncthreads();
    for (int off = 1; off < 256; off <<= 1){
        int v = (tid >= off) ? sh[tid - off] : 0;
        __syncthreads();
        sh[tid] += v;
        __syncthreads();
    }
    int run = sh[tid] - s;
#pragma unroll
    for (int i = 0; i < 16; i++){ g_start[g][base + i] = run; run += local[i]; }
}

// ================= GAT edge pipeline =================
// counting-sort scatter only (2 edges/thread); logits computed inside k_agg
__global__ void k_scatter(const int* __restrict__ dst_t, const int* __restrict__ dst_c){
    int g = blockIdx.y;
    const int* dst = g ? dst_c : dst_t;
    int e0 = blockIdx.x * 512 + threadIdx.x;
    int e1 = e0 + 256;
    if (e0 < NE){
        int d = dst[e0];
        g_sorted[g][g_start[g][d] + atomicAdd(&g_cur[g][d], 1)] = e0;
    }
    if (e1 < NE){
        int d = dst[e1];
        g_sorted[g][g_start[g][d] + atomicAdd(&g_cur[g][d], 1)] = e1;
    }
}

// fused: logits + per-node max + exp + denominator + weighted aggregation
__global__ void __launch_bounds__(256) k_agg(
        const int* __restrict__ src_t, const int* __restrict__ src_c,
        const float* __restrict__ ea_t, const float* __restrict__ ea_c,
        const float* __restrict__ b_t, const float* __restrict__ b_c){
    int g = blockIdx.y;
    const int* src = g ? src_c : src_t;
    const float* ea = g ? ea_c : ea_t;
    const float* bias = g ? b_c : b_t;
    int n = blockIdx.x, t = threadIdx.x;
    const float* xp = g_xp[g];
    const float* as = g_as[g];

    __shared__ float s_ad[NH], s_ce[NH], s_self[NH];
    __shared__ int   smxi[NH];
    __shared__ float smx[NH];
    __shared__ int   sc_src[ECAP];
    __shared__ float sc_w[ECAP][NH];
    if (t < NH){
        float adv = g_ad[g][n*NH + t];
        float cev = g_ce[g][t];
        s_ad[t] = adv; s_ce[t] = cev;
        float sv = as[n*NH + t] + adv + g_mean[g] * cev;
        sv = sv > 0.f ? sv : 0.2f * sv;
        s_self[t] = sv;
        smxi[t] = f2ord(sv);          // init max with self-loop logit
    }
    __syncthreads();

    int st = g_start[g][n], c = g_cnt[g][n];
    int cc = min(c, ECAP);

    // ---- prepass: compute logits (cache first ECAP), track per-head max ----
    {
        float lm[NH];
#pragma unroll
        for (int h = 0; h < NH; h++) lm[h] = -FLT_MAX;
        for (int i = t; i < c; i += 256){
            int e = g_sorted[g][st + i];
            int s = src[e];
            float av = ea[e];
            float4 a0 = *(const float4*)&as[s*NH];
            float4 a1 = *(const float4*)&as[s*NH + 4];
            float al[NH];
            al[0] = a0.x + s_ad[0] + av * s_ce[0];
            al[1] = a0.y + s_ad[1] + av * s_ce[1];
            al[2] = a0.z + s_ad[2] + av * s_ce[2];
            al[3] = a0.w + s_ad[3] + av * s_ce[3];
            al[4] = a1.x + s_ad[4] + av * s_ce[4];
            al[5] = a1.y + s_ad[5] + av * s_ce[5];
            al[6] = a1.z + s_ad[6] + av * s_ce[6];
            al[7] = a1.w + s_ad[7] + av * s_ce[7];
#pragma unroll
            for (int h = 0; h < NH; h++){
                al[h] = al[h] > 0.f ? al[h] : 0.2f * al[h];
                lm[h] = fmaxf(lm[h], al[h]);
            }
            if (i < ECAP){
                sc_src[i] = s;
#pragma unroll
                for (int h = 0; h < NH; h++) sc_w[i][h] = al[h];
            }
        }
#pragma unroll
        for (int h = 0; h < NH; h++){
            for (int o = 16; o; o >>= 1) lm[h] = fmaxf(lm[h], __shfl_xor_sync(~0u, lm[h], o));
        }
        if ((t & 31) == 0){
#pragma unroll
            for (int h = 0; h < NH; h++) atomicMax(&smxi[h], f2ord(lm[h]));
        }
    }
    __syncthreads();
    if (t < NH) smx[t] = ord2f(smxi[t]);
    __syncthreads();

    // exp-convert cached logits in place
    for (int j = t; j < cc * NH; j += 256){
        int i = j >> 3, h = j & 7;
        sc_w[i][h] = expf(sc_w[i][h] - smx[h]);
    }
    __syncthreads();

    float acc[NH], den[NH];
    {
        const float* xr = xp + (size_t)n * NHC + t;
#pragma unroll
        for (int h = 0; h < NH; h++){
            float exs = expf(s_self[h] - smx[h]);
            acc[h] = exs * xr[h * NC];
            den[h] = exs;
        }
    }
    // main gather over cached edges (no syncs needed)
    int jj = 0;
    for (; jj + 4 <= cc; jj += 4){
        const float* x0 = xp + (size_t)sc_src[jj+0] * NHC + t;
        const float* x1 = xp + (size_t)sc_src[jj+1] * NHC + t;
        const float* x2 = xp + (size_t)sc_src[jj+2] * NHC + t;
        const float* x3 = xp + (size_t)sc_src[jj+3] * NHC + t;
        float v0[NH], v1[NH], v2[NH], v3[NH];
#pragma unroll
        for (int h = 0; h < NH; h++){ v0[h] = x0[h*NC]; v1[h] = x1[h*NC]; v2[h] = x2[h*NC]; v3[h] = x3[h*NC]; }
#pragma unroll
        for (int h = 0; h < NH; h++){
            float w0 = sc_w[jj+0][h], w1 = sc_w[jj+1][h], w2 = sc_w[jj+2][h], w3 = sc_w[jj+3][h];
            acc[h] = fmaf(w0, v0[h], acc[h]);
            acc[h] = fmaf(w1, v1[h], acc[h]);
            acc[h] = fmaf(w2, v2[h], acc[h]);
            acc[h] = fmaf(w3, v3[h], acc[h]);
            den[h] += (w0 + w1) + (w2 + w3);
        }
    }
    for (; jj < cc; jj++){
        const float* xr = xp + (size_t)sc_src[jj] * NHC + t;
#pragma unroll
        for (int h = 0; h < NH; h++){
            float ww = sc_w[jj][h];
            acc[h] = fmaf(ww, xr[h * NC], acc[h]);
            den[h] += ww;
        }
    }
    // overflow edges (c > ECAP): recompute logits exactly — effectively never taken
    for (int i = ECAP; i < c; i++){
        int e = g_sorted[g][st + i];
        int s = src[e];
        float av = ea[e];
        const float* xr = xp + (size_t)s * NHC + t;
#pragma unroll
        for (int h = 0; h < NH; h++){
            float al = as[s*NH + h] + s_ad[h] + av * s_ce[h];
            al = al > 0.f ? al : 0.2f * al;
            float ww = expf(al - smx[h]);
            acc[h] = fmaf(ww, xr[h * NC], acc[h]);
            den[h] += ww;
        }
    }

    if (g == 0){
#pragma unroll
        for (int h = 0; h < NH; h++){
            float v = acc[h] / (den[h] + 1e-16f) + bias[h * NC + t];
            f2hl(v, g_hth, g_htl, (size_t)n * NHC + h * NC + t);
        }
    } else {
        float s = 0.f;
#pragma unroll
        for (int h = 0; h < NH; h++) s += acc[h] / (den[h] + 1e-16f);
        f2hl(s * 0.125f + bias[t], g_hch, g_hcl, (size_t)n * NC + t);
    }
}

// ================= HMMA bf16x3 GEMM core =================
struct GA {
    const __nv_bfloat16 *Ah, *Al, *Bh, *Bl;
    float* C;
    __nv_bfloat16 *Ch, *Cl;
    const float* bias;
    const float *pas, *pad;
    float *oas, *oad;
    __nv_bfloat16 *vh2, *vl2;   // optional: transposed V write (qkv GEMM), cols >= 512
    int lda, ldb, ldc, ldc2, c2off, K, act, gx;
    float alpha;
};

__device__ __forceinline__ void gemm_core(const GA a, int row0, int col0){
    extern __shared__ char sm[];
    int tid = threadIdx.x, lane = tid & 31, wid = tid >> 5;
    int wm = wid & 3, wn = wid >> 2;
    const __nv_bfloat16* Ah = a.Ah + (size_t)row0 * a.lda;
    const __nv_bfloat16* Al = a.Al + (size_t)row0 * a.lda;
    const __nv_bfloat16* Bh = a.Bh + (size_t)col0 * a.ldb;
    const __nv_bfloat16* Bl = a.Bl + (size_t)col0 * a.ldb;

    uint32_t sbase = smem_u32(sm);
    int nkb = a.K >> 6;

    auto issue = [&](int kb, int st){
        uint32_t su = sbase + st * 49152;
        int k0 = kb << 6;
#pragma unroll
        for (int it = 0; it < 4; it++){
            int i = tid + it * 256;
            int row = i >> 3, seg = i & 7;
            size_t goff = (size_t)row * a.lda + k0 + seg * 8;
            uint32_t so = row * 128 + ((seg ^ (row & 7)) << 4);
            cpa16(su + so,         Ah + goff);
            cpa16(su + 16384 + so, Al + goff);
        }
#pragma unroll
        for (int it = 0; it < 2; it++){
            int i = tid + it * 256;
            int row = i >> 3, seg = i & 7;
            size_t goff = (size_t)row * a.ldb + k0 + seg * 8;
            uint32_t so = row * 128 + ((seg ^ (row & 7)) << 4);
            cpa16(su + 32768 + so, Bh + goff);
            cpa16(su + 40960 + so, Bl + goff);
        }
        cpa_commit();
    };

    issue(0, 0);
    if (nkb > 1) issue(1, 1);

    float acc[2][4][4] = {};
    for (int kb = 0; kb < nkb; kb++){
        if (kb + 1 < nkb) asm volatile("cp.async.wait_group 1;" ::: "memory");
        else              asm volatile("cp.async.wait_group 0;" ::: "memory");
        __syncthreads();
        uint32_t sb2 = sbase + (kb & 1) * 49152;
#pragma unroll
        for (int ks = 0; ks < 4; ks++){
            uint32_t a_h[2][4], a_l[2][4], b_h[4][2], b_l[4][2];
#pragma unroll
            for (int mt = 0; mt < 2; mt++){
                int r = wm * 32 + mt * 16 + (lane & 15);
                int seg = ks * 2 + (lane >> 4);
                uint32_t ad = sb2 + r * 128 + ((seg ^ (r & 7)) << 4);
                ldm_x4(a_h[mt], ad);
                ldm_x4(a_l[mt], ad + 16384);
            }
#pragma unroll
            for (int nt = 0; nt < 4; nt++){
                int r = wn * 32 + nt * 8 + (lane & 7);
                int seg = ks * 2 + ((lane >> 3) & 1);
                uint32_t bd = sb2 + 32768 + r * 128 + ((seg ^ (r & 7)) << 4);
                ldm_x2(b_h[nt], bd);
                ldm_x2(b_l[nt], bd + 8192);
            }
#pragma unroll
            for (int mt = 0; mt < 2; mt++)
#pragma unroll
                for (int nt = 0; nt < 4; nt++){
                    mma_bf16(acc[mt][nt], a_h[mt], b_h[nt]);
                    mma_bf16(acc[mt][nt], a_h[mt], b_l[nt]);
                    mma_bf16(acc[mt][nt], a_l[mt], b_h[nt]);
                }
        }
        __syncthreads();
        if (kb + 2 < nkb) issue(kb + 2, kb & 1);
    }

    float s1[4] = {}, s2[4] = {};
    int h = col0 >> 8;
#pragma unroll
    for (int mt = 0; mt < 2; mt++){
#pragma unroll
        for (int nt = 0; nt < 4; nt++){
            int r0 = row0 + wm * 32 + mt * 16 + (lane >> 2);
            int c0 = col0 + wn * 32 + nt * 8 + ((lane & 3) << 1);
#pragma unroll
            for (int q = 0; q < 4; q++){
                int r = r0 + (q >> 1) * 8;
                int cc = c0 + (q & 1);
                float v = acc[mt][nt][q] * a.alpha;
                if (a.bias) v += a.bias[cc];
                if (a.act == 1) v = fmaxf(v, 0.f);
                if (a.C) a.C[(size_t)r * a.ldc + cc] = v;
                if (a.Ch) f2hl(v, a.Ch, a.Cl, (size_t)r * a.ldc2 + a.c2off + cc);
                if (a.vh2 && cc >= 512) f2hl(v, a.vh2, a.vl2, (size_t)(cc - 512) * 4096 + r);
                if (a.pas){
                    int ridx = mt * 2 + (q >> 1);
                    int ci = h * 256 + (cc & 255);
                    s1[ridx] = fmaf(v, a.pas[ci], s1[ridx]);
                    s2[ridx] = fmaf(v, a.pad[ci], s2[ridx]);
                }
            }
        }
    }
    if (a.pas){
#pragma unroll
        for (int i = 0; i < 4; i++){
            s1[i] += __shfl_xor_sync(~0u, s1[i], 1); s1[i] += __shfl_xor_sync(~0u, s1[i], 2);
            s2[i] += __shfl_xor_sync(~0u, s2[i], 1); s2[i] += __shfl_xor_sync(~0u, s2[i], 2);
        }
        if ((lane & 3) == 0){
#pragma unroll
            for (int i = 0; i < 4; i++){
                int mt = i >> 1, rr = i & 1;
                int r = row0 + wm * 32 + mt * 16 + (lane >> 2) + rr * 8;
                atomicAdd(&a.oas[r * NH + h], s1[i]);
                atomicAdd(&a.oad[r * NH + h], s2[i]);
            }
        }
    }
}

__global__ void __launch_bounds__(256) mma_single(GA a){
    if ((int)blockIdx.x >= a.gx) return;
    gemm_core(a, blockIdx.y * 128, blockIdx.x * 64);
}
// z=0/1: the two xp GEMMs; z=2: the two edge-count prefix scans
__global__ void __launch_bounds__(256) mma_dual(GA a0, GA a1){
    if (blockIdx.z == 2){
        if (blockIdx.y == 0 && blockIdx.x < 2) scan_body(blockIdx.x);
        return;
    }
    GA a = blockIdx.z ? a1 : a0;
    if ((int)blockIdx.x >= a.gx) return;
    gemm_core(a, blockIdx.y * 128, blockIdx.x * 64);
}

// ================= flash attention body (split-KV) =================
__device__ void flash_body(
    const __nv_bfloat16* __restrict__ qkvh, const __nv_bfloat16* __restrict__ qkvl,
    const __nv_bfloat16* __restrict__ vth, const __nv_bfloat16* __restrict__ vtl,
    float* __restrict__ pO, float* __restrict__ pML,
    int row0, int head, int z)
{
    extern __shared__ char sm[];
    int tid = threadIdx.x, lane = tid & 31, wid = tid >> 5;
    int kv0 = z * 2048;
    uint32_t sb = smem_u32(sm);

    const __nv_bfloat16* Qh = qkvh + (size_t)row0 * 768 + head * 64;
    const __nv_bfloat16* Ql = qkvl + (size_t)row0 * 768 + head * 64;
    const __nv_bfloat16* Kh = qkvh + 256 + head * 64;
    const __nv_bfloat16* Kl = qkvl + 256 + head * 64;
    const __nv_bfloat16* Vh = vth + (size_t)head * 64 * 4096;
    const __nv_bfloat16* Vl = vtl + (size_t)head * 64 * 4096;

#pragma unroll
    for (int it = 0; it < 4; it++){
        int i = tid + it * 256;
        int r = i >> 3, seg = i & 7;
        uint32_t so = r * 128 + ((seg ^ (r & 7)) << 4);
        cpa16(sb + so,         Qh + (size_t)r * 768 + seg * 8);
        cpa16(sb + 16384 + so, Ql + (size_t)r * 768 + seg * 8);
    }
#pragma unroll
    for (int it = 0; it < 2; it++){
        int i = tid + it * 256;
        int r = i >> 3, seg = i & 7;
        uint32_t so = r * 128 + ((seg ^ (r & 7)) << 4);
        cpa16(sb + 32768 + so,         Kh + (size_t)(kv0 + r) * 768 + seg * 8);
        cpa16(sb + 32768 + 8192 + so,  Kl + (size_t)(kv0 + r) * 768 + seg * 8);
        cpa16(sb + 32768 + 16384 + so, Vh + (size_t)r * 4096 + kv0 + seg * 8);
        cpa16(sb + 32768 + 24576 + so, Vl + (size_t)r * 4096 + kv0 + seg * 8);
    }
    cpa_commit();
    asm volatile("cp.async.wait_group 0;" ::: "memory");
    __syncthreads();

    uint32_t qf_h[4][4], qf_l[4][4];
#pragma unroll
    for (int ks = 0; ks < 4; ks++){
        int r = wid * 16 + (lane & 15);
        int seg = ks * 2 + (lane >> 4);
        uint32_t ad = sb + r * 128 + ((seg ^ (r & 7)) << 4);
        ldm_x4(qf_h[ks], ad);
        ldm_x4(qf_l[ks], ad + 16384);
    }

    float m0 = -1e30f, m1 = -1e30f, l0 = 0.f, l1 = 0.f;
    float acc_o[8][4] = {};
    int buf = 0;

    for (int kt = 0; kt < 32; kt++){
        if (kt < 31){
            uint32_t bo = sb + 32768 + (buf ^ 1) * 32768;
            int key0 = kv0 + (kt + 1) * 64;
#pragma unroll
            for (int it = 0; it < 2; it++){
                int i = tid + it * 256;
                int r = i >> 3, seg = i & 7;
                uint32_t so = r * 128 + ((seg ^ (r & 7)) << 4);
                cpa16(bo + so,         Kh + (size_t)(key0 + r) * 768 + seg * 8);
                cpa16(bo + 8192 + so,  Kl + (size_t)(key0 + r) * 768 + seg * 8);
                cpa16(bo + 16384 + so, Vh + (size_t)r * 4096 + key0 + seg * 8);
                cpa16(bo + 24576 + so, Vl + (size_t)r * 4096 + key0 + seg * 8);
            }
            cpa_commit();
            asm volatile("cp.async.wait_group 1;" ::: "memory");
        } else {
            asm volatile("cp.async.wait_group 0;" ::: "memory");
        }
        __syncthreads();

        uint32_t kb = sb + 32768 + buf * 32768;

        float acc_s[8][4] = {};
#pragma unroll
        for (int ks = 0; ks < 4; ks++){
            uint32_t bh[8][2], bl[8][2];
#pragma unroll
            for (int nt = 0; nt < 8; nt++){
                int r = nt * 8 + (lane & 7);
                int seg = ks * 2 + ((lane >> 3) & 1);
                uint32_t bd = kb + r * 128 + ((seg ^ (r & 7)) << 4);
                ldm_x2(bh[nt], bd);
                ldm_x2(bl[nt], bd + 8192);
            }
#pragma unroll
            for (int nt = 0; nt < 8; nt++){
                mma_bf16(acc_s[nt], qf_h[ks], bh[nt]);
                mma_bf16(acc_s[nt], qf_h[ks], bl[nt]);
                mma_bf16(acc_s[nt], qf_l[ks], bh[nt]);
            }
        }
#pragma unroll
        for (int nt = 0; nt < 8; nt++){
            acc_s[nt][0] *= 0.125f; acc_s[nt][1] *= 0.125f;
            acc_s[nt][2] *= 0.125f; acc_s[nt][3] *= 0.125f;
        }

        float tm0 = -1e30f, tm1 = -1e30f;
#pragma unroll
        for (int nt = 0; nt < 8; nt++){
            tm0 = fmaxf(tm0, fmaxf(acc_s[nt][0], acc_s[nt][1]));
            tm1 = fmaxf(tm1, fmaxf(acc_s[nt][2], acc_s[nt][3]));
        }
        tm0 = fmaxf(tm0, __shfl_xor_sync(~0u, tm0, 1)); tm0 = fmaxf(tm0, __shfl_xor_sync(~0u, tm0, 2));
        tm1 = fmaxf(tm1, __shfl_xor_sync(~0u, tm1, 1)); tm1 = fmaxf(tm1, __shfl_xor_sync(~0u, tm1, 2));
        float mn0 = fmaxf(m0, tm0), mn1 = fmaxf(m1, tm1);
        float sc0 = __expf(m0 - mn0), sc1 = __expf(m1 - mn1);
        m0 = mn0; m1 = mn1;
        l0 *= sc0; l1 *= sc1;
#pragma unroll
        for (int nt = 0; nt < 8; nt++){
            acc_o[nt][0] *= sc0; acc_o[nt][1] *= sc0;
            acc_o[nt][2] *= sc1; acc_o[nt][3] *= sc1;
        }
        float rs0 = 0.f, rs1 = 0.f;
        uint32_t pa_h[4][4], pa_l[4][4];
#pragma unroll
        for (int nt = 0; nt < 8; nt++){
            float p0 = __expf(acc_s[nt][0] - mn0), p1 = __expf(acc_s[nt][1] - mn0);
            float p2 = __expf(acc_s[nt][2] - mn1), p3 = __expf(acc_s[nt][3] - mn1);
            rs0 += p0 + p1; rs1 += p2 + p3;
            int k2 = nt >> 1;
            if (!(nt & 1)){
                splitpack(p0, p1, pa_h[k2][0], pa_l[k2][0]);
                splitpack(p2, p3, pa_h[k2][1], pa_l[k2][1]);
            } else {
                splitpack(p0, p1, pa_h[k2][2], pa_l[k2][2]);
                splitpack(p2, p3, pa_h[k2][3], pa_l[k2][3]);
            }
        }
        rs0 += __shfl_xor_sync(~0u, rs0, 1); rs0 += __shfl_xor_sync(~0u, rs0, 2);
        rs1 += __shfl_xor_sync(~0u, rs1, 1); rs1 += __shfl_xor_sync(~0u, rs1, 2);
        l0 += rs0; l1 += rs1;

        uint32_t vb = kb + 16384;
#pragma unroll
        for (int k2 = 0; k2 < 4; k2++){
            uint32_t vh[8][2], vl[8][2];
#pragma unroll
            for (int nt = 0; nt < 8; nt++){
                int r = nt * 8 + (lane & 7);
                int seg = k2 * 2 + ((lane >> 3) & 1);
                uint32_t vd = vb + r * 128 + ((seg ^ (r & 7)) << 4);
                ldm_x2(vh[nt], vd);
                ldm_x2(vl[nt], vd + 8192);
            }
#pragma unroll
            for (int nt = 0; nt < 8; nt++){
                mma_bf16(acc_o[nt], pa_h[k2], vh[nt]);
                mma_bf16(acc_o[nt], pa_h[k2], vl[nt]);
                mma_bf16(acc_o[nt], pa_l[k2], vh[nt]);
            }
        }
        __syncthreads();
        buf ^= 1;
    }

    int r = row0 + wid * 16 + (lane >> 2);
    size_t ro0 = ((size_t)z * NNODE + r) * 256;
    size_t ro1 = ((size_t)z * NNODE + r + 8) * 256;
#pragma unroll
    for (int nt = 0; nt < 8; nt++){
        int cc = head * 64 + nt * 8 + ((lane & 3) << 1);
        pO[ro0 + cc]     = acc_o[nt][0];
        pO[ro0 + cc + 1] = acc_o[nt][1];
        pO[ro1 + cc]     = acc_o[nt][2];
        pO[ro1 + cc + 1] = acc_o[nt][3];
    }
    if ((lane & 3) == 0){
        pML[((size_t)z * NNODE + r) * 8 + head * 2]     = m0;
        pML[((size_t)z * NNODE + r) * 8 + head * 2 + 1] = l0;
        pML[((size_t)z * NNODE + r + 8) * 8 + head * 2]     = m1;
        pML[((size_t)z * NNODE + r + 8) * 8 + head * 2 + 1] = l1;
    }
}

// combo: blocks 0..255 = flash; 256..767 = LSTM-gates GEMM
__global__ void __launch_bounds__(256) k_combo(
    GA a,
    const __nv_bfloat16* __restrict__ qkvh, const __nv_bfloat16* __restrict__ qkvl,
    const __nv_bfloat16* __restrict__ vth, const __nv_bfloat16* __restrict__ vtl,
    float* __restrict__ pO, float* __restrict__ pML)
{
    int bx = blockIdx.x;
    if (bx < 256){
        int row0 = (bx & 31) * 128;
        int head = (bx >> 5) & 3;
        int z = bx >> 7;
        flash_body(qkvh, qkvl, vth, vtl, pO, pML, row0, head, z);
    } else {
        int idx = bx - 256;
        gemm_core(a, (idx >> 4) * 128, (idx & 15) * 64);
    }
}

// ================= pointwise =================
__global__ void k_mergelstm(const float* __restrict__ pO, const float* __restrict__ pML,
                            __nv_bfloat16* __restrict__ Oh, __nv_bfloat16* __restrict__ Ol,
                            const float* __restrict__ G, float* __restrict__ ht_out){
    int b = blockIdx.x;
    if (b < NNODE){
        int row = b, col = threadIdx.x;
        int head = col >> 6;
        float m0 = pML[(size_t)row * 8 + head * 2],            l0 = pML[(size_t)row * 8 + head * 2 + 1];
        float m1 = pML[((size_t)NNODE + row) * 8 + head * 2],  l1 = pML[((size_t)NNODE + row) * 8 + head * 2 + 1];
        float mx = fmaxf(m0, m1);
        float w0 = __expf(m0 - mx), w1 = __expf(m1 - mx);
        float num = pO[(size_t)row * 256 + col] * w0 + pO[((size_t)NNODE + row) * 256 + col] * w1;
        float den = l0 * w0 + l1 * w1;
        f2hl(num / den, Oh, Ol, (size_t)row * 256 + col);
    } else {
        int idx = (b - NNODE) * 256 + threadIdx.x;
        int n = idx >> 8, j = idx & 255;
        const float* gr = G + (size_t)n * 1024;
        float ig = gr[j], gg = gr[512 + j], og = gr[768 + j];
        float cc = sigmf(ig) * tanhf(gg);
        float hv = sigmf(og) * tanhf(cc);
        ht_out[idx] = hv;
        f2hl(hv, g_hcath, g_hcatl, (size_t)n * 512 + j);
    }
}

// ================= launch =================
#define SYMADDR(p, s) do { void* _t; cudaGetSymbolAddress(&_t, s); p = (decltype(p))_t; } while(0)

extern "C" void kernel_launch(void* const* d_in, const int* in_sizes, int n_in,
                              void* d_out, int out_size) {
    const float* x     = (const float*)d_in[0];
    const int*   ei_t  = (const int*)d_in[1];
    const int*   ei_c  = (const int*)d_in[2];
    const float* ea_t  = (const float*)d_in[3];
    const float* ea_c  = (const float*)d_in[4];
    const float* W_t   = (const float*)d_in[5];
    const float* asrc_t= (const float*)d_in[6];
    const float* adst_t= (const float*)d_in[7];
    const float* We_t  = (const float*)d_in[8];
    const float* ae_t  = (const float*)d_in[9];
    const float* b_t   = (const float*)d_in[10];
    const float* W_c   = (const float*)d_in[11];
    const float* asrc_c= (const float*)d_in[12];
    const float* adst_c= (const float*)d_in[13];
    const float* We_c  = (const float*)d_in[14];
    const float* ae_c  = (const float*)d_in[15];
    const float* b_c   = (const float*)d_in[16];
    const float* lstm_Wih = (const float*)d_in[17];
    const float* lstm_bih = (const float*)d_in[19];
    const float* lstm_bhh = (const float*)d_in[20];
    const float* mha_in_w  = (const float*)d_in[21];
    const float* mha_in_b  = (const float*)d_in[22];
    const float* mha_out_w = (const float*)d_in[23];
    const float* mha_out_b = (const float*)d_in[24];
    const float* fus_w = (const float*)d_in[25];
    const float* fus_b = (const float*)d_in[26];
    const float* out_w = (const float*)d_in[27];
    const float* out_b = (const float*)d_in[28];

    float* big; SYMADDR(big, g_big);
    float* po;  SYMADDR(po, g_po);
    float* pml; SYMADDR(pml, g_pml);
    float* xp0; SYMADDR(xp0, g_xp);
    float* xp1 = xp0 + (size_t)NNODE * NHC;
    float* as0; SYMADDR(as0, g_as);
    float* as1 = as0 + NNODE * NH;
    float* ad0; SYMADDR(ad0, g_ad);
    float* ad1 = ad0 + NNODE * NH;
    __nv_bfloat16 *hth, *htl, *hch, *hcl, *qkvh, *qkvl, *vth, *vtl;
    __nv_bfloat16 *attnh, *attnl, *hcath, *hcatl, *hfush, *hfusl;
    __nv_bfloat16 *wihh, *wihl, *inwh, *inwl, *mowh, *mowl, *fuwh, *fuwl, *owh, *owl;
    __nv_bfloat16 *xpadh, *xpadl, *wpadh, *wpadl;
    SYMADDR(hth, g_hth); SYMADDR(htl, g_htl); SYMADDR(hch, g_hch); SYMADDR(hcl, g_hcl);
    SYMADDR(qkvh, g_qkvh); SYMADDR(qkvl, g_qkvl); SYMADDR(vth, g_vth); SYMADDR(vtl, g_vtl);
    SYMADDR(attnh, g_attnh); SYMADDR(attnl, g_attnl);
    SYMADDR(hcath, g_hcath); SYMADDR(hcatl, g_hcatl);
    SYMADDR(hfush, g_hfush); SYMADDR(hfusl, g_hfusl);
    SYMADDR(wihh, g_wihh); SYMADDR(wihl, g_wihl);
    SYMADDR(inwh, g_inwh); SYMADDR(inwl, g_inwl);
    SYMADDR(mowh, g_mowh); SYMADDR(mowl, g_mowl);
    SYMADDR(fuwh, g_fuwh); SYMADDR(fuwl, g_fuwl);
    SYMADDR(owh, g_owh); SYMADDR(owl, g_owl);
    SYMADDR(xpadh, g_xpadh); SYMADDR(xpadl, g_xpadl);
    SYMADDR(wpadh, g_wpadh); SYMADDR(wpadl, g_wpadl);

    cudaFuncSetAttribute(k_combo,  cudaFuncAttributeMaxDynamicSharedMemorySize, 98304);
    cudaFuncSetAttribute(mma_single, cudaFuncAttributeMaxDynamicSharedMemorySize, 98304);
    cudaFuncSetAttribute(mma_dual, cudaFuncAttributeMaxDynamicSharedMemorySize, 98304);
    const int DYN = 98304;

    float* out_main = (float*)d_out;
    float* out_ht   = out_main + (size_t)NNODE * NOUT;
    float* out_hc   = out_ht   + (size_t)NNODE * HID;

    const int* src_t = ei_t; const int* dst_t = ei_t + NE;
    const int* src_c = ei_c; const int* dst_c = ei_c + NE;

    k_initconv<<<128 + NCONVB, 256>>>(ea_t, ea_c, lstm_Wih, mha_in_w, mha_out_w, fus_w, out_w, x, W_t, W_c);
    k_setupcount<<<1 + 1024, 256>>>(We_t, ae_t, We_c, ae_c, lstm_bih, lstm_bhh, dst_t, dst_c);

    // ---- xp GEMMs (z=0/1) + count prefix scans (z=2) ----
    {
        GA a0 = { xpadh, xpadl, wpadh, wpadl, xp0, nullptr, nullptr, nullptr,
                  asrc_t, adst_t, as0, ad0, nullptr, nullptr,
                  64, 64, NHC, 0, 0, 64, 0, 32, 1.f };
        GA a1 = { xpadh, xpadl, wpadh + (size_t)NHC * 64, wpadl + (size_t)NHC * 64, xp1,
                  nullptr, nullptr, nullptr,
                  asrc_c, adst_c, as1, ad1, nullptr, nullptr,
                  64, 64, NHC, 0, 0, 64, 0, 32, 1.f };
        mma_dual<<<dim3(32, 32, 3), 256, DYN>>>(a0, a1);
    }

    // ---- counting-sort scatter ----
    k_scatter<<<dim3((NE + 511) / 512, 2), 256>>>(dst_t, dst_c);

    // ---- aggregation (logits + softmax + gather fused), both graphs concurrently ----
    k_agg<<<dim3(NNODE, 2), 256>>>(src_t, src_c, ea_t, ea_c, b_t, b_c);

    // ---- qkv GEMM (4096x768x256), V-transpose fused in epilogue ----
    {
        GA a = { hch, hcl, inwh, inwl, nullptr, qkvh, qkvl, mha_in_b,
                 nullptr, nullptr, nullptr, nullptr, vth, vtl,
                 256, 256, 0, 768, 0, 256, 0, 12, 1.f };
        mma_single<<<dim3(12, 32), 256, DYN>>>(a);
    }

    // ---- flash attention + LSTM gates GEMM overlapped ----
    {
        GA a = { hth, htl, wihh, wihl, big + OFF_G, nullptr, nullptr, big + OFF_BSUM,
                 nullptr, nullptr, nullptr, nullptr, nullptr, nullptr,
                 NHC, NHC, 1024, 0, 0, NHC, 0, 16, 1.f };
        k_combo<<<768, 256, DYN>>>(a, qkvh, qkvl, vth, vtl, po, pml);
    }

    // ---- merge flash partials + lstm pointwise ----
    k_mergelstm<<<2 * NNODE, 256>>>(po, pml, attnh, attnl, big + OFF_G, out_ht);

    // ---- proj (4096x256x256) ----
    {
        GA a = { attnh, attnl, mowh, mowl, out_hc, hcath, hcatl, mha_out_b,
                 nullptr, nullptr, nullptr, nullptr, nullptr, nullptr,
                 256, 256, 256, 512, 256, 256, 0, 4, 1.f };
        mma_single<<<dim3(4, 32), 256, DYN>>>(a);
    }
    // ---- fusion relu (4096x256x512) ----
    {
        GA a = { hcath, hcatl, fuwh, fuwl, nullptr, hfush, hfusl, fus_b,
                 nullptr, nullptr, nullptr, nullptr, nullptr, nullptr,
                 512, 512, 0, 256, 0, 512, 1, 4, 1.f };
        mma_single<<<dim3(4, 32), 256, DYN>>>(a);
    }
    // ---- out (4096x128x256) ----
    {
        GA a = { hfush, hfusl, owh, owl, out_main, nullptr, nullptr, out_b,
                 nullptr, nullptr, nullptr, nullptr, nullptr, nullptr,
                 256, 256, NOUT, 0, 0, 256, 0, 2, 1.f };
        mma_single<<<dim3(2, 32), 256, DYN>>>(a);
    }
}